// round 7
// baseline (speedup 1.0000x reference)
#include <cuda_runtime.h>
#include <cuda_bf16.h>
#include <math.h>
#include <stdint.h>

#define NN 100000
#define EE 1600000
#define SCAN_CHUNK 256

// Scratch (no device allocation allowed)
__device__ float g_h[(size_t)NN * 128];
__device__ float g_t[(size_t)NN * 128];
__device__ float g_deg[NN];
__device__ float g_dinv[NN];
__device__ int   g_cnt[NN];
__device__ int   g_off[NN + 1];
__device__ int   g_cur[NN];
__device__ int2  g_epack[EE];     // {src, coef-as-int}
__device__ int   g_part[512];
// transposed + split weights: Wp^T @0 (128x256), W1^T @32768, W2^T @49152, Wl1^T @65536
__device__ __nv_bfloat16 g_whi[81920];
__device__ __nv_bfloat16 g_wlo[81920];

// ================= mma.sync helpers (baseline PTX, sm_80+) =================
__device__ __forceinline__ void ldsm4(uint32_t d[4], const void* p) {
    uint32_t a = (uint32_t)__cvta_generic_to_shared(p);
    asm volatile("ldmatrix.sync.aligned.m8n8.x4.shared.b16 {%0,%1,%2,%3}, [%4];"
        : "=r"(d[0]), "=r"(d[1]), "=r"(d[2]), "=r"(d[3]) : "r"(a));
}
__device__ __forceinline__ void ldsm2(uint32_t d[2], const void* p) {
    uint32_t a = (uint32_t)__cvta_generic_to_shared(p);
    asm volatile("ldmatrix.sync.aligned.m8n8.x2.shared.b16 {%0,%1}, [%2];"
        : "=r"(d[0]), "=r"(d[1]) : "r"(a));
}
__device__ __forceinline__ void mma16816(float c[4], const uint32_t a[4], const uint32_t b[2]) {
    asm volatile("mma.sync.aligned.m16n8k16.row.col.f32.bf16.bf16.f32 "
        "{%0,%1,%2,%3}, {%4,%5,%6,%7}, {%8,%9}, {%0,%1,%2,%3};"
        : "+f"(c[0]), "+f"(c[1]), "+f"(c[2]), "+f"(c[3])
        : "r"(a[0]), "r"(a[1]), "r"(a[2]), "r"(a[3]), "r"(b[0]), "r"(b[1]));
}
__device__ __forceinline__ uint32_t pack_bf16(__nv_bfloat16 a, __nv_bfloat16 b) {
    return (uint32_t)__bfloat16_as_ushort(a) | ((uint32_t)__bfloat16_as_ushort(b) << 16);
}
__device__ __forceinline__ void split8(const float4& v0, const float4& v1,
                                       uint4& uh, uint4& ul) {
    float f[8] = {v0.x, v0.y, v0.z, v0.w, v1.x, v1.y, v1.z, v1.w};
    uint32_t h[4], l[4];
#pragma unroll
    for (int j = 0; j < 4; j++) {
        __nv_bfloat16 h0 = __float2bfloat16(f[2*j]);
        __nv_bfloat16 h1 = __float2bfloat16(f[2*j+1]);
        __nv_bfloat16 l0 = __float2bfloat16(f[2*j]   - __bfloat162float(h0));
        __nv_bfloat16 l1 = __float2bfloat16(f[2*j+1] - __bfloat162float(h1));
        h[j] = pack_bf16(h0, h1);
        l[j] = pack_bf16(l0, l1);
    }
    uh = make_uint4(h[0], h[1], h[2], h[3]);
    ul = make_uint4(l[0], l[1], l[2], l[3]);
}

// ================= CSR build =================
__global__ void k_init(float* deg, int* cnt, int n) {
    int i = blockIdx.x * blockDim.x + threadIdx.x;
    if (i < n) { deg[i] = 1.0f; cnt[i] = 0; }
}
__global__ void k_edge_deg(const int* __restrict__ dst, const float* __restrict__ ew,
                           float* deg, int* cnt, int E) {
    int e = blockIdx.x * blockDim.x + threadIdx.x;
    if (e < E) {
        int d = dst[e];
        atomicAdd(&deg[d], ew[e]);
        atomicAdd(&cnt[d], 1);
    }
}
__global__ void k_dinv(const float* __restrict__ deg, float* dinv, int n) {
    int i = blockIdx.x * blockDim.x + threadIdx.x;
    if (i < n) dinv[i] = rsqrtf(deg[i]);
}
__global__ __launch_bounds__(SCAN_CHUNK) void k_scan1(const int* __restrict__ cnt,
                                                      int* part, int n) {
    __shared__ int ws[8];
    int i = blockIdx.x * SCAN_CHUNK + threadIdx.x;
    int v = (i < n) ? cnt[i] : 0;
#pragma unroll
    for (int o = 16; o >= 1; o >>= 1) v += __shfl_xor_sync(0xFFFFFFFFu, v, o);
    if ((threadIdx.x & 31) == 0) ws[threadIdx.x >> 5] = v;
    __syncthreads();
    if (threadIdx.x == 0) {
        int s = 0;
#pragma unroll
        for (int w = 0; w < 8; w++) s += ws[w];
        part[blockIdx.x] = s;
    }
}
__global__ __launch_bounds__(512) void k_scan2(int* part, int nb) {
    __shared__ int s[512];
    int tid = threadIdx.x;
    int v = (tid < nb) ? part[tid] : 0;
    s[tid] = v;
    __syncthreads();
#pragma unroll
    for (int d = 1; d < 512; d <<= 1) {
        int add = (tid >= d) ? s[tid - d] : 0;
        __syncthreads();
        s[tid] += add;
        __syncthreads();
    }
    if (tid < nb) part[tid] = s[tid] - v;
}
__global__ __launch_bounds__(SCAN_CHUNK) void k_scan3(const int* __restrict__ cnt,
                                                      const int* __restrict__ part,
                                                      int* off, int* cur, int n, int E) {
    __shared__ int ws[8];
    int tid = threadIdx.x;
    int i = blockIdx.x * SCAN_CHUNK + tid;
    int lane = tid & 31;
    int warp = tid >> 5;
    int v = (i < n) ? cnt[i] : 0;
    int x = v;
#pragma unroll
    for (int o = 1; o < 32; o <<= 1) {
        int y = __shfl_up_sync(0xFFFFFFFFu, x, o);
        if (lane >= o) x += y;
    }
    if (lane == 31) ws[warp] = x;
    __syncthreads();
    if (warp == 0 && lane < 8) {
        int y = ws[lane];
        int z = y;
#pragma unroll
        for (int o = 1; o < 8; o <<= 1) {
            int u = __shfl_up_sync(0xFFu, z, o);
            if (lane >= o) z += u;
        }
        ws[lane] = z - y;
    }
    __syncthreads();
    if (i < n) {
        int excl = part[blockIdx.x] + ws[warp] + x - v;
        off[i] = excl;
        cur[i] = excl;
    }
    if (i == n - 1) off[n] = E;
}
__global__ void k_scatter(const int* __restrict__ src, const int* __restrict__ dst,
                          const float* __restrict__ ew, const float* __restrict__ dinv,
                          int* cur, int2* epack, int E) {
    int e = blockIdx.x * blockDim.x + threadIdx.x;
    if (e >= E) return;
    int s = src[e];
    int d = dst[e];
    float c = __ldg(dinv + s) * ew[e] * __ldg(dinv + d);
    int pos = atomicAdd(&cur[d], 1);
    epack[pos] = make_int2(s, __float_as_int(c));
}

// ================= weight transpose + bf16 split =================
__global__ void k_prep_w(const float* __restrict__ W, int K, int N,
                         __nv_bfloat16* hi, __nv_bfloat16* lo) {
    int idx = blockIdx.x * blockDim.x + threadIdx.x;
    if (idx >= K * N) return;
    int n = idx / K, k = idx % K;
    float w = W[(size_t)k * N + n];
    __nv_bfloat16 h = __float2bfloat16(w);
    hi[idx] = h;
    lo[idx] = __float2bfloat16(w - __bfloat162float(h));
}

// ================= HMMA GEMM: out[M,128] = A[M,K] @ W[K,128] =================
// split-bf16 (hi/lo), mma.sync m16n8k16, BM=64 BN=128 BK=128, 128 threads.
// EPI==0: out = relu(acc + bias);  EPI==1: out = acc
#define KP 136
#define SM_AH 0
#define SM_AL (64 * KP * 2)
#define SM_BH (2 * 64 * KP * 2)
#define SM_BL (SM_BH + 128 * KP * 2)
#define GEMM_SMEM (SM_BL + 128 * KP * 2)   // 104448 bytes

template <int K, int EPI>
__global__ __launch_bounds__(128) void k_gemm_mma(
    const float* __restrict__ A, const __nv_bfloat16* __restrict__ Whi,
    const __nv_bfloat16* __restrict__ Wlo, const float* __restrict__ bias,
    float* __restrict__ out, int M)
{
    extern __shared__ char sm[];
    __nv_bfloat16* Ah = (__nv_bfloat16*)(sm + SM_AH);
    __nv_bfloat16* Al = (__nv_bfloat16*)(sm + SM_AL);
    __nv_bfloat16* Bh = (__nv_bfloat16*)(sm + SM_BH);
    __nv_bfloat16* Bl = (__nv_bfloat16*)(sm + SM_BL);

    const int tid  = threadIdx.x;
    const int wid  = tid >> 5;
    const int lane = tid & 31;
    const int wm   = wid & 1;       // warp row: 32 output rows
    const int wn   = wid >> 1;      // warp col: 64 output cols
    const int row0 = blockIdx.x * 64;

    float acc[2][8][4];
#pragma unroll
    for (int mt = 0; mt < 2; mt++)
#pragma unroll
        for (int nt = 0; nt < 8; nt++)
#pragma unroll
            for (int j = 0; j < 4; j++) acc[mt][nt][j] = 0.0f;

#pragma unroll 1
    for (int kc = 0; kc < K; kc += 128) {
        if (kc) __syncthreads();
        // ---- A fill: row = tid>>1, half-row of 64 floats, convert to hi/lo ----
        {
            int r = tid >> 1;
            int gr = row0 + r;
            int cbase = (tid & 1) * 64;
            const float4* ap = (const float4*)(A + (size_t)gr * K + kc + cbase);
            __nv_bfloat16* dh = Ah + r * KP + cbase;
            __nv_bfloat16* dl = Al + r * KP + cbase;
            bool ok = gr < M;
            float4 z = make_float4(0.f, 0.f, 0.f, 0.f);
#pragma unroll
            for (int j = 0; j < 8; j++) {
                float4 v0 = ok ? ap[2*j]     : z;
                float4 v1 = ok ? ap[2*j + 1] : z;
                uint4 uh, ul;
                split8(v0, v1, uh, ul);
                *(uint4*)(dh + j * 8) = uh;
                *(uint4*)(dl + j * 8) = ul;
            }
        }
        // ---- B fill: row n = tid, 128 bf16 hi + 128 bf16 lo ----
        {
            const uint4* bh = (const uint4*)(Whi + (size_t)tid * K + kc);
            const uint4* bl = (const uint4*)(Wlo + (size_t)tid * K + kc);
            uint4* dh = (uint4*)(Bh + tid * KP);
            uint4* dl = (uint4*)(Bl + tid * KP);
#pragma unroll
            for (int j = 0; j < 16; j++) { dh[j] = bh[j]; dl[j] = bl[j]; }
        }
        __syncthreads();

#pragma unroll
        for (int ks = 0; ks < 128; ks += 16) {
            uint32_t ah[2][4], al[2][4], bhf[8][2], blf[8][2];
#pragma unroll
            for (int mt = 0; mt < 2; mt++) {
                int r = wm * 32 + mt * 16 + (lane & 15);
                int c = ks + ((lane >> 4) << 3);
                ldsm4(ah[mt], Ah + r * KP + c);
                ldsm4(al[mt], Al + r * KP + c);
            }
#pragma unroll
            for (int nt = 0; nt < 8; nt++) {
                int n = wn * 64 + nt * 8 + (lane & 7);
                int c = ks + ((lane >> 3) & 1) * 8;
                ldsm2(bhf[nt], Bh + n * KP + c);
                ldsm2(blf[nt], Bl + n * KP + c);
            }
#pragma unroll
            for (int mt = 0; mt < 2; mt++)
#pragma unroll
                for (int nt = 0; nt < 8; nt++) {
                    mma16816(acc[mt][nt], ah[mt], bhf[nt]);
                    mma16816(acc[mt][nt], ah[mt], blf[nt]);
                    mma16816(acc[mt][nt], al[mt], bhf[nt]);
                }
        }
    }

    // ---- epilogue ----
#pragma unroll
    for (int mt = 0; mt < 2; mt++) {
        int r1 = row0 + wm * 32 + mt * 16 + (lane >> 2);
        int r2 = r1 + 8;
#pragma unroll
        for (int nt = 0; nt < 8; nt++) {
            int c = wn * 64 + nt * 8 + (lane & 3) * 2;
            float2 v1 = make_float2(acc[mt][nt][0], acc[mt][nt][1]);
            float2 v2 = make_float2(acc[mt][nt][2], acc[mt][nt][3]);
            if (EPI == 0) {
                float b0 = __ldg(bias + c), b1 = __ldg(bias + c + 1);
                v1.x = fmaxf(v1.x + b0, 0.f); v1.y = fmaxf(v1.y + b1, 0.f);
                v2.x = fmaxf(v2.x + b0, 0.f); v2.y = fmaxf(v2.y + b1, 0.f);
            }
            if (r1 < M) *(float2*)&out[(size_t)r1 * 128 + c] = v1;
            if (r2 < M) *(float2*)&out[(size_t)r2 * 128 + c] = v2;
        }
    }
}

// ================= gather aggregation: one warp per node =================
__global__ __launch_bounds__(256) void k_agg(
    const int* __restrict__ off, const int2* __restrict__ epack,
    const float* __restrict__ t, const float* __restrict__ dinv,
    const float* __restrict__ bias, float* __restrict__ out, int n)
{
    int w = (blockIdx.x * blockDim.x + threadIdx.x) >> 5;
    if (w >= n) return;
    int lane = threadIdx.x & 31;

    const float4* tp = (const float4*)t;
    int beg = __ldg(off + w);
    int end = __ldg(off + w + 1);

    float di = __ldg(dinv + w);
    float s = di * di;
    float4 acc = tp[(size_t)w * 32 + lane];
    acc.x *= s; acc.y *= s; acc.z *= s; acc.w *= s;

    int e = beg;
    for (; e + 3 < end; e += 4) {
        int2 p0 = __ldg(epack + e);
        int2 p1 = __ldg(epack + e + 1);
        int2 p2 = __ldg(epack + e + 2);
        int2 p3 = __ldg(epack + e + 3);
        float4 h0 = tp[(size_t)p0.x * 32 + lane];
        float4 h1 = tp[(size_t)p1.x * 32 + lane];
        float4 h2 = tp[(size_t)p2.x * 32 + lane];
        float4 h3 = tp[(size_t)p3.x * 32 + lane];
        float c0 = __int_as_float(p0.y), c1 = __int_as_float(p1.y);
        float c2 = __int_as_float(p2.y), c3 = __int_as_float(p3.y);
        acc.x += c0 * h0.x + c1 * h1.x + c2 * h2.x + c3 * h3.x;
        acc.y += c0 * h0.y + c1 * h1.y + c2 * h2.y + c3 * h3.y;
        acc.z += c0 * h0.z + c1 * h1.z + c2 * h2.z + c3 * h3.z;
        acc.w += c0 * h0.w + c1 * h1.w + c2 * h2.w + c3 * h3.w;
    }
    for (; e < end; e++) {
        int2 p0 = __ldg(epack + e);
        float c0 = __int_as_float(p0.y);
        float4 h0 = tp[(size_t)p0.x * 32 + lane];
        acc.x += c0 * h0.x;
        acc.y += c0 * h0.y;
        acc.z += c0 * h0.z;
        acc.w += c0 * h0.w;
    }

    float4 bv = *(const float4*)&bias[lane * 4];
    acc.x = fmaxf(acc.x + bv.x, 0.f);
    acc.y = fmaxf(acc.y + bv.y, 0.f);
    acc.z = fmaxf(acc.z + bv.z, 0.f);
    acc.w = fmaxf(acc.w + bv.w, 0.f);
    ((float4*)out)[(size_t)w * 32 + lane] = acc;
}

// ================= logits + softmax =================
__global__ __launch_bounds__(256) void k_logits_softmax(
    const float* __restrict__ h, const float* __restrict__ Wl2,
    const float* __restrict__ bl2, float* __restrict__ out, int M)
{
    __shared__ float hs[8][128];
    int tid = threadIdx.x;
    int warp = tid >> 5;
    int lane = tid & 31;
    int row0 = blockIdx.x * 8;

    {
        int rloc = tid >> 5;
        int cloc = (tid & 31) * 4;
        int r = row0 + rloc;
        float4 v = make_float4(0.f, 0.f, 0.f, 0.f);
        if (r < M) v = *(const float4*)&h[(size_t)r * 128 + cloc];
        *(float4*)&hs[rloc][cloc] = v;
    }
    __syncthreads();

    int r = row0 + warp;
    if (r >= M) return;

    float acc = bl2[lane];
#pragma unroll
    for (int k = 0; k < 128; k++) {
        acc += hs[warp][k] * __ldg(&Wl2[(size_t)k * 32 + lane]);
    }

    float m = acc;
#pragma unroll
    for (int o = 16; o >= 1; o >>= 1) m = fmaxf(m, __shfl_xor_sync(0xFFFFFFFFu, m, o));
    float e = __expf(acc - m);
    float s = e;
#pragma unroll
    for (int o = 16; o >= 1; o >>= 1) s += __shfl_xor_sync(0xFFFFFFFFu, s, o);
    out[(size_t)r * 32 + lane] = e / s;
}

// ================= launch =================
extern "C" void kernel_launch(void* const* d_in, const int* in_sizes, int n_in,
                              void* d_out, int out_size)
{
    const float* x   = (const float*)d_in[0];
    const int*   ei  = (const int*)d_in[1];
    const float* ew  = (const float*)d_in[2];
    const float* Wp  = (const float*)d_in[3];
    const float* bp  = (const float*)d_in[4];
    const float* W1  = (const float*)d_in[5];
    const float* b1  = (const float*)d_in[6];
    const float* W2  = (const float*)d_in[7];
    const float* b2  = (const float*)d_in[8];
    const float* Wl1 = (const float*)d_in[9];
    const float* bl1 = (const float*)d_in[10];
    const float* Wl2 = (const float*)d_in[11];
    const float* bl2 = (const float*)d_in[12];
    float* out = (float*)d_out;

    const int M = in_sizes[0] / 256;   // 100000
    const int E = in_sizes[1] / 2;     // 1600000
    const int* src = ei;
    const int* dst = ei + E;

    float *p_h, *p_t, *p_deg, *p_dinv;
    int *p_cnt, *p_off, *p_cur, *p_part;
    int2 *p_epack;
    __nv_bfloat16 *p_whi, *p_wlo;
    cudaGetSymbolAddress((void**)&p_h, g_h);
    cudaGetSymbolAddress((void**)&p_t, g_t);
    cudaGetSymbolAddress((void**)&p_deg, g_deg);
    cudaGetSymbolAddress((void**)&p_dinv, g_dinv);
    cudaGetSymbolAddress((void**)&p_cnt, g_cnt);
    cudaGetSymbolAddress((void**)&p_off, g_off);
    cudaGetSymbolAddress((void**)&p_cur, g_cur);
    cudaGetSymbolAddress((void**)&p_epack, g_epack);
    cudaGetSymbolAddress((void**)&p_part, g_part);
    cudaGetSymbolAddress((void**)&p_whi, g_whi);
    cudaGetSymbolAddress((void**)&p_wlo, g_wlo);

    cudaFuncSetAttribute(k_gemm_mma<256, 0>, cudaFuncAttributeMaxDynamicSharedMemorySize, GEMM_SMEM);
    cudaFuncSetAttribute(k_gemm_mma<128, 1>, cudaFuncAttributeMaxDynamicSharedMemorySize, GEMM_SMEM);
    cudaFuncSetAttribute(k_gemm_mma<128, 0>, cudaFuncAttributeMaxDynamicSharedMemorySize, GEMM_SMEM);

    const int gemm_blocks = (M + 63) / 64;
    const int agg_blocks  = (M + 7) / 8;
    const int scan_blocks = (M + SCAN_CHUNK - 1) / SCAN_CHUNK;

    // weight transpose + split (tiny)
    k_prep_w<<<(256 * 128 + 255) / 256, 256>>>(Wp,  256, 128, p_whi,         p_wlo);
    k_prep_w<<<(128 * 128 + 255) / 256, 256>>>(W1,  128, 128, p_whi + 32768, p_wlo + 32768);
    k_prep_w<<<(128 * 128 + 255) / 256, 256>>>(W2,  128, 128, p_whi + 49152, p_wlo + 49152);
    k_prep_w<<<(128 * 128 + 255) / 256, 256>>>(Wl1, 128, 128, p_whi + 65536, p_wlo + 65536);

    // CSR build + normalization (reused by both conv layers)
    k_init<<<(M + 255) / 256, 256>>>(p_deg, p_cnt, M);
    k_edge_deg<<<(E + 255) / 256, 256>>>(dst, ew, p_deg, p_cnt, E);
    k_dinv<<<(M + 255) / 256, 256>>>(p_deg, p_dinv, M);
    k_scan1<<<scan_blocks, SCAN_CHUNK>>>(p_cnt, p_part, M);
    k_scan2<<<1, 512>>>(p_part, scan_blocks);
    k_scan3<<<scan_blocks, SCAN_CHUNK>>>(p_cnt, p_part, p_off, p_cur, M, E);
    k_scatter<<<(E + 255) / 256, 256>>>(src, dst, ew, p_dinv, p_cur, p_epack, E);

    // h0 = relu(x @ Wp + bp)
    k_gemm_mma<256, 0><<<gemm_blocks, 128, GEMM_SMEM>>>(x, p_whi, p_wlo, bp, p_h, M);

    // conv1: t = h0 @ W1; h = relu(aggregate(t) + b1)
    k_gemm_mma<128, 1><<<gemm_blocks, 128, GEMM_SMEM>>>(p_h, p_whi + 32768, p_wlo + 32768, nullptr, p_t, M);
    k_agg<<<agg_blocks, 256>>>(p_off, p_epack, p_t, p_dinv, b1, p_h, M);

    // conv2
    k_gemm_mma<128, 1><<<gemm_blocks, 128, GEMM_SMEM>>>(p_h, p_whi + 49152, p_wlo + 49152, nullptr, p_t, M);
    k_agg<<<agg_blocks, 256>>>(p_off, p_epack, p_t, p_dinv, b2, p_h, M);

    // h = relu(h @ Wl1 + bl1)
    k_gemm_mma<128, 0><<<gemm_blocks, 128, GEMM_SMEM>>>(p_h, p_whi + 65536, p_wlo + 65536, bl1, p_t, M);

    // softmax(h @ Wl2 + bl2)
    k_logits_softmax<<<(M + 7) / 8, 256>>>(p_t, Wl2, bl2, out, M);
}

// round 8
// speedup vs baseline: 1.0633x; 1.0633x over previous
#include <cuda_runtime.h>
#include <cuda_bf16.h>
#include <math.h>
#include <stdint.h>

#define NN 100000
#define EE 1600000
#define SCAN_CHUNK 256

// Scratch (no device allocation allowed)
__device__ float g_h[(size_t)NN * 128];
__device__ float g_t[(size_t)NN * 128];
__device__ float g_deg[NN];
__device__ float g_dinv[NN];
__device__ int   g_cnt[NN];
__device__ int   g_off[NN + 1];
__device__ int   g_cur[NN];
__device__ int2  g_epack[EE];     // {src, coef-as-int}
__device__ int   g_part[512];
// transposed + split weights: Wp^T @0 (128x256), W1^T @32768, W2^T @49152, Wl1^T @65536
__device__ __nv_bfloat16 g_whi[81920];
__device__ __nv_bfloat16 g_wlo[81920];

// ================= mma.sync / cp.async helpers (baseline PTX, sm_80+) =================
__device__ __forceinline__ void ldsm4(uint32_t d[4], const void* p) {
    uint32_t a = (uint32_t)__cvta_generic_to_shared(p);
    asm volatile("ldmatrix.sync.aligned.m8n8.x4.shared.b16 {%0,%1,%2,%3}, [%4];"
        : "=r"(d[0]), "=r"(d[1]), "=r"(d[2]), "=r"(d[3]) : "r"(a));
}
__device__ __forceinline__ void ldsm2(uint32_t d[2], const void* p) {
    uint32_t a = (uint32_t)__cvta_generic_to_shared(p);
    asm volatile("ldmatrix.sync.aligned.m8n8.x2.shared.b16 {%0,%1}, [%2];"
        : "=r"(d[0]), "=r"(d[1]) : "r"(a));
}
__device__ __forceinline__ void mma16816(float c[4], const uint32_t a[4], const uint32_t b[2]) {
    asm volatile("mma.sync.aligned.m16n8k16.row.col.f32.bf16.bf16.f32 "
        "{%0,%1,%2,%3}, {%4,%5,%6,%7}, {%8,%9}, {%0,%1,%2,%3};"
        : "+f"(c[0]), "+f"(c[1]), "+f"(c[2]), "+f"(c[3])
        : "r"(a[0]), "r"(a[1]), "r"(a[2]), "r"(a[3]), "r"(b[0]), "r"(b[1]));
}
__device__ __forceinline__ uint32_t pack_bf16(__nv_bfloat16 a, __nv_bfloat16 b) {
    return (uint32_t)__bfloat16_as_ushort(a) | ((uint32_t)__bfloat16_as_ushort(b) << 16);
}
__device__ __forceinline__ void split8(const float4& v0, const float4& v1,
                                       uint4& uh, uint4& ul) {
    float f[8] = {v0.x, v0.y, v0.z, v0.w, v1.x, v1.y, v1.z, v1.w};
    uint32_t h[4], l[4];
#pragma unroll
    for (int j = 0; j < 4; j++) {
        __nv_bfloat16 h0 = __float2bfloat16(f[2*j]);
        __nv_bfloat16 h1 = __float2bfloat16(f[2*j+1]);
        __nv_bfloat16 l0 = __float2bfloat16(f[2*j]   - __bfloat162float(h0));
        __nv_bfloat16 l1 = __float2bfloat16(f[2*j+1] - __bfloat162float(h1));
        h[j] = pack_bf16(h0, h1);
        l[j] = pack_bf16(l0, l1);
    }
    uh = make_uint4(h[0], h[1], h[2], h[3]);
    ul = make_uint4(l[0], l[1], l[2], l[3]);
}
__device__ __forceinline__ void cp16(void* dst_smem, const void* src) {
    uint32_t d = (uint32_t)__cvta_generic_to_shared(dst_smem);
    asm volatile("cp.async.cg.shared.global [%0], [%1], 16;" :: "r"(d), "l"(src) : "memory");
}
#define CP_COMMIT() asm volatile("cp.async.commit_group;" ::: "memory")
#define CP_WAIT0()  asm volatile("cp.async.wait_group 0;" ::: "memory")

// ================= CSR build =================
__global__ void k_init(float* deg, int* cnt, int n) {
    int i = blockIdx.x * blockDim.x + threadIdx.x;
    if (i < n) { deg[i] = 1.0f; cnt[i] = 0; }
}
__global__ void k_edge_deg(const int* __restrict__ dst, const float* __restrict__ ew,
                           float* deg, int* cnt, int E) {
    int e = blockIdx.x * blockDim.x + threadIdx.x;
    if (e < E) {
        int d = dst[e];
        atomicAdd(&deg[d], ew[e]);
        atomicAdd(&cnt[d], 1);
    }
}
__global__ void k_dinv(const float* __restrict__ deg, float* dinv, int n) {
    int i = blockIdx.x * blockDim.x + threadIdx.x;
    if (i < n) dinv[i] = rsqrtf(deg[i]);
}
__global__ __launch_bounds__(SCAN_CHUNK) void k_scan1(const int* __restrict__ cnt,
                                                      int* part, int n) {
    __shared__ int ws[8];
    int i = blockIdx.x * SCAN_CHUNK + threadIdx.x;
    int v = (i < n) ? cnt[i] : 0;
#pragma unroll
    for (int o = 16; o >= 1; o >>= 1) v += __shfl_xor_sync(0xFFFFFFFFu, v, o);
    if ((threadIdx.x & 31) == 0) ws[threadIdx.x >> 5] = v;
    __syncthreads();
    if (threadIdx.x == 0) {
        int s = 0;
#pragma unroll
        for (int w = 0; w < 8; w++) s += ws[w];
        part[blockIdx.x] = s;
    }
}
__global__ __launch_bounds__(512) void k_scan2(int* part, int nb) {
    __shared__ int s[512];
    int tid = threadIdx.x;
    int v = (tid < nb) ? part[tid] : 0;
    s[tid] = v;
    __syncthreads();
#pragma unroll
    for (int d = 1; d < 512; d <<= 1) {
        int add = (tid >= d) ? s[tid - d] : 0;
        __syncthreads();
        s[tid] += add;
        __syncthreads();
    }
    if (tid < nb) part[tid] = s[tid] - v;
}
__global__ __launch_bounds__(SCAN_CHUNK) void k_scan3(const int* __restrict__ cnt,
                                                      const int* __restrict__ part,
                                                      int* off, int* cur, int n, int E) {
    __shared__ int ws[8];
    int tid = threadIdx.x;
    int i = blockIdx.x * SCAN_CHUNK + tid;
    int lane = tid & 31;
    int warp = tid >> 5;
    int v = (i < n) ? cnt[i] : 0;
    int x = v;
#pragma unroll
    for (int o = 1; o < 32; o <<= 1) {
        int y = __shfl_up_sync(0xFFFFFFFFu, x, o);
        if (lane >= o) x += y;
    }
    if (lane == 31) ws[warp] = x;
    __syncthreads();
    if (warp == 0 && lane < 8) {
        int y = ws[lane];
        int z = y;
#pragma unroll
        for (int o = 1; o < 8; o <<= 1) {
            int u = __shfl_up_sync(0xFFu, z, o);
            if (lane >= o) z += u;
        }
        ws[lane] = z - y;
    }
    __syncthreads();
    if (i < n) {
        int excl = part[blockIdx.x] + ws[warp] + x - v;
        off[i] = excl;
        cur[i] = excl;
    }
    if (i == n - 1) off[n] = E;
}
__global__ void k_scatter(const int* __restrict__ src, const int* __restrict__ dst,
                          const float* __restrict__ ew, const float* __restrict__ dinv,
                          int* cur, int2* epack, int E) {
    int e = blockIdx.x * blockDim.x + threadIdx.x;
    if (e >= E) return;
    int s = src[e];
    int d = dst[e];
    float c = __ldg(dinv + s) * ew[e] * __ldg(dinv + d);
    int pos = atomicAdd(&cur[d], 1);
    epack[pos] = make_int2(s, __float_as_int(c));
}

// ================= weight transpose + bf16 split =================
__global__ void k_prep_w(const float* __restrict__ W, int K, int N,
                         __nv_bfloat16* hi, __nv_bfloat16* lo) {
    int idx = blockIdx.x * blockDim.x + threadIdx.x;
    if (idx >= K * N) return;
    int n = idx / K, k = idx % K;
    float w = W[(size_t)k * N + n];
    __nv_bfloat16 h = __float2bfloat16(w);
    hi[idx] = h;
    lo[idx] = __float2bfloat16(w - __bfloat162float(h));
}

// ================= HMMA GEMM: out[M,128] = A[M,K] @ W[K,128] =================
// split-bf16 (hi/lo), mma.sync m16n8k16, BM=64 BN=128 BK=64, 128 threads,
// 2-stage pipeline: cp.async for B, register prefetch + convert for A.
// EPI==0: out = relu(acc + bias);  EPI==1: out = acc
#define KP 72
#define A_BUF (64 * KP * 2)            // 9216 bytes per A hi/lo buffer
#define B_BUF (128 * KP * 2)           // 18432 bytes per B hi/lo buffer
#define OFF_AH 0
#define OFF_AL (2 * A_BUF)
#define OFF_BH (4 * A_BUF)
#define OFF_BL (4 * A_BUF + 2 * B_BUF)
#define GEMM_SMEM (4 * A_BUF + 4 * B_BUF)   // 110592 bytes

template <int K, int EPI>
__global__ __launch_bounds__(128) void k_gemm_mma(
    const float* __restrict__ A, const __nv_bfloat16* __restrict__ Whi,
    const __nv_bfloat16* __restrict__ Wlo, const float* __restrict__ bias,
    float* __restrict__ out, int M)
{
    extern __shared__ char sm[];

    const int tid  = threadIdx.x;
    const int wid  = tid >> 5;
    const int lane = tid & 31;
    const int wm   = wid & 1;       // warp row: 32 output rows
    const int wn   = wid >> 1;      // warp col: 64 output cols
    const int row0 = blockIdx.x * 64;
    constexpr int CHUNKS = K / 64;

    // A fill mapping: row r = tid>>1 (0..63), 32 floats at col (tid&1)*32
    const int ar = tid >> 1;
    const int ac = (tid & 1) * 32;
    const int gr = row0 + ar;
    const bool aok = gr < M;
    const float4* arow = (const float4*)(A + (size_t)gr * K + ac);
    // B fill mapping: row n = tid, 64 bf16 per chunk
    const __nv_bfloat16* bh_row = Whi + (size_t)tid * K;
    const __nv_bfloat16* bl_row = Wlo + (size_t)tid * K;

    float acc[2][8][4];
#pragma unroll
    for (int mt = 0; mt < 2; mt++)
#pragma unroll
        for (int nt = 0; nt < 8; nt++)
#pragma unroll
            for (int j = 0; j < 4; j++) acc[mt][nt][j] = 0.0f;

    float4 areg[8];
    const float4 z4 = make_float4(0.f, 0.f, 0.f, 0.f);

    // ---- prologue: stage chunk 0 into buf 0 ----
    {
        __nv_bfloat16* dbh = (__nv_bfloat16*)(sm + OFF_BH) + tid * KP;
        __nv_bfloat16* dbl = (__nv_bfloat16*)(sm + OFF_BL) + tid * KP;
#pragma unroll
        for (int j = 0; j < 8; j++) {
            cp16(dbh + j * 8, bh_row + j * 8);
            cp16(dbl + j * 8, bl_row + j * 8);
        }
        CP_COMMIT();
#pragma unroll
        for (int j = 0; j < 8; j++) areg[j] = aok ? arow[j] : z4;
        __nv_bfloat16* dah = (__nv_bfloat16*)(sm + OFF_AH) + ar * KP + ac;
        __nv_bfloat16* dal = (__nv_bfloat16*)(sm + OFF_AL) + ar * KP + ac;
#pragma unroll
        for (int j = 0; j < 4; j++) {
            uint4 uh, ul;
            split8(areg[2*j], areg[2*j+1], uh, ul);
            *(uint4*)(dah + j * 8) = uh;
            *(uint4*)(dal + j * 8) = ul;
        }
        CP_WAIT0();
    }
    __syncthreads();

#pragma unroll
    for (int c = 0; c < CHUNKS; c++) {
        const int buf = c & 1;
        const int nbuf = buf ^ 1;
        const bool more = (c + 1) < CHUNKS;

        // stage next chunk: cp.async B, LDG A into regs (latency hidden under MMAs)
        if (more) {
            int kn = (c + 1) * 64;
            __nv_bfloat16* dbh = (__nv_bfloat16*)(sm + OFF_BH + nbuf * B_BUF) + tid * KP;
            __nv_bfloat16* dbl = (__nv_bfloat16*)(sm + OFF_BL + nbuf * B_BUF) + tid * KP;
#pragma unroll
            for (int j = 0; j < 8; j++) {
                cp16(dbh + j * 8, bh_row + kn + j * 8);
                cp16(dbl + j * 8, bl_row + kn + j * 8);
            }
            CP_COMMIT();
#pragma unroll
            for (int j = 0; j < 8; j++) areg[j] = aok ? arow[kn / 4 + j] : z4;
        }

        // ---- MMA on current buffer ----
        const __nv_bfloat16* Ah = (const __nv_bfloat16*)(sm + OFF_AH + buf * A_BUF);
        const __nv_bfloat16* Al = (const __nv_bfloat16*)(sm + OFF_AL + buf * A_BUF);
        const __nv_bfloat16* Bh = (const __nv_bfloat16*)(sm + OFF_BH + buf * B_BUF);
        const __nv_bfloat16* Bl = (const __nv_bfloat16*)(sm + OFF_BL + buf * B_BUF);
#pragma unroll
        for (int ks = 0; ks < 64; ks += 16) {
            uint32_t ah[2][4], al[2][4], bhf[8][2], blf[8][2];
#pragma unroll
            for (int mt = 0; mt < 2; mt++) {
                int r = wm * 32 + mt * 16 + (lane & 15);
                int cc = ks + ((lane >> 4) << 3);
                ldsm4(ah[mt], Ah + r * KP + cc);
                ldsm4(al[mt], Al + r * KP + cc);
            }
#pragma unroll
            for (int nt = 0; nt < 8; nt++) {
                int n = wn * 64 + nt * 8 + (lane & 7);
                int cc = ks + ((lane >> 3) & 1) * 8;
                ldsm2(bhf[nt], Bh + n * KP + cc);
                ldsm2(blf[nt], Bl + n * KP + cc);
            }
#pragma unroll
            for (int mt = 0; mt < 2; mt++)
#pragma unroll
                for (int nt = 0; nt < 8; nt++) {
                    mma16816(acc[mt][nt], ah[mt], bhf[nt]);
                    mma16816(acc[mt][nt], ah[mt], blf[nt]);
                    mma16816(acc[mt][nt], al[mt], bhf[nt]);
                }
        }

        if (more) {
            // convert + STS next A into nbuf, then drain cp.async
            __nv_bfloat16* dah = (__nv_bfloat16*)(sm + OFF_AH + nbuf * A_BUF) + ar * KP + ac;
            __nv_bfloat16* dal = (__nv_bfloat16*)(sm + OFF_AL + nbuf * A_BUF) + ar * KP + ac;
#pragma unroll
            for (int j = 0; j < 4; j++) {
                uint4 uh, ul;
                split8(areg[2*j], areg[2*j+1], uh, ul);
                *(uint4*)(dah + j * 8) = uh;
                *(uint4*)(dal + j * 8) = ul;
            }
            CP_WAIT0();
            __syncthreads();
        }
    }

    // ---- epilogue ----
#pragma unroll
    for (int mt = 0; mt < 2; mt++) {
        int r1 = row0 + wm * 32 + mt * 16 + (lane >> 2);
        int r2 = r1 + 8;
#pragma unroll
        for (int nt = 0; nt < 8; nt++) {
            int c = wn * 64 + nt * 8 + (lane & 3) * 2;
            float2 v1 = make_float2(acc[mt][nt][0], acc[mt][nt][1]);
            float2 v2 = make_float2(acc[mt][nt][2], acc[mt][nt][3]);
            if (EPI == 0) {
                float b0 = __ldg(bias + c), b1 = __ldg(bias + c + 1);
                v1.x = fmaxf(v1.x + b0, 0.f); v1.y = fmaxf(v1.y + b1, 0.f);
                v2.x = fmaxf(v2.x + b0, 0.f); v2.y = fmaxf(v2.y + b1, 0.f);
            }
            if (r1 < M) *(float2*)&out[(size_t)r1 * 128 + c] = v1;
            if (r2 < M) *(float2*)&out[(size_t)r2 * 128 + c] = v2;
        }
    }
}

// ================= gather aggregation: one warp per node =================
__global__ __launch_bounds__(256) void k_agg(
    const int* __restrict__ off, const int2* __restrict__ epack,
    const float* __restrict__ t, const float* __restrict__ dinv,
    const float* __restrict__ bias, float* __restrict__ out, int n)
{
    int w = (blockIdx.x * blockDim.x + threadIdx.x) >> 5;
    if (w >= n) return;
    int lane = threadIdx.x & 31;

    const float4* tp = (const float4*)t;
    int beg = __ldg(off + w);
    int end = __ldg(off + w + 1);

    float di = __ldg(dinv + w);
    float s = di * di;
    float4 acc = tp[(size_t)w * 32 + lane];
    acc.x *= s; acc.y *= s; acc.z *= s; acc.w *= s;

    int e = beg;
    for (; e + 3 < end; e += 4) {
        int2 p0 = __ldg(epack + e);
        int2 p1 = __ldg(epack + e + 1);
        int2 p2 = __ldg(epack + e + 2);
        int2 p3 = __ldg(epack + e + 3);
        float4 h0 = tp[(size_t)p0.x * 32 + lane];
        float4 h1 = tp[(size_t)p1.x * 32 + lane];
        float4 h2 = tp[(size_t)p2.x * 32 + lane];
        float4 h3 = tp[(size_t)p3.x * 32 + lane];
        float c0 = __int_as_float(p0.y), c1 = __int_as_float(p1.y);
        float c2 = __int_as_float(p2.y), c3 = __int_as_float(p3.y);
        acc.x += c0 * h0.x + c1 * h1.x + c2 * h2.x + c3 * h3.x;
        acc.y += c0 * h0.y + c1 * h1.y + c2 * h2.y + c3 * h3.y;
        acc.z += c0 * h0.z + c1 * h1.z + c2 * h2.z + c3 * h3.z;
        acc.w += c0 * h0.w + c1 * h1.w + c2 * h2.w + c3 * h3.w;
    }
    for (; e < end; e++) {
        int2 p0 = __ldg(epack + e);
        float c0 = __int_as_float(p0.y);
        float4 h0 = tp[(size_t)p0.x * 32 + lane];
        acc.x += c0 * h0.x;
        acc.y += c0 * h0.y;
        acc.z += c0 * h0.z;
        acc.w += c0 * h0.w;
    }

    float4 bv = *(const float4*)&bias[lane * 4];
    acc.x = fmaxf(acc.x + bv.x, 0.f);
    acc.y = fmaxf(acc.y + bv.y, 0.f);
    acc.z = fmaxf(acc.z + bv.z, 0.f);
    acc.w = fmaxf(acc.w + bv.w, 0.f);
    ((float4*)out)[(size_t)w * 32 + lane] = acc;
}

// ================= logits + softmax =================
__global__ __launch_bounds__(256) void k_logits_softmax(
    const float* __restrict__ h, const float* __restrict__ Wl2,
    const float* __restrict__ bl2, float* __restrict__ out, int M)
{
    __shared__ float hs[8][128];
    int tid = threadIdx.x;
    int warp = tid >> 5;
    int lane = tid & 31;
    int row0 = blockIdx.x * 8;

    {
        int rloc = tid >> 5;
        int cloc = (tid & 31) * 4;
        int r = row0 + rloc;
        float4 v = make_float4(0.f, 0.f, 0.f, 0.f);
        if (r < M) v = *(const float4*)&h[(size_t)r * 128 + cloc];
        *(float4*)&hs[rloc][cloc] = v;
    }
    __syncthreads();

    int r = row0 + warp;
    if (r >= M) return;

    float acc = bl2[lane];
#pragma unroll
    for (int k = 0; k < 128; k++) {
        acc += hs[warp][k] * __ldg(&Wl2[(size_t)k * 32 + lane]);
    }

    float m = acc;
#pragma unroll
    for (int o = 16; o >= 1; o >>= 1) m = fmaxf(m, __shfl_xor_sync(0xFFFFFFFFu, m, o));
    float e = __expf(acc - m);
    float s = e;
#pragma unroll
    for (int o = 16; o >= 1; o >>= 1) s += __shfl_xor_sync(0xFFFFFFFFu, s, o);
    out[(size_t)r * 32 + lane] = e / s;
}

// ================= launch =================
extern "C" void kernel_launch(void* const* d_in, const int* in_sizes, int n_in,
                              void* d_out, int out_size)
{
    const float* x   = (const float*)d_in[0];
    const int*   ei  = (const int*)d_in[1];
    const float* ew  = (const float*)d_in[2];
    const float* Wp  = (const float*)d_in[3];
    const float* bp  = (const float*)d_in[4];
    const float* W1  = (const float*)d_in[5];
    const float* b1  = (const float*)d_in[6];
    const float* W2  = (const float*)d_in[7];
    const float* b2  = (const float*)d_in[8];
    const float* Wl1 = (const float*)d_in[9];
    const float* bl1 = (const float*)d_in[10];
    const float* Wl2 = (const float*)d_in[11];
    const float* bl2 = (const float*)d_in[12];
    float* out = (float*)d_out;

    const int M = in_sizes[0] / 256;   // 100000
    const int E = in_sizes[1] / 2;     // 1600000
    const int* src = ei;
    const int* dst = ei + E;

    float *p_h, *p_t, *p_deg, *p_dinv;
    int *p_cnt, *p_off, *p_cur, *p_part;
    int2 *p_epack;
    __nv_bfloat16 *p_whi, *p_wlo;
    cudaGetSymbolAddress((void**)&p_h, g_h);
    cudaGetSymbolAddress((void**)&p_t, g_t);
    cudaGetSymbolAddress((void**)&p_deg, g_deg);
    cudaGetSymbolAddress((void**)&p_dinv, g_dinv);
    cudaGetSymbolAddress((void**)&p_cnt, g_cnt);
    cudaGetSymbolAddress((void**)&p_off, g_off);
    cudaGetSymbolAddress((void**)&p_cur, g_cur);
    cudaGetSymbolAddress((void**)&p_epack, g_epack);
    cudaGetSymbolAddress((void**)&p_part, g_part);
    cudaGetSymbolAddress((void**)&p_whi, g_whi);
    cudaGetSymbolAddress((void**)&p_wlo, g_wlo);

    cudaFuncSetAttribute(k_gemm_mma<256, 0>, cudaFuncAttributeMaxDynamicSharedMemorySize, GEMM_SMEM);
    cudaFuncSetAttribute(k_gemm_mma<128, 1>, cudaFuncAttributeMaxDynamicSharedMemorySize, GEMM_SMEM);
    cudaFuncSetAttribute(k_gemm_mma<128, 0>, cudaFuncAttributeMaxDynamicSharedMemorySize, GEMM_SMEM);

    const int gemm_blocks = (M + 63) / 64;
    const int agg_blocks  = (M + 7) / 8;
    const int scan_blocks = (M + SCAN_CHUNK - 1) / SCAN_CHUNK;

    // weight transpose + split (tiny)
    k_prep_w<<<(256 * 128 + 255) / 256, 256>>>(Wp,  256, 128, p_whi,         p_wlo);
    k_prep_w<<<(128 * 128 + 255) / 256, 256>>>(W1,  128, 128, p_whi + 32768, p_wlo + 32768);
    k_prep_w<<<(128 * 128 + 255) / 256, 256>>>(W2,  128, 128, p_whi + 49152, p_wlo + 49152);
    k_prep_w<<<(128 * 128 + 255) / 256, 256>>>(Wl1, 128, 128, p_whi + 65536, p_wlo + 65536);

    // CSR build + normalization (reused by both conv layers)
    k_init<<<(M + 255) / 256, 256>>>(p_deg, p_cnt, M);
    k_edge_deg<<<(E + 255) / 256, 256>>>(dst, ew, p_deg, p_cnt, E);
    k_dinv<<<(M + 255) / 256, 256>>>(p_deg, p_dinv, M);
    k_scan1<<<scan_blocks, SCAN_CHUNK>>>(p_cnt, p_part, M);
    k_scan2<<<1, 512>>>(p_part, scan_blocks);
    k_scan3<<<scan_blocks, SCAN_CHUNK>>>(p_cnt, p_part, p_off, p_cur, M, E);
    k_scatter<<<(E + 255) / 256, 256>>>(src, dst, ew, p_dinv, p_cur, p_epack, E);

    // h0 = relu(x @ Wp + bp)
    k_gemm_mma<256, 0><<<gemm_blocks, 128, GEMM_SMEM>>>(x, p_whi, p_wlo, bp, p_h, M);

    // conv1: t = h0 @ W1; h = relu(aggregate(t) + b1)
    k_gemm_mma<128, 1><<<gemm_blocks, 128, GEMM_SMEM>>>(p_h, p_whi + 32768, p_wlo + 32768, nullptr, p_t, M);
    k_agg<<<agg_blocks, 256>>>(p_off, p_epack, p_t, p_dinv, b1, p_h, M);

    // conv2
    k_gemm_mma<128, 1><<<gemm_blocks, 128, GEMM_SMEM>>>(p_h, p_whi + 49152, p_wlo + 49152, nullptr, p_t, M);
    k_agg<<<agg_blocks, 256>>>(p_off, p_epack, p_t, p_dinv, b2, p_h, M);

    // h = relu(h @ Wl1 + bl1)
    k_gemm_mma<128, 0><<<gemm_blocks, 128, GEMM_SMEM>>>(p_h, p_whi + 65536, p_wlo + 65536, bl1, p_t, M);

    // softmax(h @ Wl2 + bl2)
    k_logits_softmax<<<(M + 7) / 8, 256>>>(p_t, Wl2, bl2, out, M);
}

// round 9
// speedup vs baseline: 1.2227x; 1.1499x over previous
#include <cuda_runtime.h>
#include <cuda_bf16.h>
#include <math.h>
#include <stdint.h>

#define NN 100000
#define EE 1600000
#define SCAN_CHUNK 256

// Scratch (no device allocation allowed)
__device__ float g_h[(size_t)NN * 128];
__device__ float g_t[(size_t)NN * 128];
__device__ unsigned long long g_degcnt[NN];   // packed: cnt<<40 | ew_sum*2^24
__device__ float g_dinv[NN];
__device__ int   g_cnt[NN];
__device__ int   g_off[NN + 1];
__device__ int   g_cur[NN];
__device__ int2  g_epack[EE];     // {src, coef-as-int}
__device__ int   g_part[512];
// transposed + split weights: Wp^T @0 (128x256), W1^T @32768, W2^T @49152, Wl1^T @65536
__device__ __nv_bfloat16 g_whi[81920];
__device__ __nv_bfloat16 g_wlo[81920];

// ================= mma.sync / cp.async helpers (baseline PTX, sm_80+) =================
__device__ __forceinline__ void ldsm4(uint32_t d[4], const void* p) {
    uint32_t a = (uint32_t)__cvta_generic_to_shared(p);
    asm volatile("ldmatrix.sync.aligned.m8n8.x4.shared.b16 {%0,%1,%2,%3}, [%4];"
        : "=r"(d[0]), "=r"(d[1]), "=r"(d[2]), "=r"(d[3]) : "r"(a));
}
__device__ __forceinline__ void ldsm2(uint32_t d[2], const void* p) {
    uint32_t a = (uint32_t)__cvta_generic_to_shared(p);
    asm volatile("ldmatrix.sync.aligned.m8n8.x2.shared.b16 {%0,%1}, [%2];"
        : "=r"(d[0]), "=r"(d[1]) : "r"(a));
}
__device__ __forceinline__ void mma16816(float c[4], const uint32_t a[4], const uint32_t b[2]) {
    asm volatile("mma.sync.aligned.m16n8k16.row.col.f32.bf16.bf16.f32 "
        "{%0,%1,%2,%3}, {%4,%5,%6,%7}, {%8,%9}, {%0,%1,%2,%3};"
        : "+f"(c[0]), "+f"(c[1]), "+f"(c[2]), "+f"(c[3])
        : "r"(a[0]), "r"(a[1]), "r"(a[2]), "r"(a[3]), "r"(b[0]), "r"(b[1]));
}
__device__ __forceinline__ uint32_t pack_bf16(__nv_bfloat16 a, __nv_bfloat16 b) {
    return (uint32_t)__bfloat16_as_ushort(a) | ((uint32_t)__bfloat16_as_ushort(b) << 16);
}
__device__ __forceinline__ void split8(const float4& v0, const float4& v1,
                                       uint4& uh, uint4& ul) {
    float f[8] = {v0.x, v0.y, v0.z, v0.w, v1.x, v1.y, v1.z, v1.w};
    uint32_t h[4], l[4];
#pragma unroll
    for (int j = 0; j < 4; j++) {
        __nv_bfloat16 h0 = __float2bfloat16(f[2*j]);
        __nv_bfloat16 h1 = __float2bfloat16(f[2*j+1]);
        __nv_bfloat16 l0 = __float2bfloat16(f[2*j]   - __bfloat162float(h0));
        __nv_bfloat16 l1 = __float2bfloat16(f[2*j+1] - __bfloat162float(h1));
        h[j] = pack_bf16(h0, h1);
        l[j] = pack_bf16(l0, l1);
    }
    uh = make_uint4(h[0], h[1], h[2], h[3]);
    ul = make_uint4(l[0], l[1], l[2], l[3]);
}
__device__ __forceinline__ void cp16(void* dst_smem, const void* src) {
    uint32_t d = (uint32_t)__cvta_generic_to_shared(dst_smem);
    asm volatile("cp.async.cg.shared.global [%0], [%1], 16;" :: "r"(d), "l"(src) : "memory");
}
#define CP_COMMIT() asm volatile("cp.async.commit_group;" ::: "memory")
#define CP_WAIT0()  asm volatile("cp.async.wait_group 0;" ::: "memory")

// ================= CSR build =================
__global__ void k_init(unsigned long long* degcnt, int n) {
    int i = blockIdx.x * blockDim.x + threadIdx.x;
    if (i < n) degcnt[i] = 0ull;
}
// one packed 64-bit atomic per edge: cnt in bits [40:64), ew fixed-point 2^-24 in [0:40)
__global__ void k_edge_deg(const int* __restrict__ dst, const float* __restrict__ ew,
                           unsigned long long* degcnt, int E) {
    int e = blockIdx.x * blockDim.x + threadIdx.x;
    if (e < E) {
        unsigned long long v = (1ull << 40)
            + (unsigned long long)((double)ew[e] * 16777216.0);
        atomicAdd(&degcnt[dst[e]], v);
    }
}
__global__ void k_dinv(const unsigned long long* __restrict__ degcnt,
                       float* dinv, int* cnt, int n) {
    int i = blockIdx.x * blockDim.x + threadIdx.x;
    if (i < n) {
        unsigned long long v = degcnt[i];
        cnt[i] = (int)(v >> 40);
        float deg = 1.0f + (float)((double)(v & ((1ull << 40) - 1)) * (1.0 / 16777216.0));
        dinv[i] = rsqrtf(deg);
    }
}
__global__ __launch_bounds__(SCAN_CHUNK) void k_scan1(const int* __restrict__ cnt,
                                                      int* part, int n) {
    __shared__ int ws[8];
    int i = blockIdx.x * SCAN_CHUNK + threadIdx.x;
    int v = (i < n) ? cnt[i] : 0;
#pragma unroll
    for (int o = 16; o >= 1; o >>= 1) v += __shfl_xor_sync(0xFFFFFFFFu, v, o);
    if ((threadIdx.x & 31) == 0) ws[threadIdx.x >> 5] = v;
    __syncthreads();
    if (threadIdx.x == 0) {
        int s = 0;
#pragma unroll
        for (int w = 0; w < 8; w++) s += ws[w];
        part[blockIdx.x] = s;
    }
}
__global__ __launch_bounds__(512) void k_scan2(int* part, int nb) {
    __shared__ int s[512];
    int tid = threadIdx.x;
    int v = (tid < nb) ? part[tid] : 0;
    s[tid] = v;
    __syncthreads();
#pragma unroll
    for (int d = 1; d < 512; d <<= 1) {
        int add = (tid >= d) ? s[tid - d] : 0;
        __syncthreads();
        s[tid] += add;
        __syncthreads();
    }
    if (tid < nb) part[tid] = s[tid] - v;
}
__global__ __launch_bounds__(SCAN_CHUNK) void k_scan3(const int* __restrict__ cnt,
                                                      const int* __restrict__ part,
                                                      int* off, int* cur, int n, int E) {
    __shared__ int ws[8];
    int tid = threadIdx.x;
    int i = blockIdx.x * SCAN_CHUNK + tid;
    int lane = tid & 31;
    int warp = tid >> 5;
    int v = (i < n) ? cnt[i] : 0;
    int x = v;
#pragma unroll
    for (int o = 1; o < 32; o <<= 1) {
        int y = __shfl_up_sync(0xFFFFFFFFu, x, o);
        if (lane >= o) x += y;
    }
    if (lane == 31) ws[warp] = x;
    __syncthreads();
    if (warp == 0 && lane < 8) {
        int y = ws[lane];
        int z = y;
#pragma unroll
        for (int o = 1; o < 8; o <<= 1) {
            int u = __shfl_up_sync(0xFFu, z, o);
            if (lane >= o) z += u;
        }
        ws[lane] = z - y;
    }
    __syncthreads();
    if (i < n) {
        int excl = part[blockIdx.x] + ws[warp] + x - v;
        off[i] = excl;
        cur[i] = excl;
    }
    if (i == n - 1) off[n] = E;
}
__global__ void k_scatter(const int* __restrict__ src, const int* __restrict__ dst,
                          const float* __restrict__ ew, const float* __restrict__ dinv,
                          int* cur, int2* epack, int E) {
    int e = blockIdx.x * blockDim.x + threadIdx.x;
    if (e >= E) return;
    int s = src[e];
    int d = dst[e];
    float c = __ldg(dinv + s) * ew[e] * __ldg(dinv + d);
    int pos = atomicAdd(&cur[d], 1);
    epack[pos] = make_int2(s, __float_as_int(c));
}

// ================= weight transpose + bf16 split =================
__global__ void k_prep_w(const float* __restrict__ W, int K, int N,
                         __nv_bfloat16* hi, __nv_bfloat16* lo) {
    int idx = blockIdx.x * blockDim.x + threadIdx.x;
    if (idx >= K * N) return;
    int n = idx / K, k = idx % K;
    float w = W[(size_t)k * N + n];
    __nv_bfloat16 h = __float2bfloat16(w);
    hi[idx] = h;
    lo[idx] = __float2bfloat16(w - __bfloat162float(h));
}

// ================= HMMA GEMM: out[M,128] = A[M,K] @ W[K,128] =================
// split-bf16 (hi/lo), mma.sync m16n8k16, BM=64 BN=128 BK=64, 256 threads (8 warps),
// warp grid 2x4 (each warp 32x32), 2-stage pipeline (cp.async B, reg prefetch A).
// EPI==0: out = relu(acc + bias);  EPI==1: out = acc
#define KP 72
#define A_BUF (64 * KP * 2)            // 9216 bytes per A hi/lo buffer
#define B_BUF (128 * KP * 2)           // 18432 bytes per B hi/lo buffer
#define OFF_AH 0
#define OFF_AL (2 * A_BUF)
#define OFF_BH (4 * A_BUF)
#define OFF_BL (4 * A_BUF + 2 * B_BUF)
#define GEMM_SMEM (4 * A_BUF + 4 * B_BUF)   // 110592 bytes

template <int K, int EPI>
__global__ __launch_bounds__(256) void k_gemm_mma(
    const float* __restrict__ A, const __nv_bfloat16* __restrict__ Whi,
    const __nv_bfloat16* __restrict__ Wlo, const float* __restrict__ bias,
    float* __restrict__ out, int M)
{
    extern __shared__ char sm[];

    const int tid  = threadIdx.x;
    const int wid  = tid >> 5;
    const int lane = tid & 31;
    const int wm   = wid & 1;       // warp row: 32 output rows
    const int wn   = wid >> 1;      // warp col (0..3): 32 output cols
    const int row0 = blockIdx.x * 64;
    constexpr int CHUNKS = K / 64;

    // A fill mapping: row = tid>>2 (0..63), 16 floats at col (tid&3)*16
    const int ar = tid >> 2;
    const int ac = (tid & 3) * 16;
    const int gr = row0 + ar;
    const bool aok = gr < M;
    const float4* arow = (const float4*)(A + (size_t)gr * K + ac);
    // B fill mapping: row = tid>>1 (0..127), 32 bf16 at col (tid&1)*32
    const int br = tid >> 1;
    const int bc = (tid & 1) * 32;
    const __nv_bfloat16* bh_row = Whi + (size_t)br * K + bc;
    const __nv_bfloat16* bl_row = Wlo + (size_t)br * K + bc;

    float acc[2][4][4];
#pragma unroll
    for (int mt = 0; mt < 2; mt++)
#pragma unroll
        for (int nt = 0; nt < 4; nt++)
#pragma unroll
            for (int j = 0; j < 4; j++) acc[mt][nt][j] = 0.0f;

    float4 areg[4];
    const float4 z4 = make_float4(0.f, 0.f, 0.f, 0.f);

    // ---- prologue: stage chunk 0 into buf 0 ----
    {
        __nv_bfloat16* dbh = (__nv_bfloat16*)(sm + OFF_BH) + br * KP + bc;
        __nv_bfloat16* dbl = (__nv_bfloat16*)(sm + OFF_BL) + br * KP + bc;
#pragma unroll
        for (int j = 0; j < 4; j++) {
            cp16(dbh + j * 8, bh_row + j * 8);
            cp16(dbl + j * 8, bl_row + j * 8);
        }
        CP_COMMIT();
#pragma unroll
        for (int j = 0; j < 4; j++) areg[j] = aok ? arow[j] : z4;
        __nv_bfloat16* dah = (__nv_bfloat16*)(sm + OFF_AH) + ar * KP + ac;
        __nv_bfloat16* dal = (__nv_bfloat16*)(sm + OFF_AL) + ar * KP + ac;
#pragma unroll
        for (int j = 0; j < 2; j++) {
            uint4 uh, ul;
            split8(areg[2*j], areg[2*j+1], uh, ul);
            *(uint4*)(dah + j * 8) = uh;
            *(uint4*)(dal + j * 8) = ul;
        }
        CP_WAIT0();
    }
    __syncthreads();

#pragma unroll
    for (int c = 0; c < CHUNKS; c++) {
        const int buf = c & 1;
        const int nbuf = buf ^ 1;
        const bool more = (c + 1) < CHUNKS;

        // stage next chunk: cp.async B, LDG A into regs (latency hidden under MMAs)
        if (more) {
            int kn = (c + 1) * 64;
            __nv_bfloat16* dbh = (__nv_bfloat16*)(sm + OFF_BH + nbuf * B_BUF) + br * KP + bc;
            __nv_bfloat16* dbl = (__nv_bfloat16*)(sm + OFF_BL + nbuf * B_BUF) + br * KP + bc;
#pragma unroll
            for (int j = 0; j < 4; j++) {
                cp16(dbh + j * 8, bh_row + kn + j * 8);
                cp16(dbl + j * 8, bl_row + kn + j * 8);
            }
            CP_COMMIT();
#pragma unroll
            for (int j = 0; j < 4; j++) areg[j] = aok ? arow[kn / 4 + j] : z4;
        }

        // ---- MMA on current buffer ----
        const __nv_bfloat16* Ah = (const __nv_bfloat16*)(sm + OFF_AH + buf * A_BUF);
        const __nv_bfloat16* Al = (const __nv_bfloat16*)(sm + OFF_AL + buf * A_BUF);
        const __nv_bfloat16* Bh = (const __nv_bfloat16*)(sm + OFF_BH + buf * B_BUF);
        const __nv_bfloat16* Bl = (const __nv_bfloat16*)(sm + OFF_BL + buf * B_BUF);
#pragma unroll
        for (int ks = 0; ks < 64; ks += 16) {
            uint32_t ah[2][4], al[2][4], bhf[4][2], blf[4][2];
#pragma unroll
            for (int mt = 0; mt < 2; mt++) {
                int r = wm * 32 + mt * 16 + (lane & 15);
                int cc = ks + ((lane >> 4) << 3);
                ldsm4(ah[mt], Ah + r * KP + cc);
                ldsm4(al[mt], Al + r * KP + cc);
            }
#pragma unroll
            for (int nt = 0; nt < 4; nt++) {
                int n = wn * 32 + nt * 8 + (lane & 7);
                int cc = ks + ((lane >> 3) & 1) * 8;
                ldsm2(bhf[nt], Bh + n * KP + cc);
                ldsm2(blf[nt], Bl + n * KP + cc);
            }
#pragma unroll
            for (int mt = 0; mt < 2; mt++)
#pragma unroll
                for (int nt = 0; nt < 4; nt++) {
                    mma16816(acc[mt][nt], ah[mt], bhf[nt]);
                    mma16816(acc[mt][nt], ah[mt], blf[nt]);
                    mma16816(acc[mt][nt], al[mt], bhf[nt]);
                }
        }

        if (more) {
            // convert + STS next A into nbuf, then drain cp.async
            __nv_bfloat16* dah = (__nv_bfloat16*)(sm + OFF_AH + nbuf * A_BUF) + ar * KP + ac;
            __nv_bfloat16* dal = (__nv_bfloat16*)(sm + OFF_AL + nbuf * A_BUF) + ar * KP + ac;
#pragma unroll
            for (int j = 0; j < 2; j++) {
                uint4 uh, ul;
                split8(areg[2*j], areg[2*j+1], uh, ul);
                *(uint4*)(dah + j * 8) = uh;
                *(uint4*)(dal + j * 8) = ul;
            }
            CP_WAIT0();
            __syncthreads();
        }
    }

    // ---- epilogue ----
#pragma unroll
    for (int mt = 0; mt < 2; mt++) {
        int r1 = row0 + wm * 32 + mt * 16 + (lane >> 2);
        int r2 = r1 + 8;
#pragma unroll
        for (int nt = 0; nt < 4; nt++) {
            int c = wn * 32 + nt * 8 + (lane & 3) * 2;
            float2 v1 = make_float2(acc[mt][nt][0], acc[mt][nt][1]);
            float2 v2 = make_float2(acc[mt][nt][2], acc[mt][nt][3]);
            if (EPI == 0) {
                float b0 = __ldg(bias + c), b1 = __ldg(bias + c + 1);
                v1.x = fmaxf(v1.x + b0, 0.f); v1.y = fmaxf(v1.y + b1, 0.f);
                v2.x = fmaxf(v2.x + b0, 0.f); v2.y = fmaxf(v2.y + b1, 0.f);
            }
            if (r1 < M) *(float2*)&out[(size_t)r1 * 128 + c] = v1;
            if (r2 < M) *(float2*)&out[(size_t)r2 * 128 + c] = v2;
        }
    }
}

// ================= gather aggregation: one warp per node =================
__global__ __launch_bounds__(256) void k_agg(
    const int* __restrict__ off, const int2* __restrict__ epack,
    const float* __restrict__ t, const float* __restrict__ dinv,
    const float* __restrict__ bias, float* __restrict__ out, int n)
{
    int w = (blockIdx.x * blockDim.x + threadIdx.x) >> 5;
    if (w >= n) return;
    int lane = threadIdx.x & 31;

    const float4* tp = (const float4*)t;
    int beg = __ldg(off + w);
    int end = __ldg(off + w + 1);

    float di = __ldg(dinv + w);
    float s = di * di;
    float4 acc = tp[(size_t)w * 32 + lane];
    acc.x *= s; acc.y *= s; acc.z *= s; acc.w *= s;

    int e = beg;
    for (; e + 3 < end; e += 4) {
        int2 p0 = __ldg(epack + e);
        int2 p1 = __ldg(epack + e + 1);
        int2 p2 = __ldg(epack + e + 2);
        int2 p3 = __ldg(epack + e + 3);
        float4 h0 = tp[(size_t)p0.x * 32 + lane];
        float4 h1 = tp[(size_t)p1.x * 32 + lane];
        float4 h2 = tp[(size_t)p2.x * 32 + lane];
        float4 h3 = tp[(size_t)p3.x * 32 + lane];
        float c0 = __int_as_float(p0.y), c1 = __int_as_float(p1.y);
        float c2 = __int_as_float(p2.y), c3 = __int_as_float(p3.y);
        acc.x += c0 * h0.x + c1 * h1.x + c2 * h2.x + c3 * h3.x;
        acc.y += c0 * h0.y + c1 * h1.y + c2 * h2.y + c3 * h3.y;
        acc.z += c0 * h0.z + c1 * h1.z + c2 * h2.z + c3 * h3.z;
        acc.w += c0 * h0.w + c1 * h1.w + c2 * h2.w + c3 * h3.w;
    }
    for (; e < end; e++) {
        int2 p0 = __ldg(epack + e);
        float c0 = __int_as_float(p0.y);
        float4 h0 = tp[(size_t)p0.x * 32 + lane];
        acc.x += c0 * h0.x;
        acc.y += c0 * h0.y;
        acc.z += c0 * h0.z;
        acc.w += c0 * h0.w;
    }

    float4 bv = *(const float4*)&bias[lane * 4];
    acc.x = fmaxf(acc.x + bv.x, 0.f);
    acc.y = fmaxf(acc.y + bv.y, 0.f);
    acc.z = fmaxf(acc.z + bv.z, 0.f);
    acc.w = fmaxf(acc.w + bv.w, 0.f);
    ((float4*)out)[(size_t)w * 32 + lane] = acc;
}

// ================= logits + softmax =================
__global__ __launch_bounds__(256) void k_logits_softmax(
    const float* __restrict__ h, const float* __restrict__ Wl2,
    const float* __restrict__ bl2, float* __restrict__ out, int M)
{
    __shared__ float hs[8][128];
    int tid = threadIdx.x;
    int warp = tid >> 5;
    int lane = tid & 31;
    int row0 = blockIdx.x * 8;

    {
        int rloc = tid >> 5;
        int cloc = (tid & 31) * 4;
        int r = row0 + rloc;
        float4 v = make_float4(0.f, 0.f, 0.f, 0.f);
        if (r < M) v = *(const float4*)&h[(size_t)r * 128 + cloc];
        *(float4*)&hs[rloc][cloc] = v;
    }
    __syncthreads();

    int r = row0 + warp;
    if (r >= M) return;

    float acc = bl2[lane];
#pragma unroll
    for (int k = 0; k < 128; k++) {
        acc += hs[warp][k] * __ldg(&Wl2[(size_t)k * 32 + lane]);
    }

    float m = acc;
#pragma unroll
    for (int o = 16; o >= 1; o >>= 1) m = fmaxf(m, __shfl_xor_sync(0xFFFFFFFFu, m, o));
    float e = __expf(acc - m);
    float s = e;
#pragma unroll
    for (int o = 16; o >= 1; o >>= 1) s += __shfl_xor_sync(0xFFFFFFFFu, s, o);
    out[(size_t)r * 32 + lane] = e / s;
}

// ================= launch =================
extern "C" void kernel_launch(void* const* d_in, const int* in_sizes, int n_in,
                              void* d_out, int out_size)
{
    const float* x   = (const float*)d_in[0];
    const int*   ei  = (const int*)d_in[1];
    const float* ew  = (const float*)d_in[2];
    const float* Wp  = (const float*)d_in[3];
    const float* bp  = (const float*)d_in[4];
    const float* W1  = (const float*)d_in[5];
    const float* b1  = (const float*)d_in[6];
    const float* W2  = (const float*)d_in[7];
    const float* b2  = (const float*)d_in[8];
    const float* Wl1 = (const float*)d_in[9];
    const float* bl1 = (const float*)d_in[10];
    const float* Wl2 = (const float*)d_in[11];
    const float* bl2 = (const float*)d_in[12];
    float* out = (float*)d_out;

    const int M = in_sizes[0] / 256;   // 100000
    const int E = in_sizes[1] / 2;     // 1600000
    const int* src = ei;
    const int* dst = ei + E;

    float *p_h, *p_t, *p_dinv;
    unsigned long long* p_degcnt;
    int *p_cnt, *p_off, *p_cur, *p_part;
    int2 *p_epack;
    __nv_bfloat16 *p_whi, *p_wlo;
    cudaGetSymbolAddress((void**)&p_h, g_h);
    cudaGetSymbolAddress((void**)&p_t, g_t);
    cudaGetSymbolAddress((void**)&p_degcnt, g_degcnt);
    cudaGetSymbolAddress((void**)&p_dinv, g_dinv);
    cudaGetSymbolAddress((void**)&p_cnt, g_cnt);
    cudaGetSymbolAddress((void**)&p_off, g_off);
    cudaGetSymbolAddress((void**)&p_cur, g_cur);
    cudaGetSymbolAddress((void**)&p_epack, g_epack);
    cudaGetSymbolAddress((void**)&p_part, g_part);
    cudaGetSymbolAddress((void**)&p_whi, g_whi);
    cudaGetSymbolAddress((void**)&p_wlo, g_wlo);

    cudaFuncSetAttribute(k_gemm_mma<256, 0>, cudaFuncAttributeMaxDynamicSharedMemorySize, GEMM_SMEM);
    cudaFuncSetAttribute(k_gemm_mma<128, 1>, cudaFuncAttributeMaxDynamicSharedMemorySize, GEMM_SMEM);
    cudaFuncSetAttribute(k_gemm_mma<128, 0>, cudaFuncAttributeMaxDynamicSharedMemorySize, GEMM_SMEM);

    const int gemm_blocks = (M + 63) / 64;
    const int agg_blocks  = (M + 7) / 8;
    const int scan_blocks = (M + SCAN_CHUNK - 1) / SCAN_CHUNK;

    // weight transpose + split (tiny)
    k_prep_w<<<(256 * 128 + 255) / 256, 256>>>(Wp,  256, 128, p_whi,         p_wlo);
    k_prep_w<<<(128 * 128 + 255) / 256, 256>>>(W1,  128, 128, p_whi + 32768, p_wlo + 32768);
    k_prep_w<<<(128 * 128 + 255) / 256, 256>>>(W2,  128, 128, p_whi + 49152, p_wlo + 49152);
    k_prep_w<<<(128 * 128 + 255) / 256, 256>>>(Wl1, 128, 128, p_whi + 65536, p_wlo + 65536);

    // CSR build + normalization (reused by both conv layers)
    k_init<<<(M + 255) / 256, 256>>>(p_degcnt, M);
    k_edge_deg<<<(E + 255) / 256, 256>>>(dst, ew, p_degcnt, E);
    k_dinv<<<(M + 255) / 256, 256>>>(p_degcnt, p_dinv, p_cnt, M);
    k_scan1<<<scan_blocks, SCAN_CHUNK>>>(p_cnt, p_part, M);
    k_scan2<<<1, 512>>>(p_part, scan_blocks);
    k_scan3<<<scan_blocks, SCAN_CHUNK>>>(p_cnt, p_part, p_off, p_cur, M, E);
    k_scatter<<<(E + 255) / 256, 256>>>(src, dst, ew, p_dinv, p_cur, p_epack, E);

    // h0 = relu(x @ Wp + bp)
    k_gemm_mma<256, 0><<<gemm_blocks, 256, GEMM_SMEM>>>(x, p_whi, p_wlo, bp, p_h, M);

    // conv1: t = h0 @ W1; h = relu(aggregate(t) + b1)
    k_gemm_mma<128, 1><<<gemm_blocks, 256, GEMM_SMEM>>>(p_h, p_whi + 32768, p_wlo + 32768, nullptr, p_t, M);
    k_agg<<<agg_blocks, 256>>>(p_off, p_epack, p_t, p_dinv, b1, p_h, M);

    // conv2
    k_gemm_mma<128, 1><<<gemm_blocks, 256, GEMM_SMEM>>>(p_h, p_whi + 49152, p_wlo + 49152, nullptr, p_t, M);
    k_agg<<<agg_blocks, 256>>>(p_off, p_epack, p_t, p_dinv, b2, p_h, M);

    // h = relu(h @ Wl1 + bl1)
    k_gemm_mma<128, 0><<<gemm_blocks, 256, GEMM_SMEM>>>(p_h, p_whi + 65536, p_wlo + 65536, bl1, p_t, M);

    // softmax(h @ Wl2 + bl2)
    k_logits_softmax<<<(M + 7) / 8, 256>>>(p_t, Wl2, bl2, out, M);
}

// round 10
// speedup vs baseline: 1.3991x; 1.1443x over previous
#include <cuda_runtime.h>
#include <cuda_bf16.h>
#include <math.h>
#include <stdint.h>

#define NN 100000
#define EE 1600000
#define SCAN_CHUNK 256

// Scratch (no device allocation allowed)
__device__ float g_h[(size_t)NN * 128];
__device__ float g_t[(size_t)NN * 128];
__device__ unsigned long long g_degcnt[NN];   // packed: cnt<<40 | ew_sum*2^24
__device__ float g_dinv[NN];
__device__ int   g_cnt[NN];
__device__ int   g_off[NN + 1];
__device__ int   g_cur[NN];
__device__ int2  g_epack[EE];     // {src, coef-as-int}
__device__ int   g_part[512];
// transposed bf16 weights: Wp^T @0 (128x256), W1^T @32768, W2^T @49152, Wl1^T @65536
__device__ __nv_bfloat16 g_whi[81920];

// ================= mma.sync / cp.async helpers (baseline PTX, sm_80+) =================
__device__ __forceinline__ void ldsm4(uint32_t d[4], const void* p) {
    uint32_t a = (uint32_t)__cvta_generic_to_shared(p);
    asm volatile("ldmatrix.sync.aligned.m8n8.x4.shared.b16 {%0,%1,%2,%3}, [%4];"
        : "=r"(d[0]), "=r"(d[1]), "=r"(d[2]), "=r"(d[3]) : "r"(a));
}
__device__ __forceinline__ void ldsm2(uint32_t d[2], const void* p) {
    uint32_t a = (uint32_t)__cvta_generic_to_shared(p);
    asm volatile("ldmatrix.sync.aligned.m8n8.x2.shared.b16 {%0,%1}, [%2];"
        : "=r"(d[0]), "=r"(d[1]) : "r"(a));
}
__device__ __forceinline__ void mma16816(float c[4], const uint32_t a[4], const uint32_t b[2]) {
    asm volatile("mma.sync.aligned.m16n8k16.row.col.f32.bf16.bf16.f32 "
        "{%0,%1,%2,%3}, {%4,%5,%6,%7}, {%8,%9}, {%0,%1,%2,%3};"
        : "+f"(c[0]), "+f"(c[1]), "+f"(c[2]), "+f"(c[3])
        : "r"(a[0]), "r"(a[1]), "r"(a[2]), "r"(a[3]), "r"(b[0]), "r"(b[1]));
}
__device__ __forceinline__ uint32_t pack_bf16(__nv_bfloat16 a, __nv_bfloat16 b) {
    return (uint32_t)__bfloat16_as_ushort(a) | ((uint32_t)__bfloat16_as_ushort(b) << 16);
}
__device__ __forceinline__ void split8(const float4& v0, const float4& v1,
                                       uint4& uh, uint4& ul) {
    float f[8] = {v0.x, v0.y, v0.z, v0.w, v1.x, v1.y, v1.z, v1.w};
    uint32_t h[4], l[4];
#pragma unroll
    for (int j = 0; j < 4; j++) {
        __nv_bfloat16 h0 = __float2bfloat16(f[2*j]);
        __nv_bfloat16 h1 = __float2bfloat16(f[2*j+1]);
        __nv_bfloat16 l0 = __float2bfloat16(f[2*j]   - __bfloat162float(h0));
        __nv_bfloat16 l1 = __float2bfloat16(f[2*j+1] - __bfloat162float(h1));
        h[j] = pack_bf16(h0, h1);
        l[j] = pack_bf16(l0, l1);
    }
    uh = make_uint4(h[0], h[1], h[2], h[3]);
    ul = make_uint4(l[0], l[1], l[2], l[3]);
}
__device__ __forceinline__ void cp16(void* dst_smem, const void* src) {
    uint32_t d = (uint32_t)__cvta_generic_to_shared(dst_smem);
    asm volatile("cp.async.cg.shared.global [%0], [%1], 16;" :: "r"(d), "l"(src) : "memory");
}
#define CP_COMMIT() asm volatile("cp.async.commit_group;" ::: "memory")
#define CP_WAIT0()  asm volatile("cp.async.wait_group 0;" ::: "memory")

// ================= CSR build =================
__global__ void k_init(unsigned long long* degcnt, int n) {
    int i = blockIdx.x * blockDim.x + threadIdx.x;
    if (i < n) degcnt[i] = 0ull;
}
__global__ void k_edge_deg(const int* __restrict__ dst, const float* __restrict__ ew,
                           unsigned long long* degcnt, int E) {
    int e = blockIdx.x * blockDim.x + threadIdx.x;
    if (e < E) {
        unsigned long long v = (1ull << 40)
            + (unsigned long long)((double)ew[e] * 16777216.0);
        atomicAdd(&degcnt[dst[e]], v);
    }
}
__global__ void k_dinv(const unsigned long long* __restrict__ degcnt,
                       float* dinv, int* cnt, int n) {
    int i = blockIdx.x * blockDim.x + threadIdx.x;
    if (i < n) {
        unsigned long long v = degcnt[i];
        cnt[i] = (int)(v >> 40);
        float deg = 1.0f + (float)((double)(v & ((1ull << 40) - 1)) * (1.0 / 16777216.0));
        dinv[i] = rsqrtf(deg);
    }
}
__global__ __launch_bounds__(SCAN_CHUNK) void k_scan1(const int* __restrict__ cnt,
                                                      int* part, int n) {
    __shared__ int ws[8];
    int i = blockIdx.x * SCAN_CHUNK + threadIdx.x;
    int v = (i < n) ? cnt[i] : 0;
#pragma unroll
    for (int o = 16; o >= 1; o >>= 1) v += __shfl_xor_sync(0xFFFFFFFFu, v, o);
    if ((threadIdx.x & 31) == 0) ws[threadIdx.x >> 5] = v;
    __syncthreads();
    if (threadIdx.x == 0) {
        int s = 0;
#pragma unroll
        for (int w = 0; w < 8; w++) s += ws[w];
        part[blockIdx.x] = s;
    }
}
__global__ __launch_bounds__(512) void k_scan2(int* part, int nb) {
    __shared__ int s[512];
    int tid = threadIdx.x;
    int v = (tid < nb) ? part[tid] : 0;
    s[tid] = v;
    __syncthreads();
#pragma unroll
    for (int d = 1; d < 512; d <<= 1) {
        int add = (tid >= d) ? s[tid - d] : 0;
        __syncthreads();
        s[tid] += add;
        __syncthreads();
    }
    if (tid < nb) part[tid] = s[tid] - v;
}
__global__ __launch_bounds__(SCAN_CHUNK) void k_scan3(const int* __restrict__ cnt,
                                                      const int* __restrict__ part,
                                                      int* off, int* cur, int n, int E) {
    __shared__ int ws[8];
    int tid = threadIdx.x;
    int i = blockIdx.x * SCAN_CHUNK + tid;
    int lane = tid & 31;
    int warp = tid >> 5;
    int v = (i < n) ? cnt[i] : 0;
    int x = v;
#pragma unroll
    for (int o = 1; o < 32; o <<= 1) {
        int y = __shfl_up_sync(0xFFFFFFFFu, x, o);
        if (lane >= o) x += y;
    }
    if (lane == 31) ws[warp] = x;
    __syncthreads();
    if (warp == 0 && lane < 8) {
        int y = ws[lane];
        int z = y;
#pragma unroll
        for (int o = 1; o < 8; o <<= 1) {
            int u = __shfl_up_sync(0xFFu, z, o);
            if (lane >= o) z += u;
        }
        ws[lane] = z - y;
    }
    __syncthreads();
    if (i < n) {
        int excl = part[blockIdx.x] + ws[warp] + x - v;
        off[i] = excl;
        cur[i] = excl;
    }
    if (i == n - 1) off[n] = E;
}
__global__ void k_scatter(const int* __restrict__ src, const int* __restrict__ dst,
                          const float* __restrict__ ew, const float* __restrict__ dinv,
                          int* cur, int2* epack, int E) {
    int e = blockIdx.x * blockDim.x + threadIdx.x;
    if (e >= E) return;
    int s = src[e];
    int d = dst[e];
    float c = __ldg(dinv + s) * ew[e] * __ldg(dinv + d);
    int pos = atomicAdd(&cur[d], 1);
    epack[pos] = make_int2(s, __float_as_int(c));
}

// ================= weight transpose to bf16 =================
__global__ void k_prep_w(const float* __restrict__ W, int K, int N,
                         __nv_bfloat16* hi) {
    int idx = blockIdx.x * blockDim.x + threadIdx.x;
    if (idx >= K * N) return;
    int n = idx / K, k = idx % K;
    hi[idx] = __float2bfloat16(W[(size_t)k * N + n]);
}

// ================= HMMA GEMM: out[M,128] = A[M,K] @ W[K,128] =================
// A split (hi/lo bf16, 2 MMAs), W plain bf16. BM=64 BN=128 BK=64, 256 threads,
// warp grid 2x4 (each warp 32x32), 2-stage pipeline (cp.async B, reg prefetch A).
// EPI==0: out = relu(acc + bias);  EPI==1: out = acc
#define KP 72
#define A_BUF (64 * KP * 2)            // 9216 bytes per A hi/lo buffer
#define B_BUF (128 * KP * 2)           // 18432 bytes per B buffer
#define OFF_AH 0
#define OFF_AL (2 * A_BUF)
#define OFF_BH (4 * A_BUF)
#define GEMM_SMEM (4 * A_BUF + 2 * B_BUF)   // 73728 bytes -> 3 CTAs/SM

template <int K, int EPI>
__global__ __launch_bounds__(256) void k_gemm_mma(
    const float* __restrict__ A, const __nv_bfloat16* __restrict__ Whi,
    const float* __restrict__ bias, float* __restrict__ out, int M)
{
    extern __shared__ char sm[];

    const int tid  = threadIdx.x;
    const int wid  = tid >> 5;
    const int lane = tid & 31;
    const int wm   = wid & 1;       // warp row: 32 output rows
    const int wn   = wid >> 1;      // warp col (0..3): 32 output cols
    const int row0 = blockIdx.x * 64;
    constexpr int CHUNKS = K / 64;

    // A fill mapping: row = tid>>2 (0..63), 16 floats at col (tid&3)*16
    const int ar = tid >> 2;
    const int ac = (tid & 3) * 16;
    const int gr = row0 + ar;
    const bool aok = gr < M;
    const float4* arow = (const float4*)(A + (size_t)gr * K + ac);
    // B fill mapping: row = tid>>1 (0..127), 32 bf16 at col (tid&1)*32
    const int br = tid >> 1;
    const int bc = (tid & 1) * 32;
    const __nv_bfloat16* bh_row = Whi + (size_t)br * K + bc;

    float acc[2][4][4];
#pragma unroll
    for (int mt = 0; mt < 2; mt++)
#pragma unroll
        for (int nt = 0; nt < 4; nt++)
#pragma unroll
            for (int j = 0; j < 4; j++) acc[mt][nt][j] = 0.0f;

    float4 areg[4];
    const float4 z4 = make_float4(0.f, 0.f, 0.f, 0.f);

    // ---- prologue: stage chunk 0 into buf 0 ----
    {
        __nv_bfloat16* dbh = (__nv_bfloat16*)(sm + OFF_BH) + br * KP + bc;
#pragma unroll
        for (int j = 0; j < 4; j++) cp16(dbh + j * 8, bh_row + j * 8);
        CP_COMMIT();
#pragma unroll
        for (int j = 0; j < 4; j++) areg[j] = aok ? arow[j] : z4;
        __nv_bfloat16* dah = (__nv_bfloat16*)(sm + OFF_AH) + ar * KP + ac;
        __nv_bfloat16* dal = (__nv_bfloat16*)(sm + OFF_AL) + ar * KP + ac;
#pragma unroll
        for (int j = 0; j < 2; j++) {
            uint4 uh, ul;
            split8(areg[2*j], areg[2*j+1], uh, ul);
            *(uint4*)(dah + j * 8) = uh;
            *(uint4*)(dal + j * 8) = ul;
        }
        CP_WAIT0();
    }
    __syncthreads();

#pragma unroll
    for (int c = 0; c < CHUNKS; c++) {
        const int buf = c & 1;
        const int nbuf = buf ^ 1;
        const bool more = (c + 1) < CHUNKS;

        // stage next chunk: cp.async B, LDG A into regs (latency hidden under MMAs)
        if (more) {
            int kn = (c + 1) * 64;
            __nv_bfloat16* dbh = (__nv_bfloat16*)(sm + OFF_BH + nbuf * B_BUF) + br * KP + bc;
#pragma unroll
            for (int j = 0; j < 4; j++) cp16(dbh + j * 8, bh_row + kn + j * 8);
            CP_COMMIT();
#pragma unroll
            for (int j = 0; j < 4; j++) areg[j] = aok ? arow[kn / 4 + j] : z4;
        }

        // ---- MMA on current buffer ----
        const __nv_bfloat16* Ah = (const __nv_bfloat16*)(sm + OFF_AH + buf * A_BUF);
        const __nv_bfloat16* Al = (const __nv_bfloat16*)(sm + OFF_AL + buf * A_BUF);
        const __nv_bfloat16* Bh = (const __nv_bfloat16*)(sm + OFF_BH + buf * B_BUF);
#pragma unroll
        for (int ks = 0; ks < 64; ks += 16) {
            uint32_t ah[2][4], al[2][4], bhf[4][2];
#pragma unroll
            for (int mt = 0; mt < 2; mt++) {
                int r = wm * 32 + mt * 16 + (lane & 15);
                int cc = ks + ((lane >> 4) << 3);
                ldsm4(ah[mt], Ah + r * KP + cc);
                ldsm4(al[mt], Al + r * KP + cc);
            }
#pragma unroll
            for (int nt = 0; nt < 4; nt++) {
                int n = wn * 32 + nt * 8 + (lane & 7);
                int cc = ks + ((lane >> 3) & 1) * 8;
                ldsm2(bhf[nt], Bh + n * KP + cc);
            }
#pragma unroll
            for (int mt = 0; mt < 2; mt++)
#pragma unroll
                for (int nt = 0; nt < 4; nt++) {
                    mma16816(acc[mt][nt], ah[mt], bhf[nt]);
                    mma16816(acc[mt][nt], al[mt], bhf[nt]);
                }
        }

        if (more) {
            // convert + STS next A into nbuf, then drain cp.async
            __nv_bfloat16* dah = (__nv_bfloat16*)(sm + OFF_AH + nbuf * A_BUF) + ar * KP + ac;
            __nv_bfloat16* dal = (__nv_bfloat16*)(sm + OFF_AL + nbuf * A_BUF) + ar * KP + ac;
#pragma unroll
            for (int j = 0; j < 2; j++) {
                uint4 uh, ul;
                split8(areg[2*j], areg[2*j+1], uh, ul);
                *(uint4*)(dah + j * 8) = uh;
                *(uint4*)(dal + j * 8) = ul;
            }
            CP_WAIT0();
            __syncthreads();
        }
    }

    // ---- epilogue ----
#pragma unroll
    for (int mt = 0; mt < 2; mt++) {
        int r1 = row0 + wm * 32 + mt * 16 + (lane >> 2);
        int r2 = r1 + 8;
#pragma unroll
        for (int nt = 0; nt < 4; nt++) {
            int c = wn * 32 + nt * 8 + (lane & 3) * 2;
            float2 v1 = make_float2(acc[mt][nt][0], acc[mt][nt][1]);
            float2 v2 = make_float2(acc[mt][nt][2], acc[mt][nt][3]);
            if (EPI == 0) {
                float b0 = __ldg(bias + c), b1 = __ldg(bias + c + 1);
                v1.x = fmaxf(v1.x + b0, 0.f); v1.y = fmaxf(v1.y + b1, 0.f);
                v2.x = fmaxf(v2.x + b0, 0.f); v2.y = fmaxf(v2.y + b1, 0.f);
            }
            if (r1 < M) *(float2*)&out[(size_t)r1 * 128 + c] = v1;
            if (r2 < M) *(float2*)&out[(size_t)r2 * 128 + c] = v2;
        }
    }
}

// ================= gather aggregation: one warp per node =================
__global__ __launch_bounds__(256) void k_agg(
    const int* __restrict__ off, const int2* __restrict__ epack,
    const float* __restrict__ t, const float* __restrict__ dinv,
    const float* __restrict__ bias, float* __restrict__ out, int n)
{
    int w = (blockIdx.x * blockDim.x + threadIdx.x) >> 5;
    if (w >= n) return;
    int lane = threadIdx.x & 31;

    const float4* tp = (const float4*)t;
    int beg = __ldg(off + w);
    int end = __ldg(off + w + 1);

    float di = __ldg(dinv + w);
    float s = di * di;
    float4 acc = tp[(size_t)w * 32 + lane];
    acc.x *= s; acc.y *= s; acc.z *= s; acc.w *= s;

    int e = beg;
    for (; e + 3 < end; e += 4) {
        int2 p0 = __ldg(epack + e);
        int2 p1 = __ldg(epack + e + 1);
        int2 p2 = __ldg(epack + e + 2);
        int2 p3 = __ldg(epack + e + 3);
        float4 h0 = tp[(size_t)p0.x * 32 + lane];
        float4 h1 = tp[(size_t)p1.x * 32 + lane];
        float4 h2 = tp[(size_t)p2.x * 32 + lane];
        float4 h3 = tp[(size_t)p3.x * 32 + lane];
        float c0 = __int_as_float(p0.y), c1 = __int_as_float(p1.y);
        float c2 = __int_as_float(p2.y), c3 = __int_as_float(p3.y);
        acc.x += c0 * h0.x + c1 * h1.x + c2 * h2.x + c3 * h3.x;
        acc.y += c0 * h0.y + c1 * h1.y + c2 * h2.y + c3 * h3.y;
        acc.z += c0 * h0.z + c1 * h1.z + c2 * h2.z + c3 * h3.z;
        acc.w += c0 * h0.w + c1 * h1.w + c2 * h2.w + c3 * h3.w;
    }
    for (; e < end; e++) {
        int2 p0 = __ldg(epack + e);
        float c0 = __int_as_float(p0.y);
        float4 h0 = tp[(size_t)p0.x * 32 + lane];
        acc.x += c0 * h0.x;
        acc.y += c0 * h0.y;
        acc.z += c0 * h0.z;
        acc.w += c0 * h0.w;
    }

    float4 bv = *(const float4*)&bias[lane * 4];
    acc.x = fmaxf(acc.x + bv.x, 0.f);
    acc.y = fmaxf(acc.y + bv.y, 0.f);
    acc.z = fmaxf(acc.z + bv.z, 0.f);
    acc.w = fmaxf(acc.w + bv.w, 0.f);
    ((float4*)out)[(size_t)w * 32 + lane] = acc;
}

// ================= logits + softmax =================
__global__ __launch_bounds__(256) void k_logits_softmax(
    const float* __restrict__ h, const float* __restrict__ Wl2,
    const float* __restrict__ bl2, float* __restrict__ out, int M)
{
    __shared__ float hs[8][128];
    int tid = threadIdx.x;
    int warp = tid >> 5;
    int lane = tid & 31;
    int row0 = blockIdx.x * 8;

    {
        int rloc = tid >> 5;
        int cloc = (tid & 31) * 4;
        int r = row0 + rloc;
        float4 v = make_float4(0.f, 0.f, 0.f, 0.f);
        if (r < M) v = *(const float4*)&h[(size_t)r * 128 + cloc];
        *(float4*)&hs[rloc][cloc] = v;
    }
    __syncthreads();

    int r = row0 + warp;
    if (r >= M) return;

    float acc = bl2[lane];
#pragma unroll
    for (int k = 0; k < 128; k++) {
        acc += hs[warp][k] * __ldg(&Wl2[(size_t)k * 32 + lane]);
    }

    float m = acc;
#pragma unroll
    for (int o = 16; o >= 1; o >>= 1) m = fmaxf(m, __shfl_xor_sync(0xFFFFFFFFu, m, o));
    float e = __expf(acc - m);
    float s = e;
#pragma unroll
    for (int o = 16; o >= 1; o >>= 1) s += __shfl_xor_sync(0xFFFFFFFFu, s, o);
    out[(size_t)r * 32 + lane] = e / s;
}

// ================= launch =================
extern "C" void kernel_launch(void* const* d_in, const int* in_sizes, int n_in,
                              void* d_out, int out_size)
{
    const float* x   = (const float*)d_in[0];
    const int*   ei  = (const int*)d_in[1];
    const float* ew  = (const float*)d_in[2];
    const float* Wp  = (const float*)d_in[3];
    const float* bp  = (const float*)d_in[4];
    const float* W1  = (const float*)d_in[5];
    const float* b1  = (const float*)d_in[6];
    const float* W2  = (const float*)d_in[7];
    const float* b2  = (const float*)d_in[8];
    const float* Wl1 = (const float*)d_in[9];
    const float* bl1 = (const float*)d_in[10];
    const float* Wl2 = (const float*)d_in[11];
    const float* bl2 = (const float*)d_in[12];
    float* out = (float*)d_out;

    const int M = in_sizes[0] / 256;   // 100000
    const int E = in_sizes[1] / 2;     // 1600000
    const int* src = ei;
    const int* dst = ei + E;

    float *p_h, *p_t, *p_dinv;
    unsigned long long* p_degcnt;
    int *p_cnt, *p_off, *p_cur, *p_part;
    int2 *p_epack;
    __nv_bfloat16 *p_whi;
    cudaGetSymbolAddress((void**)&p_h, g_h);
    cudaGetSymbolAddress((void**)&p_t, g_t);
    cudaGetSymbolAddress((void**)&p_degcnt, g_degcnt);
    cudaGetSymbolAddress((void**)&p_dinv, g_dinv);
    cudaGetSymbolAddress((void**)&p_cnt, g_cnt);
    cudaGetSymbolAddress((void**)&p_off, g_off);
    cudaGetSymbolAddress((void**)&p_cur, g_cur);
    cudaGetSymbolAddress((void**)&p_epack, g_epack);
    cudaGetSymbolAddress((void**)&p_part, g_part);
    cudaGetSymbolAddress((void**)&p_whi, g_whi);

    cudaFuncSetAttribute(k_gemm_mma<256, 0>, cudaFuncAttributeMaxDynamicSharedMemorySize, GEMM_SMEM);
    cudaFuncSetAttribute(k_gemm_mma<128, 1>, cudaFuncAttributeMaxDynamicSharedMemorySize, GEMM_SMEM);
    cudaFuncSetAttribute(k_gemm_mma<128, 0>, cudaFuncAttributeMaxDynamicSharedMemorySize, GEMM_SMEM);

    const int gemm_blocks = (M + 63) / 64;
    const int agg_blocks  = (M + 7) / 8;
    const int scan_blocks = (M + SCAN_CHUNK - 1) / SCAN_CHUNK;

    // weight transpose to bf16 (tiny)
    k_prep_w<<<(256 * 128 + 255) / 256, 256>>>(Wp,  256, 128, p_whi);
    k_prep_w<<<(128 * 128 + 255) / 256, 256>>>(W1,  128, 128, p_whi + 32768);
    k_prep_w<<<(128 * 128 + 255) / 256, 256>>>(W2,  128, 128, p_whi + 49152);
    k_prep_w<<<(128 * 128 + 255) / 256, 256>>>(Wl1, 128, 128, p_whi + 65536);

    // CSR build + normalization (reused by both conv layers)
    k_init<<<(M + 255) / 256, 256>>>(p_degcnt, M);
    k_edge_deg<<<(E + 255) / 256, 256>>>(dst, ew, p_degcnt, E);
    k_dinv<<<(M + 255) / 256, 256>>>(p_degcnt, p_dinv, p_cnt, M);
    k_scan1<<<scan_blocks, SCAN_CHUNK>>>(p_cnt, p_part, M);
    k_scan2<<<1, 512>>>(p_part, scan_blocks);
    k_scan3<<<scan_blocks, SCAN_CHUNK>>>(p_cnt, p_part, p_off, p_cur, M, E);
    k_scatter<<<(E + 255) / 256, 256>>>(src, dst, ew, p_dinv, p_cur, p_epack, E);

    // h0 = relu(x @ Wp + bp)
    k_gemm_mma<256, 0><<<gemm_blocks, 256, GEMM_SMEM>>>(x, p_whi, bp, p_h, M);

    // conv1: t = h0 @ W1; h = relu(aggregate(t) + b1)
    k_gemm_mma<128, 1><<<gemm_blocks, 256, GEMM_SMEM>>>(p_h, p_whi + 32768, nullptr, p_t, M);
    k_agg<<<agg_blocks, 256>>>(p_off, p_epack, p_t, p_dinv, b1, p_h, M);

    // conv2
    k_gemm_mma<128, 1><<<gemm_blocks, 256, GEMM_SMEM>>>(p_h, p_whi + 49152, nullptr, p_t, M);
    k_agg<<<agg_blocks, 256>>>(p_off, p_epack, p_t, p_dinv, b2, p_h, M);

    // h = relu(h @ Wl1 + bl1)
    k_gemm_mma<128, 0><<<gemm_blocks, 256, GEMM_SMEM>>>(p_h, p_whi + 65536, bl1, p_t, M);

    // softmax(h @ Wl2 + bl2)
    k_logits_softmax<<<(M + 7) / 8, 256>>>(p_t, Wl2, bl2, out, M);
}

// round 11
// speedup vs baseline: 1.4141x; 1.0107x over previous
#include <cuda_runtime.h>
#include <cuda_bf16.h>
#include <math.h>
#include <stdint.h>

#define NN 100000
#define EE 1600000
#define SCAN_CHUNK 256

// Scratch (no device allocation allowed)
__device__ float g_h[(size_t)NN * 128];
__device__ float g_t[(size_t)NN * 128];
__device__ unsigned long long g_degcnt[NN];   // packed: cnt<<40 | ew_sum*2^24
__device__ float g_dinv[NN];
__device__ int   g_cnt[NN];
__device__ int   g_off[NN + 1];
__device__ int   g_cur[NN];
__device__ int2  g_epack[EE];     // {src, coef-as-int}
__device__ int   g_part[512];
// transposed bf16 weights: Wp^T @0 (128x256), W1^T @32768, W2^T @49152, Wl1^T @65536
__device__ __nv_bfloat16 g_whi[81920];

// ================= mma.sync / cp.async helpers (baseline PTX, sm_80+) =================
__device__ __forceinline__ void ldsm4(uint32_t d[4], const void* p) {
    uint32_t a = (uint32_t)__cvta_generic_to_shared(p);
    asm volatile("ldmatrix.sync.aligned.m8n8.x4.shared.b16 {%0,%1,%2,%3}, [%4];"
        : "=r"(d[0]), "=r"(d[1]), "=r"(d[2]), "=r"(d[3]) : "r"(a));
}
__device__ __forceinline__ void ldsm2(uint32_t d[2], const void* p) {
    uint32_t a = (uint32_t)__cvta_generic_to_shared(p);
    asm volatile("ldmatrix.sync.aligned.m8n8.x2.shared.b16 {%0,%1}, [%2];"
        : "=r"(d[0]), "=r"(d[1]) : "r"(a));
}
__device__ __forceinline__ void mma16816(float c[4], const uint32_t a[4], const uint32_t b[2]) {
    asm volatile("mma.sync.aligned.m16n8k16.row.col.f32.bf16.bf16.f32 "
        "{%0,%1,%2,%3}, {%4,%5,%6,%7}, {%8,%9}, {%0,%1,%2,%3};"
        : "+f"(c[0]), "+f"(c[1]), "+f"(c[2]), "+f"(c[3])
        : "r"(a[0]), "r"(a[1]), "r"(a[2]), "r"(a[3]), "r"(b[0]), "r"(b[1]));
}
__device__ __forceinline__ uint32_t pack_bf16(__nv_bfloat16 a, __nv_bfloat16 b) {
    return (uint32_t)__bfloat16_as_ushort(a) | ((uint32_t)__bfloat16_as_ushort(b) << 16);
}
__device__ __forceinline__ void split8(const float4& v0, const float4& v1,
                                       uint4& uh, uint4& ul) {
    float f[8] = {v0.x, v0.y, v0.z, v0.w, v1.x, v1.y, v1.z, v1.w};
    uint32_t h[4], l[4];
#pragma unroll
    for (int j = 0; j < 4; j++) {
        __nv_bfloat16 h0 = __float2bfloat16(f[2*j]);
        __nv_bfloat16 h1 = __float2bfloat16(f[2*j+1]);
        __nv_bfloat16 l0 = __float2bfloat16(f[2*j]   - __bfloat162float(h0));
        __nv_bfloat16 l1 = __float2bfloat16(f[2*j+1] - __bfloat162float(h1));
        h[j] = pack_bf16(h0, h1);
        l[j] = pack_bf16(l0, l1);
    }
    uh = make_uint4(h[0], h[1], h[2], h[3]);
    ul = make_uint4(l[0], l[1], l[2], l[3]);
}
__device__ __forceinline__ void cp16(void* dst_smem, const void* src) {
    uint32_t d = (uint32_t)__cvta_generic_to_shared(dst_smem);
    asm volatile("cp.async.cg.shared.global [%0], [%1], 16;" :: "r"(d), "l"(src) : "memory");
}
#define CP_COMMIT() asm volatile("cp.async.commit_group;" ::: "memory")
#define CP_WAIT0()  asm volatile("cp.async.wait_group 0;" ::: "memory")

// ================= CSR build =================
__global__ void k_init(unsigned long long* degcnt, int n) {
    int i = blockIdx.x * blockDim.x + threadIdx.x;
    if (i < n) degcnt[i] = 0ull;
}
__global__ void k_edge_deg(const int* __restrict__ dst, const float* __restrict__ ew,
                           unsigned long long* degcnt, int E) {
    int e = blockIdx.x * blockDim.x + threadIdx.x;
    if (e < E) {
        unsigned long long v = (1ull << 40)
            + (unsigned long long)((double)ew[e] * 16777216.0);
        atomicAdd(&degcnt[dst[e]], v);
    }
}
__global__ void k_dinv(const unsigned long long* __restrict__ degcnt,
                       float* dinv, int* cnt, int n) {
    int i = blockIdx.x * blockDim.x + threadIdx.x;
    if (i < n) {
        unsigned long long v = degcnt[i];
        cnt[i] = (int)(v >> 40);
        float deg = 1.0f + (float)((double)(v & ((1ull << 40) - 1)) * (1.0 / 16777216.0));
        dinv[i] = rsqrtf(deg);
    }
}
__global__ __launch_bounds__(SCAN_CHUNK) void k_scan1(const int* __restrict__ cnt,
                                                      int* part, int n) {
    __shared__ int ws[8];
    int i = blockIdx.x * SCAN_CHUNK + threadIdx.x;
    int v = (i < n) ? cnt[i] : 0;
#pragma unroll
    for (int o = 16; o >= 1; o >>= 1) v += __shfl_xor_sync(0xFFFFFFFFu, v, o);
    if ((threadIdx.x & 31) == 0) ws[threadIdx.x >> 5] = v;
    __syncthreads();
    if (threadIdx.x == 0) {
        int s = 0;
#pragma unroll
        for (int w = 0; w < 8; w++) s += ws[w];
        part[blockIdx.x] = s;
    }
}
__global__ __launch_bounds__(512) void k_scan2(int* part, int nb) {
    __shared__ int s[512];
    int tid = threadIdx.x;
    int v = (tid < nb) ? part[tid] : 0;
    s[tid] = v;
    __syncthreads();
#pragma unroll
    for (int d = 1; d < 512; d <<= 1) {
        int add = (tid >= d) ? s[tid - d] : 0;
        __syncthreads();
        s[tid] += add;
        __syncthreads();
    }
    if (tid < nb) part[tid] = s[tid] - v;
}
__global__ __launch_bounds__(SCAN_CHUNK) void k_scan3(const int* __restrict__ cnt,
                                                      const int* __restrict__ part,
                                                      int* off, int* cur, int n, int E) {
    __shared__ int ws[8];
    int tid = threadIdx.x;
    int i = blockIdx.x * SCAN_CHUNK + tid;
    int lane = tid & 31;
    int warp = tid >> 5;
    int v = (i < n) ? cnt[i] : 0;
    int x = v;
#pragma unroll
    for (int o = 1; o < 32; o <<= 1) {
        int y = __shfl_up_sync(0xFFFFFFFFu, x, o);
        if (lane >= o) x += y;
    }
    if (lane == 31) ws[warp] = x;
    __syncthreads();
    if (warp == 0 && lane < 8) {
        int y = ws[lane];
        int z = y;
#pragma unroll
        for (int o = 1; o < 8; o <<= 1) {
            int u = __shfl_up_sync(0xFFu, z, o);
            if (lane >= o) z += u;
        }
        ws[lane] = z - y;
    }
    __syncthreads();
    if (i < n) {
        int excl = part[blockIdx.x] + ws[warp] + x - v;
        off[i] = excl;
        cur[i] = excl;
    }
    if (i == n - 1) off[n] = E;
}
__global__ void k_scatter(const int* __restrict__ src, const int* __restrict__ dst,
                          const float* __restrict__ ew, const float* __restrict__ dinv,
                          int* cur, int2* epack, int E) {
    int e = blockIdx.x * blockDim.x + threadIdx.x;
    if (e >= E) return;
    int s = src[e];
    int d = dst[e];
    float c = __ldg(dinv + s) * ew[e] * __ldg(dinv + d);
    int pos = atomicAdd(&cur[d], 1);
    epack[pos] = make_int2(s, __float_as_int(c));
}

// ================= all-weights transpose to bf16 (one launch) =================
__global__ void k_prep_all(const float* __restrict__ Wp, const float* __restrict__ W1,
                           const float* __restrict__ W2, const float* __restrict__ Wl1,
                           __nv_bfloat16* hi) {
    int idx = blockIdx.x * blockDim.x + threadIdx.x;
    if (idx >= 81920) return;
    const float* W; int K, base;
    if (idx < 32768)       { W = Wp;  K = 256; base = 0; }
    else if (idx < 49152)  { W = W1;  K = 128; base = 32768; }
    else if (idx < 65536)  { W = W2;  K = 128; base = 49152; }
    else                   { W = Wl1; K = 128; base = 65536; }
    int loc = idx - base;
    int n = loc / K, k = loc % K;
    hi[idx] = __float2bfloat16(W[(size_t)k * 128 + n]);
}

// ================= HMMA GEMM core macro-parts =================
// A split (hi/lo bf16, 2 MMAs), W plain bf16. BM=64 BN=128 BK=64, 256 threads,
// warp grid 2x4 (each warp 32x32), 2-stage pipeline (cp.async B, reg prefetch A).
#define KP 72
#define A_BUF (64 * KP * 2)            // 9216 bytes per A hi/lo buffer
#define B_BUF (128 * KP * 2)           // 18432 bytes per B buffer
#define OFF_AH 0
#define OFF_AL (2 * A_BUF)
#define OFF_BH (4 * A_BUF)
#define GEMM_SMEM (4 * A_BUF + 2 * B_BUF)   // 73728 bytes -> 3 CTAs/SM

// Mainloop shared by both GEMM kernels: leaves acc[2][4][4] filled.
template <int K>
__device__ __forceinline__ void gemm_mainloop(
    char* sm, const float* __restrict__ A, const __nv_bfloat16* __restrict__ Whi,
    int M, int row0, int tid, int wm, int wn, int lane, float acc[2][4][4])
{
    constexpr int CHUNKS = K / 64;
    const int ar = tid >> 2;
    const int ac = (tid & 3) * 16;
    const int gr = row0 + ar;
    const bool aok = gr < M;
    const float4* arow = (const float4*)(A + (size_t)gr * K + ac);
    const int br = tid >> 1;
    const int bc = (tid & 1) * 32;
    const __nv_bfloat16* bh_row = Whi + (size_t)br * K + bc;

    float4 areg[4];
    const float4 z4 = make_float4(0.f, 0.f, 0.f, 0.f);

    {
        __nv_bfloat16* dbh = (__nv_bfloat16*)(sm + OFF_BH) + br * KP + bc;
#pragma unroll
        for (int j = 0; j < 4; j++) cp16(dbh + j * 8, bh_row + j * 8);
        CP_COMMIT();
#pragma unroll
        for (int j = 0; j < 4; j++) areg[j] = aok ? arow[j] : z4;
        __nv_bfloat16* dah = (__nv_bfloat16*)(sm + OFF_AH) + ar * KP + ac;
        __nv_bfloat16* dal = (__nv_bfloat16*)(sm + OFF_AL) + ar * KP + ac;
#pragma unroll
        for (int j = 0; j < 2; j++) {
            uint4 uh, ul;
            split8(areg[2*j], areg[2*j+1], uh, ul);
            *(uint4*)(dah + j * 8) = uh;
            *(uint4*)(dal + j * 8) = ul;
        }
        CP_WAIT0();
    }
    __syncthreads();

#pragma unroll
    for (int c = 0; c < CHUNKS; c++) {
        const int buf = c & 1;
        const int nbuf = buf ^ 1;
        const bool more = (c + 1) < CHUNKS;

        if (more) {
            int kn = (c + 1) * 64;
            __nv_bfloat16* dbh = (__nv_bfloat16*)(sm + OFF_BH + nbuf * B_BUF) + br * KP + bc;
#pragma unroll
            for (int j = 0; j < 4; j++) cp16(dbh + j * 8, bh_row + kn + j * 8);
            CP_COMMIT();
#pragma unroll
            for (int j = 0; j < 4; j++) areg[j] = aok ? arow[kn / 4 + j] : z4;
        }

        const __nv_bfloat16* Ah = (const __nv_bfloat16*)(sm + OFF_AH + buf * A_BUF);
        const __nv_bfloat16* Al = (const __nv_bfloat16*)(sm + OFF_AL + buf * A_BUF);
        const __nv_bfloat16* Bh = (const __nv_bfloat16*)(sm + OFF_BH + buf * B_BUF);
#pragma unroll
        for (int ks = 0; ks < 64; ks += 16) {
            uint32_t ah[2][4], al[2][4], bhf[4][2];
#pragma unroll
            for (int mt = 0; mt < 2; mt++) {
                int r = wm * 32 + mt * 16 + (lane & 15);
                int cc = ks + ((lane >> 4) << 3);
                ldsm4(ah[mt], Ah + r * KP + cc);
                ldsm4(al[mt], Al + r * KP + cc);
            }
#pragma unroll
            for (int nt = 0; nt < 4; nt++) {
                int n = wn * 32 + nt * 8 + (lane & 7);
                int cc = ks + ((lane >> 3) & 1) * 8;
                ldsm2(bhf[nt], Bh + n * KP + cc);
            }
#pragma unroll
            for (int mt = 0; mt < 2; mt++)
#pragma unroll
                for (int nt = 0; nt < 4; nt++) {
                    mma16816(acc[mt][nt], ah[mt], bhf[nt]);
                    mma16816(acc[mt][nt], al[mt], bhf[nt]);
                }
        }

        if (more) {
            __nv_bfloat16* dah = (__nv_bfloat16*)(sm + OFF_AH + nbuf * A_BUF) + ar * KP + ac;
            __nv_bfloat16* dal = (__nv_bfloat16*)(sm + OFF_AL + nbuf * A_BUF) + ar * KP + ac;
#pragma unroll
            for (int j = 0; j < 2; j++) {
                uint4 uh, ul;
                split8(areg[2*j], areg[2*j+1], uh, ul);
                *(uint4*)(dah + j * 8) = uh;
                *(uint4*)(dal + j * 8) = ul;
            }
            CP_WAIT0();
            __syncthreads();
        }
    }
}

// Standard GEMM: EPI==0: out = relu(acc + bias);  EPI==1: out = acc
template <int K, int EPI>
__global__ __launch_bounds__(256) void k_gemm_mma(
    const float* __restrict__ A, const __nv_bfloat16* __restrict__ Whi,
    const float* __restrict__ bias, float* __restrict__ out, int M)
{
    extern __shared__ char sm[];
    const int tid  = threadIdx.x;
    const int wid  = tid >> 5;
    const int lane = tid & 31;
    const int wm   = wid & 1;
    const int wn   = wid >> 1;
    const int row0 = blockIdx.x * 64;

    float acc[2][4][4];
#pragma unroll
    for (int mt = 0; mt < 2; mt++)
#pragma unroll
        for (int nt = 0; nt < 4; nt++)
#pragma unroll
            for (int j = 0; j < 4; j++) acc[mt][nt][j] = 0.0f;

    gemm_mainloop<K>(sm, A, Whi, M, row0, tid, wm, wn, lane, acc);

#pragma unroll
    for (int mt = 0; mt < 2; mt++) {
        int r1 = row0 + wm * 32 + mt * 16 + (lane >> 2);
        int r2 = r1 + 8;
#pragma unroll
        for (int nt = 0; nt < 4; nt++) {
            int c = wn * 32 + nt * 8 + (lane & 3) * 2;
            float2 v1 = make_float2(acc[mt][nt][0], acc[mt][nt][1]);
            float2 v2 = make_float2(acc[mt][nt][2], acc[mt][nt][3]);
            if (EPI == 0) {
                float b0 = __ldg(bias + c), b1 = __ldg(bias + c + 1);
                v1.x = fmaxf(v1.x + b0, 0.f); v1.y = fmaxf(v1.y + b1, 0.f);
                v2.x = fmaxf(v2.x + b0, 0.f); v2.y = fmaxf(v2.y + b1, 0.f);
            }
            if (r1 < M) *(float2*)&out[(size_t)r1 * 128 + c] = v1;
            if (r2 < M) *(float2*)&out[(size_t)r2 * 128 + c] = v2;
        }
    }
}

// Fused final: hmid = relu(h@Wl1+bl1) in smem; logits = hmid@Wl2+bl2; softmax -> out.
__global__ __launch_bounds__(256) void k_gemm_last(
    const float* __restrict__ A, const __nv_bfloat16* __restrict__ Whi,
    const float* __restrict__ bl1, const float* __restrict__ Wl2,
    const float* __restrict__ bl2, float* __restrict__ out, int M)
{
    extern __shared__ char sm[];
    const int tid  = threadIdx.x;
    const int wid  = tid >> 5;
    const int lane = tid & 31;
    const int wm   = wid & 1;
    const int wn   = wid >> 1;
    const int row0 = blockIdx.x * 64;

    float acc[2][4][4];
#pragma unroll
    for (int mt = 0; mt < 2; mt++)
#pragma unroll
        for (int nt = 0; nt < 4; nt++)
#pragma unroll
            for (int j = 0; j < 4; j++) acc[mt][nt][j] = 0.0f;

    gemm_mainloop<128>(sm, A, Whi, M, row0, tid, wm, wn, lane, acc);

    __syncthreads();   // everyone done reading smem buffers
    float* hs  = (float*)sm;             // 64 x 128 fp32 = 32768 B
    float* w2s = (float*)(sm + 32768);   // 128 x 32 fp32 = 16384 B

    // store relu(acc + bl1) tile to smem
#pragma unroll
    for (int mt = 0; mt < 2; mt++) {
        int lr1 = wm * 32 + mt * 16 + (lane >> 2);
        int lr2 = lr1 + 8;
#pragma unroll
        for (int nt = 0; nt < 4; nt++) {
            int c = wn * 32 + nt * 8 + (lane & 3) * 2;
            float b0 = __ldg(bl1 + c), b1 = __ldg(bl1 + c + 1);
            float2 v1 = make_float2(fmaxf(acc[mt][nt][0] + b0, 0.f),
                                    fmaxf(acc[mt][nt][1] + b1, 0.f));
            float2 v2 = make_float2(fmaxf(acc[mt][nt][2] + b0, 0.f),
                                    fmaxf(acc[mt][nt][3] + b1, 0.f));
            *(float2*)&hs[lr1 * 128 + c] = v1;
            *(float2*)&hs[lr2 * 128 + c] = v2;
        }
    }
    // stage Wl2 [128][32]
    for (int i = tid; i < 4096; i += 256) w2s[i] = __ldg(Wl2 + i);
    __syncthreads();

    // each warp: 8 rows of logits + softmax
    float bb = __ldg(bl2 + lane);
#pragma unroll 1
    for (int i = 0; i < 8; i++) {
        int r = row0 + wid * 8 + i;
        if (r >= M) break;
        const float* hr = hs + (wid * 8 + i) * 128;
        float a = bb;
#pragma unroll
        for (int k = 0; k < 128; k += 4) {
            float4 h4 = *(const float4*)(hr + k);
            a += h4.x * w2s[(k + 0) * 32 + lane];
            a += h4.y * w2s[(k + 1) * 32 + lane];
            a += h4.z * w2s[(k + 2) * 32 + lane];
            a += h4.w * w2s[(k + 3) * 32 + lane];
        }
        float m = a;
#pragma unroll
        for (int o = 16; o >= 1; o >>= 1) m = fmaxf(m, __shfl_xor_sync(0xFFFFFFFFu, m, o));
        float e = __expf(a - m);
        float s = e;
#pragma unroll
        for (int o = 16; o >= 1; o >>= 1) s += __shfl_xor_sync(0xFFFFFFFFu, s, o);
        out[(size_t)r * 32 + lane] = e / s;
    }
}

// ================= gather aggregation: one warp per node =================
__global__ __launch_bounds__(256) void k_agg(
    const int* __restrict__ off, const int2* __restrict__ epack,
    const float* __restrict__ t, const float* __restrict__ dinv,
    const float* __restrict__ bias, float* __restrict__ out, int n)
{
    int w = (blockIdx.x * blockDim.x + threadIdx.x) >> 5;
    if (w >= n) return;
    int lane = threadIdx.x & 31;

    const float4* tp = (const float4*)t;
    int beg = __ldg(off + w);
    int end = __ldg(off + w + 1);

    float di = __ldg(dinv + w);
    float s = di * di;
    float4 acc = tp[(size_t)w * 32 + lane];
    acc.x *= s; acc.y *= s; acc.z *= s; acc.w *= s;

    int e = beg;
    for (; e + 3 < end; e += 4) {
        int2 p0 = __ldg(epack + e);
        int2 p1 = __ldg(epack + e + 1);
        int2 p2 = __ldg(epack + e + 2);
        int2 p3 = __ldg(epack + e + 3);
        float4 h0 = tp[(size_t)p0.x * 32 + lane];
        float4 h1 = tp[(size_t)p1.x * 32 + lane];
        float4 h2 = tp[(size_t)p2.x * 32 + lane];
        float4 h3 = tp[(size_t)p3.x * 32 + lane];
        float c0 = __int_as_float(p0.y), c1 = __int_as_float(p1.y);
        float c2 = __int_as_float(p2.y), c3 = __int_as_float(p3.y);
        acc.x += c0 * h0.x + c1 * h1.x + c2 * h2.x + c3 * h3.x;
        acc.y += c0 * h0.y + c1 * h1.y + c2 * h2.y + c3 * h3.y;
        acc.z += c0 * h0.z + c1 * h1.z + c2 * h2.z + c3 * h3.z;
        acc.w += c0 * h0.w + c1 * h1.w + c2 * h2.w + c3 * h3.w;
    }
    for (; e < end; e++) {
        int2 p0 = __ldg(epack + e);
        float c0 = __int_as_float(p0.y);
        float4 h0 = tp[(size_t)p0.x * 32 + lane];
        acc.x += c0 * h0.x;
        acc.y += c0 * h0.y;
        acc.z += c0 * h0.z;
        acc.w += c0 * h0.w;
    }

    float4 bv = *(const float4*)&bias[lane * 4];
    acc.x = fmaxf(acc.x + bv.x, 0.f);
    acc.y = fmaxf(acc.y + bv.y, 0.f);
    acc.z = fmaxf(acc.z + bv.z, 0.f);
    acc.w = fmaxf(acc.w + bv.w, 0.f);
    ((float4*)out)[(size_t)w * 32 + lane] = acc;
}

// ================= launch =================
extern "C" void kernel_launch(void* const* d_in, const int* in_sizes, int n_in,
                              void* d_out, int out_size)
{
    const float* x   = (const float*)d_in[0];
    const int*   ei  = (const int*)d_in[1];
    const float* ew  = (const float*)d_in[2];
    const float* Wp  = (const float*)d_in[3];
    const float* bp  = (const float*)d_in[4];
    const float* W1  = (const float*)d_in[5];
    const float* b1  = (const float*)d_in[6];
    const float* W2  = (const float*)d_in[7];
    const float* b2  = (const float*)d_in[8];
    const float* Wl1 = (const float*)d_in[9];
    const float* bl1 = (const float*)d_in[10];
    const float* Wl2 = (const float*)d_in[11];
    const float* bl2 = (const float*)d_in[12];
    float* out = (float*)d_out;

    const int M = in_sizes[0] / 256;   // 100000
    const int E = in_sizes[1] / 2;     // 1600000
    const int* src = ei;
    const int* dst = ei + E;

    float *p_h, *p_t, *p_dinv;
    unsigned long long* p_degcnt;
    int *p_cnt, *p_off, *p_cur, *p_part;
    int2 *p_epack;
    __nv_bfloat16 *p_whi;
    cudaGetSymbolAddress((void**)&p_h, g_h);
    cudaGetSymbolAddress((void**)&p_t, g_t);
    cudaGetSymbolAddress((void**)&p_degcnt, g_degcnt);
    cudaGetSymbolAddress((void**)&p_dinv, g_dinv);
    cudaGetSymbolAddress((void**)&p_cnt, g_cnt);
    cudaGetSymbolAddress((void**)&p_off, g_off);
    cudaGetSymbolAddress((void**)&p_cur, g_cur);
    cudaGetSymbolAddress((void**)&p_epack, g_epack);
    cudaGetSymbolAddress((void**)&p_part, g_part);
    cudaGetSymbolAddress((void**)&p_whi, g_whi);

    cudaFuncSetAttribute(k_gemm_mma<256, 0>, cudaFuncAttributeMaxDynamicSharedMemorySize, GEMM_SMEM);
    cudaFuncSetAttribute(k_gemm_mma<128, 1>, cudaFuncAttributeMaxDynamicSharedMemorySize, GEMM_SMEM);
    cudaFuncSetAttribute(k_gemm_last, cudaFuncAttributeMaxDynamicSharedMemorySize, GEMM_SMEM);

    const int gemm_blocks = (M + 63) / 64;
    const int agg_blocks  = (M + 7) / 8;
    const int scan_blocks = (M + SCAN_CHUNK - 1) / SCAN_CHUNK;

    // weight transpose to bf16 — single launch
    k_prep_all<<<(81920 + 255) / 256, 256>>>(Wp, W1, W2, Wl1, p_whi);

    // CSR build + normalization (reused by both conv layers)
    k_init<<<(M + 255) / 256, 256>>>(p_degcnt, M);
    k_edge_deg<<<(E + 255) / 256, 256>>>(dst, ew, p_degcnt, E);
    k_dinv<<<(M + 255) / 256, 256>>>(p_degcnt, p_dinv, p_cnt, M);
    k_scan1<<<scan_blocks, SCAN_CHUNK>>>(p_cnt, p_part, M);
    k_scan2<<<1, 512>>>(p_part, scan_blocks);
    k_scan3<<<scan_blocks, SCAN_CHUNK>>>(p_cnt, p_part, p_off, p_cur, M, E);
    k_scatter<<<(E + 255) / 256, 256>>>(src, dst, ew, p_dinv, p_cur, p_epack, E);

    // h0 = relu(x @ Wp + bp)
    k_gemm_mma<256, 0><<<gemm_blocks, 256, GEMM_SMEM>>>(x, p_whi, bp, p_h, M);

    // conv1: t = h0 @ W1; h = relu(aggregate(t) + b1)
    k_gemm_mma<128, 1><<<gemm_blocks, 256, GEMM_SMEM>>>(p_h, p_whi + 32768, nullptr, p_t, M);
    k_agg<<<agg_blocks, 256>>>(p_off, p_epack, p_t, p_dinv, b1, p_h, M);

    // conv2
    k_gemm_mma<128, 1><<<gemm_blocks, 256, GEMM_SMEM>>>(p_h, p_whi + 49152, nullptr, p_t, M);
    k_agg<<<agg_blocks, 256>>>(p_off, p_epack, p_t, p_dinv, b2, p_h, M);

    // fused: softmax(relu(h @ Wl1 + bl1) @ Wl2 + bl2)
    k_gemm_last<<<gemm_blocks, 256, GEMM_SMEM>>>(p_h, p_whi + 65536, bl1, Wl2, bl2, out, M);
}

// round 12
// speedup vs baseline: 1.4979x; 1.0592x over previous
#include <cuda_runtime.h>
#include <cuda_bf16.h>
#include <math.h>
#include <stdint.h>

#define NN 100000
#define EE 1600000
#define SCAN_CHUNK 256

// Scratch (no device allocation allowed)
__device__ float g_h[(size_t)NN * 128];
__device__ __nv_bfloat16 g_t[(size_t)NN * 128];   // conv GEMM output, bf16
__device__ unsigned long long g_degcnt[NN];
__device__ float g_dinv[NN];
__device__ int   g_cnt[NN];
__device__ int   g_off[NN + 1];
__device__ int   g_cur[NN];
__device__ int2  g_epack[EE];     // {src, coef-as-int}
__device__ int   g_part[512];
// transposed bf16 weights: Wp^T @0 (128x256), W1^T @32768, W2^T @49152, Wl1^T @65536
__device__ __nv_bfloat16 g_whi[81920];

// ================= mma.sync / cp.async helpers (baseline PTX, sm_80+) =================
__device__ __forceinline__ void ldsm4(uint32_t d[4], const void* p) {
    uint32_t a = (uint32_t)__cvta_generic_to_shared(p);
    asm volatile("ldmatrix.sync.aligned.m8n8.x4.shared.b16 {%0,%1,%2,%3}, [%4];"
        : "=r"(d[0]), "=r"(d[1]), "=r"(d[2]), "=r"(d[3]) : "r"(a));
}
__device__ __forceinline__ void ldsm2(uint32_t d[2], const void* p) {
    uint32_t a = (uint32_t)__cvta_generic_to_shared(p);
    asm volatile("ldmatrix.sync.aligned.m8n8.x2.shared.b16 {%0,%1}, [%2];"
        : "=r"(d[0]), "=r"(d[1]) : "r"(a));
}
__device__ __forceinline__ void mma16816(float c[4], const uint32_t a[4], const uint32_t b[2]) {
    asm volatile("mma.sync.aligned.m16n8k16.row.col.f32.bf16.bf16.f32 "
        "{%0,%1,%2,%3}, {%4,%5,%6,%7}, {%8,%9}, {%0,%1,%2,%3};"
        : "+f"(c[0]), "+f"(c[1]), "+f"(c[2]), "+f"(c[3])
        : "r"(a[0]), "r"(a[1]), "r"(a[2]), "r"(a[3]), "r"(b[0]), "r"(b[1]));
}
__device__ __forceinline__ uint32_t pack_bf16(__nv_bfloat16 a, __nv_bfloat16 b) {
    return (uint32_t)__bfloat16_as_ushort(a) | ((uint32_t)__bfloat16_as_ushort(b) << 16);
}
__device__ __forceinline__ void split8(const float4& v0, const float4& v1,
                                       uint4& uh, uint4& ul) {
    float f[8] = {v0.x, v0.y, v0.z, v0.w, v1.x, v1.y, v1.z, v1.w};
    uint32_t h[4], l[4];
#pragma unroll
    for (int j = 0; j < 4; j++) {
        __nv_bfloat16 h0 = __float2bfloat16(f[2*j]);
        __nv_bfloat16 h1 = __float2bfloat16(f[2*j+1]);
        __nv_bfloat16 l0 = __float2bfloat16(f[2*j]   - __bfloat162float(h0));
        __nv_bfloat16 l1 = __float2bfloat16(f[2*j+1] - __bfloat162float(h1));
        h[j] = pack_bf16(h0, h1);
        l[j] = pack_bf16(l0, l1);
    }
    uh = make_uint4(h[0], h[1], h[2], h[3]);
    ul = make_uint4(l[0], l[1], l[2], l[3]);
}
__device__ __forceinline__ void cp16(void* dst_smem, const void* src) {
    uint32_t d = (uint32_t)__cvta_generic_to_shared(dst_smem);
    asm volatile("cp.async.cg.shared.global [%0], [%1], 16;" :: "r"(d), "l"(src) : "memory");
}
#define CP_COMMIT() asm volatile("cp.async.commit_group;" ::: "memory")
#define CP_WAIT0()  asm volatile("cp.async.wait_group 0;" ::: "memory")

// ================= CSR build =================
__global__ void k_edge_deg(const int* __restrict__ dst, const float* __restrict__ ew,
                           unsigned long long* degcnt, int E) {
    int e = blockIdx.x * blockDim.x + threadIdx.x;
    if (e < E) {
        unsigned long long v = (1ull << 40)
            + (unsigned long long)((double)ew[e] * 16777216.0);
        atomicAdd(&degcnt[dst[e]], v);
    }
}
__global__ void k_dinv(const unsigned long long* __restrict__ degcnt,
                       float* dinv, int* cnt, int n) {
    int i = blockIdx.x * blockDim.x + threadIdx.x;
    if (i < n) {
        unsigned long long v = degcnt[i];
        cnt[i] = (int)(v >> 40);
        float deg = 1.0f + (float)((double)(v & ((1ull << 40) - 1)) * (1.0 / 16777216.0));
        dinv[i] = rsqrtf(deg);
    }
}
__global__ __launch_bounds__(SCAN_CHUNK) void k_scan1(const int* __restrict__ cnt,
                                                      int* part, int n) {
    __shared__ int ws[8];
    int i = blockIdx.x * SCAN_CHUNK + threadIdx.x;
    int v = (i < n) ? cnt[i] : 0;
#pragma unroll
    for (int o = 16; o >= 1; o >>= 1) v += __shfl_xor_sync(0xFFFFFFFFu, v, o);
    if ((threadIdx.x & 31) == 0) ws[threadIdx.x >> 5] = v;
    __syncthreads();
    if (threadIdx.x == 0) {
        int s = 0;
#pragma unroll
        for (int w = 0; w < 8; w++) s += ws[w];
        part[blockIdx.x] = s;
    }
}
__global__ __launch_bounds__(512) void k_scan2(int* part, int nb) {
    __shared__ int s[512];
    int tid = threadIdx.x;
    int v = (tid < nb) ? part[tid] : 0;
    s[tid] = v;
    __syncthreads();
#pragma unroll
    for (int d = 1; d < 512; d <<= 1) {
        int add = (tid >= d) ? s[tid - d] : 0;
        __syncthreads();
        s[tid] += add;
        __syncthreads();
    }
    if (tid < nb) part[tid] = s[tid] - v;
}
__global__ __launch_bounds__(SCAN_CHUNK) void k_scan3(const int* __restrict__ cnt,
                                                      const int* __restrict__ part,
                                                      int* off, int* cur, int n, int E) {
    __shared__ int ws[8];
    int tid = threadIdx.x;
    int i = blockIdx.x * SCAN_CHUNK + tid;
    int lane = tid & 31;
    int warp = tid >> 5;
    int v = (i < n) ? cnt[i] : 0;
    int x = v;
#pragma unroll
    for (int o = 1; o < 32; o <<= 1) {
        int y = __shfl_up_sync(0xFFFFFFFFu, x, o);
        if (lane >= o) x += y;
    }
    if (lane == 31) ws[warp] = x;
    __syncthreads();
    if (warp == 0 && lane < 8) {
        int y = ws[lane];
        int z = y;
#pragma unroll
        for (int o = 1; o < 8; o <<= 1) {
            int u = __shfl_up_sync(0xFFu, z, o);
            if (lane >= o) z += u;
        }
        ws[lane] = z - y;
    }
    __syncthreads();
    if (i < n) {
        int excl = part[blockIdx.x] + ws[warp] + x - v;
        off[i] = excl;
        cur[i] = excl;
    }
    if (i == n - 1) off[n] = E;
}
__global__ void k_scatter(const int* __restrict__ src, const int* __restrict__ dst,
                          const float* __restrict__ ew, const float* __restrict__ dinv,
                          int* cur, int2* epack, int E) {
    int e = blockIdx.x * blockDim.x + threadIdx.x;
    if (e >= E) return;
    int s = src[e];
    int d = dst[e];
    float c = __ldg(dinv + s) * ew[e] * __ldg(dinv + d);
    int pos = atomicAdd(&cur[d], 1);
    epack[pos] = make_int2(s, __float_as_int(c));
}

// ================= all-weights transpose to bf16 (one launch) =================
__global__ void k_prep_all(const float* __restrict__ Wp, const float* __restrict__ W1,
                           const float* __restrict__ W2, const float* __restrict__ Wl1,
                           __nv_bfloat16* hi) {
    int idx = blockIdx.x * blockDim.x + threadIdx.x;
    if (idx >= 81920) return;
    const float* W; int K, base;
    if (idx < 32768)       { W = Wp;  K = 256; base = 0; }
    else if (idx < 49152)  { W = W1;  K = 128; base = 32768; }
    else if (idx < 65536)  { W = W2;  K = 128; base = 49152; }
    else                   { W = Wl1; K = 128; base = 65536; }
    int loc = idx - base;
    int n = loc / K, k = loc % K;
    hi[idx] = __float2bfloat16(W[(size_t)k * 128 + n]);
}

// ================= HMMA GEMM core =================
#define KP 72
#define A_BUF (64 * KP * 2)
#define B_BUF (128 * KP * 2)
#define OFF_AH 0
#define OFF_AL (2 * A_BUF)
#define OFF_BH (4 * A_BUF)
#define GEMM_SMEM (4 * A_BUF + 2 * B_BUF)   // 73728 bytes -> 3 CTAs/SM

template <int K>
__device__ __forceinline__ void gemm_mainloop(
    char* sm, const float* __restrict__ A, const __nv_bfloat16* __restrict__ Whi,
    int M, int row0, int tid, int wm, int wn, int lane, float acc[2][4][4])
{
    constexpr int CHUNKS = K / 64;
    const int ar = tid >> 2;
    const int ac = (tid & 3) * 16;
    const int gr = row0 + ar;
    const bool aok = gr < M;
    const float4* arow = (const float4*)(A + (size_t)gr * K + ac);
    const int br = tid >> 1;
    const int bc = (tid & 1) * 32;
    const __nv_bfloat16* bh_row = Whi + (size_t)br * K + bc;

    float4 areg[4];
    const float4 z4 = make_float4(0.f, 0.f, 0.f, 0.f);

    {
        __nv_bfloat16* dbh = (__nv_bfloat16*)(sm + OFF_BH) + br * KP + bc;
#pragma unroll
        for (int j = 0; j < 4; j++) cp16(dbh + j * 8, bh_row + j * 8);
        CP_COMMIT();
#pragma unroll
        for (int j = 0; j < 4; j++) areg[j] = aok ? arow[j] : z4;
        __nv_bfloat16* dah = (__nv_bfloat16*)(sm + OFF_AH) + ar * KP + ac;
        __nv_bfloat16* dal = (__nv_bfloat16*)(sm + OFF_AL) + ar * KP + ac;
#pragma unroll
        for (int j = 0; j < 2; j++) {
            uint4 uh, ul;
            split8(areg[2*j], areg[2*j+1], uh, ul);
            *(uint4*)(dah + j * 8) = uh;
            *(uint4*)(dal + j * 8) = ul;
        }
        CP_WAIT0();
    }
    __syncthreads();

#pragma unroll
    for (int c = 0; c < CHUNKS; c++) {
        const int buf = c & 1;
        const int nbuf = buf ^ 1;
        const bool more = (c + 1) < CHUNKS;

        if (more) {
            int kn = (c + 1) * 64;
            __nv_bfloat16* dbh = (__nv_bfloat16*)(sm + OFF_BH + nbuf * B_BUF) + br * KP + bc;
#pragma unroll
            for (int j = 0; j < 4; j++) cp16(dbh + j * 8, bh_row + kn + j * 8);
            CP_COMMIT();
#pragma unroll
            for (int j = 0; j < 4; j++) areg[j] = aok ? arow[kn / 4 + j] : z4;
        }

        const __nv_bfloat16* Ah = (const __nv_bfloat16*)(sm + OFF_AH + buf * A_BUF);
        const __nv_bfloat16* Al = (const __nv_bfloat16*)(sm + OFF_AL + buf * A_BUF);
        const __nv_bfloat16* Bh = (const __nv_bfloat16*)(sm + OFF_BH + buf * B_BUF);
#pragma unroll
        for (int ks = 0; ks < 64; ks += 16) {
            uint32_t ah[2][4], al[2][4], bhf[4][2];
#pragma unroll
            for (int mt = 0; mt < 2; mt++) {
                int r = wm * 32 + mt * 16 + (lane & 15);
                int cc = ks + ((lane >> 4) << 3);
                ldsm4(ah[mt], Ah + r * KP + cc);
                ldsm4(al[mt], Al + r * KP + cc);
            }
#pragma unroll
            for (int nt = 0; nt < 4; nt++) {
                int n = wn * 32 + nt * 8 + (lane & 7);
                int cc = ks + ((lane >> 3) & 1) * 8;
                ldsm2(bhf[nt], Bh + n * KP + cc);
            }
#pragma unroll
            for (int mt = 0; mt < 2; mt++)
#pragma unroll
                for (int nt = 0; nt < 4; nt++) {
                    mma16816(acc[mt][nt], ah[mt], bhf[nt]);
                    mma16816(acc[mt][nt], al[mt], bhf[nt]);
                }
        }

        if (more) {
            __nv_bfloat16* dah = (__nv_bfloat16*)(sm + OFF_AH + nbuf * A_BUF) + ar * KP + ac;
            __nv_bfloat16* dal = (__nv_bfloat16*)(sm + OFF_AL + nbuf * A_BUF) + ar * KP + ac;
#pragma unroll
            for (int j = 0; j < 2; j++) {
                uint4 uh, ul;
                split8(areg[2*j], areg[2*j+1], uh, ul);
                *(uint4*)(dah + j * 8) = uh;
                *(uint4*)(dal + j * 8) = ul;
            }
            CP_WAIT0();
            __syncthreads();
        }
    }
}

// Standard GEMM. EPI==0: fp32 out = relu(acc+bias). EPI==1: bf16 out = acc.
template <int K, int EPI>
__global__ __launch_bounds__(256) void k_gemm_mma(
    const float* __restrict__ A, const __nv_bfloat16* __restrict__ Whi,
    const float* __restrict__ bias, void* __restrict__ outv, int M)
{
    extern __shared__ char sm[];
    const int tid  = threadIdx.x;
    const int wid  = tid >> 5;
    const int lane = tid & 31;
    const int wm   = wid & 1;
    const int wn   = wid >> 1;
    const int row0 = blockIdx.x * 64;

    float acc[2][4][4];
#pragma unroll
    for (int mt = 0; mt < 2; mt++)
#pragma unroll
        for (int nt = 0; nt < 4; nt++)
#pragma unroll
            for (int j = 0; j < 4; j++) acc[mt][nt][j] = 0.0f;

    gemm_mainloop<K>(sm, A, Whi, M, row0, tid, wm, wn, lane, acc);

#pragma unroll
    for (int mt = 0; mt < 2; mt++) {
        int r1 = row0 + wm * 32 + mt * 16 + (lane >> 2);
        int r2 = r1 + 8;
#pragma unroll
        for (int nt = 0; nt < 4; nt++) {
            int c = wn * 32 + nt * 8 + (lane & 3) * 2;
            if (EPI == 0) {
                float* out = (float*)outv;
                float b0 = __ldg(bias + c), b1 = __ldg(bias + c + 1);
                float2 v1 = make_float2(fmaxf(acc[mt][nt][0] + b0, 0.f),
                                        fmaxf(acc[mt][nt][1] + b1, 0.f));
                float2 v2 = make_float2(fmaxf(acc[mt][nt][2] + b0, 0.f),
                                        fmaxf(acc[mt][nt][3] + b1, 0.f));
                if (r1 < M) *(float2*)&out[(size_t)r1 * 128 + c] = v1;
                if (r2 < M) *(float2*)&out[(size_t)r2 * 128 + c] = v2;
            } else {
                __nv_bfloat16* out = (__nv_bfloat16*)outv;
                uint32_t p1 = pack_bf16(__float2bfloat16(acc[mt][nt][0]),
                                        __float2bfloat16(acc[mt][nt][1]));
                uint32_t p2 = pack_bf16(__float2bfloat16(acc[mt][nt][2]),
                                        __float2bfloat16(acc[mt][nt][3]));
                if (r1 < M) *(uint32_t*)&out[(size_t)r1 * 128 + c] = p1;
                if (r2 < M) *(uint32_t*)&out[(size_t)r2 * 128 + c] = p2;
            }
        }
    }
}

// Fused final: hmid = relu(h@Wl1+bl1) in smem; logits = hmid@Wl2+bl2; softmax -> out.
__global__ __launch_bounds__(256) void k_gemm_last(
    const float* __restrict__ A, const __nv_bfloat16* __restrict__ Whi,
    const float* __restrict__ bl1, const float* __restrict__ Wl2,
    const float* __restrict__ bl2, float* __restrict__ out, int M)
{
    extern __shared__ char sm[];
    const int tid  = threadIdx.x;
    const int wid  = tid >> 5;
    const int lane = tid & 31;
    const int wm   = wid & 1;
    const int wn   = wid >> 1;
    const int row0 = blockIdx.x * 64;

    float acc[2][4][4];
#pragma unroll
    for (int mt = 0; mt < 2; mt++)
#pragma unroll
        for (int nt = 0; nt < 4; nt++)
#pragma unroll
            for (int j = 0; j < 4; j++) acc[mt][nt][j] = 0.0f;

    gemm_mainloop<128>(sm, A, Whi, M, row0, tid, wm, wn, lane, acc);

    __syncthreads();
    float* hs  = (float*)sm;             // 64 x 128 fp32
    float* w2s = (float*)(sm + 32768);   // 128 x 32 fp32

#pragma unroll
    for (int mt = 0; mt < 2; mt++) {
        int lr1 = wm * 32 + mt * 16 + (lane >> 2);
        int lr2 = lr1 + 8;
#pragma unroll
        for (int nt = 0; nt < 4; nt++) {
            int c = wn * 32 + nt * 8 + (lane & 3) * 2;
            float b0 = __ldg(bl1 + c), b1 = __ldg(bl1 + c + 1);
            float2 v1 = make_float2(fmaxf(acc[mt][nt][0] + b0, 0.f),
                                    fmaxf(acc[mt][nt][1] + b1, 0.f));
            float2 v2 = make_float2(fmaxf(acc[mt][nt][2] + b0, 0.f),
                                    fmaxf(acc[mt][nt][3] + b1, 0.f));
            *(float2*)&hs[lr1 * 128 + c] = v1;
            *(float2*)&hs[lr2 * 128 + c] = v2;
        }
    }
    for (int i = tid; i < 4096; i += 256) w2s[i] = __ldg(Wl2 + i);
    __syncthreads();

    float bb = __ldg(bl2 + lane);
#pragma unroll 1
    for (int i = 0; i < 8; i++) {
        int r = row0 + wid * 8 + i;
        if (r >= M) break;
        const float* hr = hs + (wid * 8 + i) * 128;
        float a = bb;
#pragma unroll
        for (int k = 0; k < 128; k += 4) {
            float4 h4 = *(const float4*)(hr + k);
            a += h4.x * w2s[(k + 0) * 32 + lane];
            a += h4.y * w2s[(k + 1) * 32 + lane];
            a += h4.z * w2s[(k + 2) * 32 + lane];
            a += h4.w * w2s[(k + 3) * 32 + lane];
        }
        float m = a;
#pragma unroll
        for (int o = 16; o >= 1; o >>= 1) m = fmaxf(m, __shfl_xor_sync(0xFFFFFFFFu, m, o));
        float e = __expf(a - m);
        float s = e;
#pragma unroll
        for (int o = 16; o >= 1; o >>= 1) s += __shfl_xor_sync(0xFFFFFFFFu, s, o);
        out[(size_t)r * 32 + lane] = e / s;
    }
}

// ================= gather aggregation (bf16 t): one warp per node =================
__global__ __launch_bounds__(256) void k_agg(
    const int* __restrict__ off, const int2* __restrict__ epack,
    const __nv_bfloat16* __restrict__ t, const float* __restrict__ dinv,
    const float* __restrict__ bias, float* __restrict__ out, int n)
{
    int w = (blockIdx.x * blockDim.x + threadIdx.x) >> 5;
    if (w >= n) return;
    int lane = threadIdx.x & 31;

    const uint2* tp = (const uint2*)t;   // 4 bf16 per lane
    int beg = __ldg(off + w);
    int end = __ldg(off + w + 1);

    float di = __ldg(dinv + w);
    float s = di * di;

    float4 acc;
    {
        uint2 raw = tp[(size_t)w * 32 + lane];
        float2 f01 = __bfloat1622float2(*reinterpret_cast<const __nv_bfloat162*>(&raw.x));
        float2 f23 = __bfloat1622float2(*reinterpret_cast<const __nv_bfloat162*>(&raw.y));
        acc = make_float4(s * f01.x, s * f01.y, s * f23.x, s * f23.y);
    }

    int e = beg;
    for (; e + 3 < end; e += 4) {
        int2 p0 = __ldg(epack + e);
        int2 p1 = __ldg(epack + e + 1);
        int2 p2 = __ldg(epack + e + 2);
        int2 p3 = __ldg(epack + e + 3);
        uint2 r0 = tp[(size_t)p0.x * 32 + lane];
        uint2 r1 = tp[(size_t)p1.x * 32 + lane];
        uint2 r2 = tp[(size_t)p2.x * 32 + lane];
        uint2 r3 = tp[(size_t)p3.x * 32 + lane];
        float c0 = __int_as_float(p0.y), c1 = __int_as_float(p1.y);
        float c2 = __int_as_float(p2.y), c3 = __int_as_float(p3.y);
        float2 a0 = __bfloat1622float2(*reinterpret_cast<const __nv_bfloat162*>(&r0.x));
        float2 b0 = __bfloat1622float2(*reinterpret_cast<const __nv_bfloat162*>(&r0.y));
        float2 a1 = __bfloat1622float2(*reinterpret_cast<const __nv_bfloat162*>(&r1.x));
        float2 b1 = __bfloat1622float2(*reinterpret_cast<const __nv_bfloat162*>(&r1.y));
        float2 a2 = __bfloat1622float2(*reinterpret_cast<const __nv_bfloat162*>(&r2.x));
        float2 b2 = __bfloat1622float2(*reinterpret_cast<const __nv_bfloat162*>(&r2.y));
        float2 a3 = __bfloat1622float2(*reinterpret_cast<const __nv_bfloat162*>(&r3.x));
        float2 b3 = __bfloat1622float2(*reinterpret_cast<const __nv_bfloat162*>(&r3.y));
        acc.x += c0 * a0.x + c1 * a1.x + c2 * a2.x + c3 * a3.x;
        acc.y += c0 * a0.y + c1 * a1.y + c2 * a2.y + c3 * a3.y;
        acc.z += c0 * b0.x + c1 * b1.x + c2 * b2.x + c3 * b3.x;
        acc.w += c0 * b0.y + c1 * b1.y + c2 * b2.y + c3 * b3.y;
    }
    for (; e < end; e++) {
        int2 p0 = __ldg(epack + e);
        float c0 = __int_as_float(p0.y);
        uint2 r0 = tp[(size_t)p0.x * 32 + lane];
        float2 a0 = __bfloat1622float2(*reinterpret_cast<const __nv_bfloat162*>(&r0.x));
        float2 b0 = __bfloat1622float2(*reinterpret_cast<const __nv_bfloat162*>(&r0.y));
        acc.x += c0 * a0.x;
        acc.y += c0 * a0.y;
        acc.z += c0 * b0.x;
        acc.w += c0 * b0.y;
    }

    float4 bv = *(const float4*)&bias[lane * 4];
    acc.x = fmaxf(acc.x + bv.x, 0.f);
    acc.y = fmaxf(acc.y + bv.y, 0.f);
    acc.z = fmaxf(acc.z + bv.z, 0.f);
    acc.w = fmaxf(acc.w + bv.w, 0.f);
    ((float4*)out)[(size_t)w * 32 + lane] = acc;
}

// ================= launch =================
extern "C" void kernel_launch(void* const* d_in, const int* in_sizes, int n_in,
                              void* d_out, int out_size)
{
    const float* x   = (const float*)d_in[0];
    const int*   ei  = (const int*)d_in[1];
    const float* ew  = (const float*)d_in[2];
    const float* Wp  = (const float*)d_in[3];
    const float* bp  = (const float*)d_in[4];
    const float* W1  = (const float*)d_in[5];
    const float* b1  = (const float*)d_in[6];
    const float* W2  = (const float*)d_in[7];
    const float* b2  = (const float*)d_in[8];
    const float* Wl1 = (const float*)d_in[9];
    const float* bl1 = (const float*)d_in[10];
    const float* Wl2 = (const float*)d_in[11];
    const float* bl2 = (const float*)d_in[12];
    float* out = (float*)d_out;

    const int M = in_sizes[0] / 256;   // 100000
    const int E = in_sizes[1] / 2;     // 1600000
    const int* src = ei;
    const int* dst = ei + E;

    float *p_h, *p_dinv;
    __nv_bfloat16* p_t;
    unsigned long long* p_degcnt;
    int *p_cnt, *p_off, *p_cur, *p_part;
    int2 *p_epack;
    __nv_bfloat16 *p_whi;
    cudaGetSymbolAddress((void**)&p_h, g_h);
    cudaGetSymbolAddress((void**)&p_t, g_t);
    cudaGetSymbolAddress((void**)&p_degcnt, g_degcnt);
    cudaGetSymbolAddress((void**)&p_dinv, g_dinv);
    cudaGetSymbolAddress((void**)&p_cnt, g_cnt);
    cudaGetSymbolAddress((void**)&p_off, g_off);
    cudaGetSymbolAddress((void**)&p_cur, g_cur);
    cudaGetSymbolAddress((void**)&p_epack, g_epack);
    cudaGetSymbolAddress((void**)&p_part, g_part);
    cudaGetSymbolAddress((void**)&p_whi, g_whi);

    cudaFuncSetAttribute(k_gemm_mma<256, 0>, cudaFuncAttributeMaxDynamicSharedMemorySize, GEMM_SMEM);
    cudaFuncSetAttribute(k_gemm_mma<128, 1>, cudaFuncAttributeMaxDynamicSharedMemorySize, GEMM_SMEM);
    cudaFuncSetAttribute(k_gemm_last, cudaFuncAttributeMaxDynamicSharedMemorySize, GEMM_SMEM);

    const int gemm_blocks = (M + 63) / 64;
    const int agg_blocks  = (M + 7) / 8;
    const int scan_blocks = (M + SCAN_CHUNK - 1) / SCAN_CHUNK;

    // weight transpose to bf16 — single launch
    k_prep_all<<<(81920 + 255) / 256, 256>>>(Wp, W1, W2, Wl1, p_whi);

    // CSR build + normalization (reused by both conv layers)
    cudaMemsetAsync(p_degcnt, 0, (size_t)NN * sizeof(unsigned long long));
    k_edge_deg<<<(E + 255) / 256, 256>>>(dst, ew, p_degcnt, E);
    k_dinv<<<(M + 255) / 256, 256>>>(p_degcnt, p_dinv, p_cnt, M);
    k_scan1<<<scan_blocks, SCAN_CHUNK>>>(p_cnt, p_part, M);
    k_scan2<<<1, 512>>>(p_part, scan_blocks);
    k_scan3<<<scan_blocks, SCAN_CHUNK>>>(p_cnt, p_part, p_off, p_cur, M, E);
    k_scatter<<<(E + 255) / 256, 256>>>(src, dst, ew, p_dinv, p_cur, p_epack, E);

    // h0 = relu(x @ Wp + bp)
    k_gemm_mma<256, 0><<<gemm_blocks, 256, GEMM_SMEM>>>(x, p_whi, bp, p_h, M);

    // conv1: t = h0 @ W1 (bf16); h = relu(aggregate(t) + b1)
    k_gemm_mma<128, 1><<<gemm_blocks, 256, GEMM_SMEM>>>(p_h, p_whi + 32768, nullptr, p_t, M);
    k_agg<<<agg_blocks, 256>>>(p_off, p_epack, p_t, p_dinv, b1, p_h, M);

    // conv2
    k_gemm_mma<128, 1><<<gemm_blocks, 256, GEMM_SMEM>>>(p_h, p_whi + 49152, nullptr, p_t, M);
    k_agg<<<agg_blocks, 256>>>(p_off, p_epack, p_t, p_dinv, b2, p_h, M);

    // fused: softmax(relu(h @ Wl1 + bl1) @ Wl2 + bl2)
    k_gemm_last<<<gemm_blocks, 256, GEMM_SMEM>>>(p_h, p_whi + 65536, bl1, Wl2, bl2, out, M);
}

// round 13
// speedup vs baseline: 1.5936x; 1.0639x over previous
#include <cuda_runtime.h>
#include <cuda_bf16.h>
#include <math.h>
#include <stdint.h>

#define NN 100000
#define EE 1600000
#define SCAN_CHUNK 256

// Scratch (no device allocation allowed)
__device__ __nv_bfloat16 g_h[(size_t)NN * 128];   // activations, bf16
__device__ __nv_bfloat16 g_t[(size_t)NN * 128];   // conv GEMM output, bf16
__device__ unsigned long long g_degcnt[NN];
__device__ float g_dinv[NN];
__device__ int   g_cnt[NN];
__device__ int   g_off[NN + 1];
__device__ int   g_cur[NN];
__device__ int2  g_epack[EE];     // {src, coef-as-int}
__device__ int   g_part[512];
// transposed bf16 weights: Wp^T @0 (128x256), W1^T @32768, W2^T @49152, Wl1^T @65536
__device__ __nv_bfloat16 g_whi[81920];

// ================= mma.sync / cp.async helpers (baseline PTX, sm_80+) =================
__device__ __forceinline__ void ldsm4(uint32_t d[4], const void* p) {
    uint32_t a = (uint32_t)__cvta_generic_to_shared(p);
    asm volatile("ldmatrix.sync.aligned.m8n8.x4.shared.b16 {%0,%1,%2,%3}, [%4];"
        : "=r"(d[0]), "=r"(d[1]), "=r"(d[2]), "=r"(d[3]) : "r"(a));
}
__device__ __forceinline__ void ldsm2(uint32_t d[2], const void* p) {
    uint32_t a = (uint32_t)__cvta_generic_to_shared(p);
    asm volatile("ldmatrix.sync.aligned.m8n8.x2.shared.b16 {%0,%1}, [%2];"
        : "=r"(d[0]), "=r"(d[1]) : "r"(a));
}
__device__ __forceinline__ void mma16816(float c[4], const uint32_t a[4], const uint32_t b[2]) {
    asm volatile("mma.sync.aligned.m16n8k16.row.col.f32.bf16.bf16.f32 "
        "{%0,%1,%2,%3}, {%4,%5,%6,%7}, {%8,%9}, {%0,%1,%2,%3};"
        : "+f"(c[0]), "+f"(c[1]), "+f"(c[2]), "+f"(c[3])
        : "r"(a[0]), "r"(a[1]), "r"(a[2]), "r"(a[3]), "r"(b[0]), "r"(b[1]));
}
__device__ __forceinline__ uint32_t pack_bf16(__nv_bfloat16 a, __nv_bfloat16 b) {
    return (uint32_t)__bfloat16_as_ushort(a) | ((uint32_t)__bfloat16_as_ushort(b) << 16);
}
__device__ __forceinline__ void split8(const float4& v0, const float4& v1,
                                       uint4& uh, uint4& ul) {
    float f[8] = {v0.x, v0.y, v0.z, v0.w, v1.x, v1.y, v1.z, v1.w};
    uint32_t h[4], l[4];
#pragma unroll
    for (int j = 0; j < 4; j++) {
        __nv_bfloat16 h0 = __float2bfloat16(f[2*j]);
        __nv_bfloat16 h1 = __float2bfloat16(f[2*j+1]);
        __nv_bfloat16 l0 = __float2bfloat16(f[2*j]   - __bfloat162float(h0));
        __nv_bfloat16 l1 = __float2bfloat16(f[2*j+1] - __bfloat162float(h1));
        h[j] = pack_bf16(h0, h1);
        l[j] = pack_bf16(l0, l1);
    }
    uh = make_uint4(h[0], h[1], h[2], h[3]);
    ul = make_uint4(l[0], l[1], l[2], l[3]);
}
__device__ __forceinline__ void cp16(void* dst_smem, const void* src) {
    uint32_t d = (uint32_t)__cvta_generic_to_shared(dst_smem);
    asm volatile("cp.async.cg.shared.global [%0], [%1], 16;" :: "r"(d), "l"(src) : "memory");
}
// conditional cp.async: src-size 0 zero-fills the 16B destination
__device__ __forceinline__ void cp16z(void* dst_smem, const void* src, bool pred) {
    uint32_t d = (uint32_t)__cvta_generic_to_shared(dst_smem);
    int sz = pred ? 16 : 0;
    asm volatile("cp.async.cg.shared.global [%0], [%1], 16, %2;"
                 :: "r"(d), "l"(src), "r"(sz) : "memory");
}
#define CP_COMMIT() asm volatile("cp.async.commit_group;" ::: "memory")
#define CP_WAIT0()  asm volatile("cp.async.wait_group 0;" ::: "memory")

// ================= CSR build =================
__global__ void k_edge_deg(const int* __restrict__ dst, const float* __restrict__ ew,
                           unsigned long long* degcnt, int E) {
    int e = blockIdx.x * blockDim.x + threadIdx.x;
    if (e < E) {
        unsigned long long v = (1ull << 40)
            + (unsigned long long)((double)ew[e] * 16777216.0);
        atomicAdd(&degcnt[dst[e]], v);
    }
}
__global__ void k_dinv(const unsigned long long* __restrict__ degcnt,
                       float* dinv, int* cnt, int n) {
    int i = blockIdx.x * blockDim.x + threadIdx.x;
    if (i < n) {
        unsigned long long v = degcnt[i];
        cnt[i] = (int)(v >> 40);
        float deg = 1.0f + (float)((double)(v & ((1ull << 40) - 1)) * (1.0 / 16777216.0));
        dinv[i] = rsqrtf(deg);
    }
}
__global__ __launch_bounds__(SCAN_CHUNK) void k_scan1(const int* __restrict__ cnt,
                                                      int* part, int n) {
    __shared__ int ws[8];
    int i = blockIdx.x * SCAN_CHUNK + threadIdx.x;
    int v = (i < n) ? cnt[i] : 0;
#pragma unroll
    for (int o = 16; o >= 1; o >>= 1) v += __shfl_xor_sync(0xFFFFFFFFu, v, o);
    if ((threadIdx.x & 31) == 0) ws[threadIdx.x >> 5] = v;
    __syncthreads();
    if (threadIdx.x == 0) {
        int s = 0;
#pragma unroll
        for (int w = 0; w < 8; w++) s += ws[w];
        part[blockIdx.x] = s;
    }
}
__global__ __launch_bounds__(512) void k_scan2(int* part, int nb) {
    __shared__ int s[512];
    int tid = threadIdx.x;
    int v = (tid < nb) ? part[tid] : 0;
    s[tid] = v;
    __syncthreads();
#pragma unroll
    for (int d = 1; d < 512; d <<= 1) {
        int add = (tid >= d) ? s[tid - d] : 0;
        __syncthreads();
        s[tid] += add;
        __syncthreads();
    }
    if (tid < nb) part[tid] = s[tid] - v;
}
__global__ __launch_bounds__(SCAN_CHUNK) void k_scan3(const int* __restrict__ cnt,
                                                      const int* __restrict__ part,
                                                      int* off, int* cur, int n, int E) {
    __shared__ int ws[8];
    int tid = threadIdx.x;
    int i = blockIdx.x * SCAN_CHUNK + tid;
    int lane = tid & 31;
    int warp = tid >> 5;
    int v = (i < n) ? cnt[i] : 0;
    int x = v;
#pragma unroll
    for (int o = 1; o < 32; o <<= 1) {
        int y = __shfl_up_sync(0xFFFFFFFFu, x, o);
        if (lane >= o) x += y;
    }
    if (lane == 31) ws[warp] = x;
    __syncthreads();
    if (warp == 0 && lane < 8) {
        int y = ws[lane];
        int z = y;
#pragma unroll
        for (int o = 1; o < 8; o <<= 1) {
            int u = __shfl_up_sync(0xFFu, z, o);
            if (lane >= o) z += u;
        }
        ws[lane] = z - y;
    }
    __syncthreads();
    if (i < n) {
        int excl = part[blockIdx.x] + ws[warp] + x - v;
        off[i] = excl;
        cur[i] = excl;
    }
    if (i == n - 1) off[n] = E;
}
__global__ void k_scatter(const int* __restrict__ src, const int* __restrict__ dst,
                          const float* __restrict__ ew, const float* __restrict__ dinv,
                          int* cur, int2* epack, int E) {
    int e = blockIdx.x * blockDim.x + threadIdx.x;
    if (e >= E) return;
    int s = src[e];
    int d = dst[e];
    float c = __ldg(dinv + s) * ew[e] * __ldg(dinv + d);
    int pos = atomicAdd(&cur[d], 1);
    epack[pos] = make_int2(s, __float_as_int(c));
}

// ================= all-weights transpose to bf16 (one launch) =================
__global__ void k_prep_all(const float* __restrict__ Wp, const float* __restrict__ W1,
                           const float* __restrict__ W2, const float* __restrict__ Wl1,
                           __nv_bfloat16* hi) {
    int idx = blockIdx.x * blockDim.x + threadIdx.x;
    if (idx >= 81920) return;
    const float* W; int K, base;
    if (idx < 32768)       { W = Wp;  K = 256; base = 0; }
    else if (idx < 49152)  { W = W1;  K = 128; base = 32768; }
    else if (idx < 65536)  { W = W2;  K = 128; base = 49152; }
    else                   { W = Wl1; K = 128; base = 65536; }
    int loc = idx - base;
    int n = loc / K, k = loc % K;
    hi[idx] = __float2bfloat16(W[(size_t)k * 128 + n]);
}

// ================= HMMA GEMM cores =================
#define KP 72
#define A_BUF (64 * KP * 2)
#define B_BUF (128 * KP * 2)
// f32-A layout (2-MMA split)
#define OFF_AH 0
#define OFF_AL (2 * A_BUF)
#define OFF_BH (4 * A_BUF)
#define GEMM_SMEM_F32 (4 * A_BUF + 2 * B_BUF)   // 73728
// bf16-A layout (1-MMA)
#define OFF_A2 0
#define OFF_B2 (2 * A_BUF)
#define GEMM_SMEM_B16 (2 * A_BUF + 2 * B_BUF)   // 55296

// ---- mainloop, fp32 A with hi/lo split (2 MMAs) ----
template <int K>
__device__ __forceinline__ void gemm_mainloop_f32(
    char* sm, const float* __restrict__ A, const __nv_bfloat16* __restrict__ Whi,
    int M, int row0, int tid, int wm, int wn, int lane, float acc[2][4][4])
{
    constexpr int CHUNKS = K / 64;
    const int ar = tid >> 2;
    const int ac = (tid & 3) * 16;
    const int gr = row0 + ar;
    const bool aok = gr < M;
    const float4* arow = (const float4*)(A + (size_t)gr * K + ac);
    const int br = tid >> 1;
    const int bc = (tid & 1) * 32;
    const __nv_bfloat16* bh_row = Whi + (size_t)br * K + bc;

    float4 areg[4];
    const float4 z4 = make_float4(0.f, 0.f, 0.f, 0.f);

    {
        __nv_bfloat16* dbh = (__nv_bfloat16*)(sm + OFF_BH) + br * KP + bc;
#pragma unroll
        for (int j = 0; j < 4; j++) cp16(dbh + j * 8, bh_row + j * 8);
        CP_COMMIT();
#pragma unroll
        for (int j = 0; j < 4; j++) areg[j] = aok ? arow[j] : z4;
        __nv_bfloat16* dah = (__nv_bfloat16*)(sm + OFF_AH) + ar * KP + ac;
        __nv_bfloat16* dal = (__nv_bfloat16*)(sm + OFF_AL) + ar * KP + ac;
#pragma unroll
        for (int j = 0; j < 2; j++) {
            uint4 uh, ul;
            split8(areg[2*j], areg[2*j+1], uh, ul);
            *(uint4*)(dah + j * 8) = uh;
            *(uint4*)(dal + j * 8) = ul;
        }
        CP_WAIT0();
    }
    __syncthreads();

#pragma unroll
    for (int c = 0; c < CHUNKS; c++) {
        const int buf = c & 1;
        const int nbuf = buf ^ 1;
        const bool more = (c + 1) < CHUNKS;

        if (more) {
            int kn = (c + 1) * 64;
            __nv_bfloat16* dbh = (__nv_bfloat16*)(sm + OFF_BH + nbuf * B_BUF) + br * KP + bc;
#pragma unroll
            for (int j = 0; j < 4; j++) cp16(dbh + j * 8, bh_row + kn + j * 8);
            CP_COMMIT();
#pragma unroll
            for (int j = 0; j < 4; j++) areg[j] = aok ? arow[kn / 4 + j] : z4;
        }

        const __nv_bfloat16* Ah = (const __nv_bfloat16*)(sm + OFF_AH + buf * A_BUF);
        const __nv_bfloat16* Al = (const __nv_bfloat16*)(sm + OFF_AL + buf * A_BUF);
        const __nv_bfloat16* Bh = (const __nv_bfloat16*)(sm + OFF_BH + buf * B_BUF);
#pragma unroll
        for (int ks = 0; ks < 64; ks += 16) {
            uint32_t ah[2][4], al[2][4], bhf[4][2];
#pragma unroll
            for (int mt = 0; mt < 2; mt++) {
                int r = wm * 32 + mt * 16 + (lane & 15);
                int cc = ks + ((lane >> 4) << 3);
                ldsm4(ah[mt], Ah + r * KP + cc);
                ldsm4(al[mt], Al + r * KP + cc);
            }
#pragma unroll
            for (int nt = 0; nt < 4; nt++) {
                int n = wn * 32 + nt * 8 + (lane & 7);
                int cc = ks + ((lane >> 3) & 1) * 8;
                ldsm2(bhf[nt], Bh + n * KP + cc);
            }
#pragma unroll
            for (int mt = 0; mt < 2; mt++)
#pragma unroll
                for (int nt = 0; nt < 4; nt++) {
                    mma16816(acc[mt][nt], ah[mt], bhf[nt]);
                    mma16816(acc[mt][nt], al[mt], bhf[nt]);
                }
        }

        if (more) {
            __nv_bfloat16* dah = (__nv_bfloat16*)(sm + OFF_AH + nbuf * A_BUF) + ar * KP + ac;
            __nv_bfloat16* dal = (__nv_bfloat16*)(sm + OFF_AL + nbuf * A_BUF) + ar * KP + ac;
#pragma unroll
            for (int j = 0; j < 2; j++) {
                uint4 uh, ul;
                split8(areg[2*j], areg[2*j+1], uh, ul);
                *(uint4*)(dah + j * 8) = uh;
                *(uint4*)(dal + j * 8) = ul;
            }
            CP_WAIT0();
            __syncthreads();
        }
    }
}

// ---- mainloop, bf16 A (1 MMA), both operands via cp.async ----
template <int K>
__device__ __forceinline__ void gemm_mainloop_b16(
    char* sm, const __nv_bfloat16* __restrict__ A, const __nv_bfloat16* __restrict__ Whi,
    int M, int row0, int tid, int wm, int wn, int lane, float acc[2][4][4])
{
    constexpr int CHUNKS = K / 64;
    const int ar = tid >> 2;
    const int ac = (tid & 3) * 16;          // 16 bf16 = 2 x cp16
    const int gr = row0 + ar;
    const bool aok = gr < M;
    const __nv_bfloat16* arow = A + (size_t)(aok ? gr : 0) * K + ac;
    const int br = tid >> 1;
    const int bc = (tid & 1) * 32;
    const __nv_bfloat16* bh_row = Whi + (size_t)br * K + bc;

#pragma unroll
    for (int c = 0; c < CHUNKS; c++) {
        const int buf = c & 1;
        {
            int kn = c * 64;
            __nv_bfloat16* da = (__nv_bfloat16*)(sm + OFF_A2 + buf * A_BUF) + ar * KP + ac;
            __nv_bfloat16* db = (__nv_bfloat16*)(sm + OFF_B2 + buf * B_BUF) + br * KP + bc;
            cp16z(da,     arow + kn,     aok);
            cp16z(da + 8, arow + kn + 8, aok);
#pragma unroll
            for (int j = 0; j < 4; j++) cp16(db + j * 8, bh_row + kn + j * 8);
            CP_COMMIT();
        }
        if (c == 0) { CP_WAIT0(); __syncthreads(); }
        else {
            // wait for this buffer's group: one group in flight -> wait all
            CP_WAIT0(); __syncthreads();
        }

        const __nv_bfloat16* Ah = (const __nv_bfloat16*)(sm + OFF_A2 + buf * A_BUF);
        const __nv_bfloat16* Bh = (const __nv_bfloat16*)(sm + OFF_B2 + buf * B_BUF);
#pragma unroll
        for (int ks = 0; ks < 64; ks += 16) {
            uint32_t ah[2][4], bhf[4][2];
#pragma unroll
            for (int mt = 0; mt < 2; mt++) {
                int r = wm * 32 + mt * 16 + (lane & 15);
                int cc = ks + ((lane >> 4) << 3);
                ldsm4(ah[mt], Ah + r * KP + cc);
            }
#pragma unroll
            for (int nt = 0; nt < 4; nt++) {
                int n = wn * 32 + nt * 8 + (lane & 7);
                int cc = ks + ((lane >> 3) & 1) * 8;
                ldsm2(bhf[nt], Bh + n * KP + cc);
            }
#pragma unroll
            for (int mt = 0; mt < 2; mt++)
#pragma unroll
                for (int nt = 0; nt < 4; nt++)
                    mma16816(acc[mt][nt], ah[mt], bhf[nt]);
        }
        if (c + 1 < CHUNKS) __syncthreads();
    }
}

// GEMM1: fp32 A, bf16 out = relu(acc + bias)
__global__ __launch_bounds__(256) void k_gemm1(
    const float* __restrict__ A, const __nv_bfloat16* __restrict__ Whi,
    const float* __restrict__ bias, __nv_bfloat16* __restrict__ out, int M)
{
    extern __shared__ char sm[];
    const int tid  = threadIdx.x;
    const int wid  = tid >> 5;
    const int lane = tid & 31;
    const int wm   = wid & 1;
    const int wn   = wid >> 1;
    const int row0 = blockIdx.x * 64;

    float acc[2][4][4];
#pragma unroll
    for (int mt = 0; mt < 2; mt++)
#pragma unroll
        for (int nt = 0; nt < 4; nt++)
#pragma unroll
            for (int j = 0; j < 4; j++) acc[mt][nt][j] = 0.0f;

    gemm_mainloop_f32<256>(sm, A, Whi, M, row0, tid, wm, wn, lane, acc);

#pragma unroll
    for (int mt = 0; mt < 2; mt++) {
        int r1 = row0 + wm * 32 + mt * 16 + (lane >> 2);
        int r2 = r1 + 8;
#pragma unroll
        for (int nt = 0; nt < 4; nt++) {
            int c = wn * 32 + nt * 8 + (lane & 3) * 2;
            float b0 = __ldg(bias + c), b1 = __ldg(bias + c + 1);
            uint32_t p1 = pack_bf16(__float2bfloat16(fmaxf(acc[mt][nt][0] + b0, 0.f)),
                                    __float2bfloat16(fmaxf(acc[mt][nt][1] + b1, 0.f)));
            uint32_t p2 = pack_bf16(__float2bfloat16(fmaxf(acc[mt][nt][2] + b0, 0.f)),
                                    __float2bfloat16(fmaxf(acc[mt][nt][3] + b1, 0.f)));
            if (r1 < M) *(uint32_t*)&out[(size_t)r1 * 128 + c] = p1;
            if (r2 < M) *(uint32_t*)&out[(size_t)r2 * 128 + c] = p2;
        }
    }
}

// Conv GEMM: bf16 A, bf16 out = acc (raw)
__global__ __launch_bounds__(256) void k_gemm_b16(
    const __nv_bfloat16* __restrict__ A, const __nv_bfloat16* __restrict__ Whi,
    __nv_bfloat16* __restrict__ out, int M)
{
    extern __shared__ char sm[];
    const int tid  = threadIdx.x;
    const int wid  = tid >> 5;
    const int lane = tid & 31;
    const int wm   = wid & 1;
    const int wn   = wid >> 1;
    const int row0 = blockIdx.x * 64;

    float acc[2][4][4];
#pragma unroll
    for (int mt = 0; mt < 2; mt++)
#pragma unroll
        for (int nt = 0; nt < 4; nt++)
#pragma unroll
            for (int j = 0; j < 4; j++) acc[mt][nt][j] = 0.0f;

    gemm_mainloop_b16<128>(sm, A, Whi, M, row0, tid, wm, wn, lane, acc);

#pragma unroll
    for (int mt = 0; mt < 2; mt++) {
        int r1 = row0 + wm * 32 + mt * 16 + (lane >> 2);
        int r2 = r1 + 8;
#pragma unroll
        for (int nt = 0; nt < 4; nt++) {
            int c = wn * 32 + nt * 8 + (lane & 3) * 2;
            uint32_t p1 = pack_bf16(__float2bfloat16(acc[mt][nt][0]),
                                    __float2bfloat16(acc[mt][nt][1]));
            uint32_t p2 = pack_bf16(__float2bfloat16(acc[mt][nt][2]),
                                    __float2bfloat16(acc[mt][nt][3]));
            if (r1 < M) *(uint32_t*)&out[(size_t)r1 * 128 + c] = p1;
            if (r2 < M) *(uint32_t*)&out[(size_t)r2 * 128 + c] = p2;
        }
    }
}

// Fused final: bf16 A; hmid = relu(acc+bl1) in smem; logits = hmid@Wl2+bl2; softmax.
__global__ __launch_bounds__(256) void k_gemm_last(
    const __nv_bfloat16* __restrict__ A, const __nv_bfloat16* __restrict__ Whi,
    const float* __restrict__ bl1, const float* __restrict__ Wl2,
    const float* __restrict__ bl2, float* __restrict__ out, int M)
{
    extern __shared__ char sm[];
    const int tid  = threadIdx.x;
    const int wid  = tid >> 5;
    const int lane = tid & 31;
    const int wm   = wid & 1;
    const int wn   = wid >> 1;
    const int row0 = blockIdx.x * 64;

    float acc[2][4][4];
#pragma unroll
    for (int mt = 0; mt < 2; mt++)
#pragma unroll
        for (int nt = 0; nt < 4; nt++)
#pragma unroll
            for (int j = 0; j < 4; j++) acc[mt][nt][j] = 0.0f;

    gemm_mainloop_b16<128>(sm, A, Whi, M, row0, tid, wm, wn, lane, acc);

    __syncthreads();
    float* hs  = (float*)sm;             // 64 x 128 fp32 = 32768 B
    float* w2s = (float*)(sm + 32768);   // 128 x 32 fp32 = 16384 B  (total 49152 < 55296)

#pragma unroll
    for (int mt = 0; mt < 2; mt++) {
        int lr1 = wm * 32 + mt * 16 + (lane >> 2);
        int lr2 = lr1 + 8;
#pragma unroll
        for (int nt = 0; nt < 4; nt++) {
            int c = wn * 32 + nt * 8 + (lane & 3) * 2;
            float b0 = __ldg(bl1 + c), b1 = __ldg(bl1 + c + 1);
            float2 v1 = make_float2(fmaxf(acc[mt][nt][0] + b0, 0.f),
                                    fmaxf(acc[mt][nt][1] + b1, 0.f));
            float2 v2 = make_float2(fmaxf(acc[mt][nt][2] + b0, 0.f),
                                    fmaxf(acc[mt][nt][3] + b1, 0.f));
            *(float2*)&hs[lr1 * 128 + c] = v1;
            *(float2*)&hs[lr2 * 128 + c] = v2;
        }
    }
    for (int i = tid; i < 4096; i += 256) w2s[i] = __ldg(Wl2 + i);
    __syncthreads();

    float bb = __ldg(bl2 + lane);
#pragma unroll 1
    for (int i = 0; i < 8; i++) {
        int r = row0 + wid * 8 + i;
        if (r >= M) break;
        const float* hr = hs + (wid * 8 + i) * 128;
        float a = bb;
#pragma unroll
        for (int k = 0; k < 128; k += 4) {
            float4 h4 = *(const float4*)(hr + k);
            a += h4.x * w2s[(k + 0) * 32 + lane];
            a += h4.y * w2s[(k + 1) * 32 + lane];
            a += h4.z * w2s[(k + 2) * 32 + lane];
            a += h4.w * w2s[(k + 3) * 32 + lane];
        }
        float m = a;
#pragma unroll
        for (int o = 16; o >= 1; o >>= 1) m = fmaxf(m, __shfl_xor_sync(0xFFFFFFFFu, m, o));
        float e = __expf(a - m);
        float s = e;
#pragma unroll
        for (int o = 16; o >= 1; o >>= 1) s += __shfl_xor_sync(0xFFFFFFFFu, s, o);
        out[(size_t)r * 32 + lane] = e / s;
    }
}

// ================= gather aggregation (bf16 t -> bf16 h): one warp per node =================
__global__ __launch_bounds__(256) void k_agg(
    const int* __restrict__ off, const int2* __restrict__ epack,
    const __nv_bfloat16* __restrict__ t, const float* __restrict__ dinv,
    const float* __restrict__ bias, __nv_bfloat16* __restrict__ out, int n)
{
    int w = (blockIdx.x * blockDim.x + threadIdx.x) >> 5;
    if (w >= n) return;
    int lane = threadIdx.x & 31;

    const uint2* tp = (const uint2*)t;
    int beg = __ldg(off + w);
    int end = __ldg(off + w + 1);

    float di = __ldg(dinv + w);
    float s = di * di;

    float4 acc;
    {
        uint2 raw = tp[(size_t)w * 32 + lane];
        float2 f01 = __bfloat1622float2(*reinterpret_cast<const __nv_bfloat162*>(&raw.x));
        float2 f23 = __bfloat1622float2(*reinterpret_cast<const __nv_bfloat162*>(&raw.y));
        acc = make_float4(s * f01.x, s * f01.y, s * f23.x, s * f23.y);
    }

    int e = beg;
    for (; e + 3 < end; e += 4) {
        int2 p0 = __ldg(epack + e);
        int2 p1 = __ldg(epack + e + 1);
        int2 p2 = __ldg(epack + e + 2);
        int2 p3 = __ldg(epack + e + 3);
        uint2 r0 = tp[(size_t)p0.x * 32 + lane];
        uint2 r1 = tp[(size_t)p1.x * 32 + lane];
        uint2 r2 = tp[(size_t)p2.x * 32 + lane];
        uint2 r3 = tp[(size_t)p3.x * 32 + lane];
        float c0 = __int_as_float(p0.y), c1 = __int_as_float(p1.y);
        float c2 = __int_as_float(p2.y), c3 = __int_as_float(p3.y);
        float2 a0 = __bfloat1622float2(*reinterpret_cast<const __nv_bfloat162*>(&r0.x));
        float2 b0 = __bfloat1622float2(*reinterpret_cast<const __nv_bfloat162*>(&r0.y));
        float2 a1 = __bfloat1622float2(*reinterpret_cast<const __nv_bfloat162*>(&r1.x));
        float2 b1 = __bfloat1622float2(*reinterpret_cast<const __nv_bfloat162*>(&r1.y));
        float2 a2 = __bfloat1622float2(*reinterpret_cast<const __nv_bfloat162*>(&r2.x));
        float2 b2 = __bfloat1622float2(*reinterpret_cast<const __nv_bfloat162*>(&r2.y));
        float2 a3 = __bfloat1622float2(*reinterpret_cast<const __nv_bfloat162*>(&r3.x));
        float2 b3 = __bfloat1622float2(*reinterpret_cast<const __nv_bfloat162*>(&r3.y));
        acc.x += c0 * a0.x + c1 * a1.x + c2 * a2.x + c3 * a3.x;
        acc.y += c0 * a0.y + c1 * a1.y + c2 * a2.y + c3 * a3.y;
        acc.z += c0 * b0.x + c1 * b1.x + c2 * b2.x + c3 * b3.x;
        acc.w += c0 * b0.y + c1 * b1.y + c2 * b2.y + c3 * b3.y;
    }
    for (; e < end; e++) {
        int2 p0 = __ldg(epack + e);
        float c0 = __int_as_float(p0.y);
        uint2 r0 = tp[(size_t)p0.x * 32 + lane];
        float2 a0 = __bfloat1622float2(*reinterpret_cast<const __nv_bfloat162*>(&r0.x));
        float2 b0 = __bfloat1622float2(*reinterpret_cast<const __nv_bfloat162*>(&r0.y));
        acc.x += c0 * a0.x;
        acc.y += c0 * a0.y;
        acc.z += c0 * b0.x;
        acc.w += c0 * b0.y;
    }

    float4 bv = *(const float4*)&bias[lane * 4];
    uint2 o;
    o.x = pack_bf16(__float2bfloat16(fmaxf(acc.x + bv.x, 0.f)),
                    __float2bfloat16(fmaxf(acc.y + bv.y, 0.f)));
    o.y = pack_bf16(__float2bfloat16(fmaxf(acc.z + bv.z, 0.f)),
                    __float2bfloat16(fmaxf(acc.w + bv.w, 0.f)));
    ((uint2*)out)[(size_t)w * 32 + lane] = o;
}

// ================= launch =================
extern "C" void kernel_launch(void* const* d_in, const int* in_sizes, int n_in,
                              void* d_out, int out_size)
{
    const float* x   = (const float*)d_in[0];
    const int*   ei  = (const int*)d_in[1];
    const float* ew  = (const float*)d_in[2];
    const float* Wp  = (const float*)d_in[3];
    const float* bp  = (const float*)d_in[4];
    const float* W1  = (const float*)d_in[5];
    const float* b1  = (const float*)d_in[6];
    const float* W2  = (const float*)d_in[7];
    const float* b2  = (const float*)d_in[8];
    const float* Wl1 = (const float*)d_in[9];
    const float* bl1 = (const float*)d_in[10];
    const float* Wl2 = (const float*)d_in[11];
    const float* bl2 = (const float*)d_in[12];
    float* out = (float*)d_out;

    const int M = in_sizes[0] / 256;   // 100000
    const int E = in_sizes[1] / 2;     // 1600000
    const int* src = ei;
    const int* dst = ei + E;

    float *p_dinv;
    __nv_bfloat16 *p_h, *p_t, *p_whi;
    unsigned long long* p_degcnt;
    int *p_cnt, *p_off, *p_cur, *p_part;
    int2 *p_epack;
    cudaGetSymbolAddress((void**)&p_h, g_h);
    cudaGetSymbolAddress((void**)&p_t, g_t);
    cudaGetSymbolAddress((void**)&p_degcnt, g_degcnt);
    cudaGetSymbolAddress((void**)&p_dinv, g_dinv);
    cudaGetSymbolAddress((void**)&p_cnt, g_cnt);
    cudaGetSymbolAddress((void**)&p_off, g_off);
    cudaGetSymbolAddress((void**)&p_cur, g_cur);
    cudaGetSymbolAddress((void**)&p_epack, g_epack);
    cudaGetSymbolAddress((void**)&p_part, g_part);
    cudaGetSymbolAddress((void**)&p_whi, g_whi);

    cudaFuncSetAttribute(k_gemm1,    cudaFuncAttributeMaxDynamicSharedMemorySize, GEMM_SMEM_F32);
    cudaFuncSetAttribute(k_gemm_b16, cudaFuncAttributeMaxDynamicSharedMemorySize, GEMM_SMEM_B16);
    cudaFuncSetAttribute(k_gemm_last, cudaFuncAttributeMaxDynamicSharedMemorySize, GEMM_SMEM_B16);

    const int gemm_blocks = (M + 63) / 64;
    const int agg_blocks  = (M + 7) / 8;
    const int scan_blocks = (M + SCAN_CHUNK - 1) / SCAN_CHUNK;

    // weight transpose to bf16 — single launch
    k_prep_all<<<(81920 + 255) / 256, 256>>>(Wp, W1, W2, Wl1, p_whi);

    // CSR build + normalization (reused by both conv layers)
    cudaMemsetAsync(p_degcnt, 0, (size_t)NN * sizeof(unsigned long long));
    k_edge_deg<<<(E + 255) / 256, 256>>>(dst, ew, p_degcnt, E);
    k_dinv<<<(M + 255) / 256, 256>>>(p_degcnt, p_dinv, p_cnt, M);
    k_scan1<<<scan_blocks, SCAN_CHUNK>>>(p_cnt, p_part, M);
    k_scan2<<<1, 512>>>(p_part, scan_blocks);
    k_scan3<<<scan_blocks, SCAN_CHUNK>>>(p_cnt, p_part, p_off, p_cur, M, E);
    k_scatter<<<(E + 255) / 256, 256>>>(src, dst, ew, p_dinv, p_cur, p_epack, E);

    // h0 = relu(x @ Wp + bp)  -> bf16
    k_gemm1<<<gemm_blocks, 256, GEMM_SMEM_F32>>>(x, p_whi, bp, p_h, M);

    // conv1: t = h0 @ W1 (bf16); h = relu(aggregate(t) + b1) -> bf16
    k_gemm_b16<<<gemm_blocks, 256, GEMM_SMEM_B16>>>(p_h, p_whi + 32768, p_t, M);
    k_agg<<<agg_blocks, 256>>>(p_off, p_epack, p_t, p_dinv, b1, p_h, M);

    // conv2
    k_gemm_b16<<<gemm_blocks, 256, GEMM_SMEM_B16>>>(p_h, p_whi + 49152, p_t, M);
    k_agg<<<agg_blocks, 256>>>(p_off, p_epack, p_t, p_dinv, b2, p_h, M);

    // fused: softmax(relu(h @ Wl1 + bl1) @ Wl2 + bl2)
    k_gemm_last<<<gemm_blocks, 256, GEMM_SMEM_B16>>>(p_h, p_whi + 65536, bl1, Wl2, bl2, out, M);
}

// round 14
// speedup vs baseline: 1.6149x; 1.0134x over previous
#include <cuda_runtime.h>
#include <cuda_bf16.h>
#include <math.h>
#include <stdint.h>

#define NN 100000
#define EE 1600000
#define SCAN_CHUNK 256

// Scratch (no device allocation allowed)
__device__ __nv_bfloat16 g_h[(size_t)NN * 128];   // activations, bf16
__device__ __nv_bfloat16 g_t[(size_t)NN * 128];   // conv GEMM output, bf16
__device__ unsigned long long g_degcnt[NN];
__device__ float g_dinv[NN];
__device__ int   g_cnt[NN];
__device__ int   g_off[NN + 1];
__device__ int   g_cur[NN];
__device__ int2  g_epack[EE];     // {src, coef-as-int}
__device__ int   g_part[512];
// transposed bf16 weights: Wp^T @0 (128x256), W1^T @32768, W2^T @49152, Wl1^T @65536
__device__ __nv_bfloat16 g_whi[81920];

// ================= mma.sync / cp.async helpers (baseline PTX, sm_80+) =================
__device__ __forceinline__ void ldsm4(uint32_t d[4], const void* p) {
    uint32_t a = (uint32_t)__cvta_generic_to_shared(p);
    asm volatile("ldmatrix.sync.aligned.m8n8.x4.shared.b16 {%0,%1,%2,%3}, [%4];"
        : "=r"(d[0]), "=r"(d[1]), "=r"(d[2]), "=r"(d[3]) : "r"(a));
}
__device__ __forceinline__ void ldsm2(uint32_t d[2], const void* p) {
    uint32_t a = (uint32_t)__cvta_generic_to_shared(p);
    asm volatile("ldmatrix.sync.aligned.m8n8.x2.shared.b16 {%0,%1}, [%2];"
        : "=r"(d[0]), "=r"(d[1]) : "r"(a));
}
__device__ __forceinline__ void mma16816(float c[4], const uint32_t a[4], const uint32_t b[2]) {
    asm volatile("mma.sync.aligned.m16n8k16.row.col.f32.bf16.bf16.f32 "
        "{%0,%1,%2,%3}, {%4,%5,%6,%7}, {%8,%9}, {%0,%1,%2,%3};"
        : "+f"(c[0]), "+f"(c[1]), "+f"(c[2]), "+f"(c[3])
        : "r"(a[0]), "r"(a[1]), "r"(a[2]), "r"(a[3]), "r"(b[0]), "r"(b[1]));
}
__device__ __forceinline__ uint32_t pack_bf16(__nv_bfloat16 a, __nv_bfloat16 b) {
    return (uint32_t)__bfloat16_as_ushort(a) | ((uint32_t)__bfloat16_as_ushort(b) << 16);
}
__device__ __forceinline__ void split8(const float4& v0, const float4& v1,
                                       uint4& uh, uint4& ul) {
    float f[8] = {v0.x, v0.y, v0.z, v0.w, v1.x, v1.y, v1.z, v1.w};
    uint32_t h[4], l[4];
#pragma unroll
    for (int j = 0; j < 4; j++) {
        __nv_bfloat16 h0 = __float2bfloat16(f[2*j]);
        __nv_bfloat16 h1 = __float2bfloat16(f[2*j+1]);
        __nv_bfloat16 l0 = __float2bfloat16(f[2*j]   - __bfloat162float(h0));
        __nv_bfloat16 l1 = __float2bfloat16(f[2*j+1] - __bfloat162float(h1));
        h[j] = pack_bf16(h0, h1);
        l[j] = pack_bf16(l0, l1);
    }
    uh = make_uint4(h[0], h[1], h[2], h[3]);
    ul = make_uint4(l[0], l[1], l[2], l[3]);
}
__device__ __forceinline__ void cp16(void* dst_smem, const void* src) {
    uint32_t d = (uint32_t)__cvta_generic_to_shared(dst_smem);
    asm volatile("cp.async.cg.shared.global [%0], [%1], 16;" :: "r"(d), "l"(src) : "memory");
}
__device__ __forceinline__ void cp16z(void* dst_smem, const void* src, bool pred) {
    uint32_t d = (uint32_t)__cvta_generic_to_shared(dst_smem);
    int sz = pred ? 16 : 0;
    asm volatile("cp.async.cg.shared.global [%0], [%1], 16, %2;"
                 :: "r"(d), "l"(src), "r"(sz) : "memory");
}
#define CP_COMMIT() asm volatile("cp.async.commit_group;" ::: "memory")
#define CP_WAIT0()  asm volatile("cp.async.wait_group 0;" ::: "memory")

// ================= CSR build =================
__global__ void k_edge_deg(const int* __restrict__ dst, const float* __restrict__ ew,
                           unsigned long long* degcnt, int E) {
    int e = blockIdx.x * blockDim.x + threadIdx.x;
    if (e < E) {
        unsigned long long v = (1ull << 40)
            + (unsigned long long)((double)ew[e] * 16777216.0);
        atomicAdd(&degcnt[dst[e]], v);
    }
}
__global__ void k_dinv(const unsigned long long* __restrict__ degcnt,
                       float* dinv, int* cnt, int n) {
    int i = blockIdx.x * blockDim.x + threadIdx.x;
    if (i < n) {
        unsigned long long v = degcnt[i];
        cnt[i] = (int)(v >> 40);
        float deg = 1.0f + (float)((double)(v & ((1ull << 40) - 1)) * (1.0 / 16777216.0));
        dinv[i] = rsqrtf(deg);
    }
}
__global__ __launch_bounds__(SCAN_CHUNK) void k_scan1(const int* __restrict__ cnt,
                                                      int* part, int n) {
    __shared__ int ws[8];
    int i = blockIdx.x * SCAN_CHUNK + threadIdx.x;
    int v = (i < n) ? cnt[i] : 0;
#pragma unroll
    for (int o = 16; o >= 1; o >>= 1) v += __shfl_xor_sync(0xFFFFFFFFu, v, o);
    if ((threadIdx.x & 31) == 0) ws[threadIdx.x >> 5] = v;
    __syncthreads();
    if (threadIdx.x == 0) {
        int s = 0;
#pragma unroll
        for (int w = 0; w < 8; w++) s += ws[w];
        part[blockIdx.x] = s;
    }
}
__global__ __launch_bounds__(512) void k_scan2(int* part, int nb) {
    __shared__ int s[512];
    int tid = threadIdx.x;
    int v = (tid < nb) ? part[tid] : 0;
    s[tid] = v;
    __syncthreads();
#pragma unroll
    for (int d = 1; d < 512; d <<= 1) {
        int add = (tid >= d) ? s[tid - d] : 0;
        __syncthreads();
        s[tid] += add;
        __syncthreads();
    }
    if (tid < nb) part[tid] = s[tid] - v;
}
__global__ __launch_bounds__(SCAN_CHUNK) void k_scan3(const int* __restrict__ cnt,
                                                      const int* __restrict__ part,
                                                      int* off, int* cur, int n, int E) {
    __shared__ int ws[8];
    int tid = threadIdx.x;
    int i = blockIdx.x * SCAN_CHUNK + tid;
    int lane = tid & 31;
    int warp = tid >> 5;
    int v = (i < n) ? cnt[i] : 0;
    int x = v;
#pragma unroll
    for (int o = 1; o < 32; o <<= 1) {
        int y = __shfl_up_sync(0xFFFFFFFFu, x, o);
        if (lane >= o) x += y;
    }
    if (lane == 31) ws[warp] = x;
    __syncthreads();
    if (warp == 0 && lane < 8) {
        int y = ws[lane];
        int z = y;
#pragma unroll
        for (int o = 1; o < 8; o <<= 1) {
            int u = __shfl_up_sync(0xFFu, z, o);
            if (lane >= o) z += u;
        }
        ws[lane] = z - y;
    }
    __syncthreads();
    if (i < n) {
        int excl = part[blockIdx.x] + ws[warp] + x - v;
        off[i] = excl;
        cur[i] = excl;
    }
    if (i == n - 1) off[n] = E;
}
__global__ void k_scatter(const int* __restrict__ src, const int* __restrict__ dst,
                          const float* __restrict__ ew, const float* __restrict__ dinv,
                          int* cur, int2* epack, int E) {
    int e = blockIdx.x * blockDim.x + threadIdx.x;
    if (e >= E) return;
    int s = src[e];
    int d = dst[e];
    float c = __ldg(dinv + s) * ew[e] * __ldg(dinv + d);
    int pos = atomicAdd(&cur[d], 1);
    epack[pos] = make_int2(s, __float_as_int(c));
}

// ================= all-weights transpose to bf16 (one launch) =================
__global__ void k_prep_all(const float* __restrict__ Wp, const float* __restrict__ W1,
                           const float* __restrict__ W2, const float* __restrict__ Wl1,
                           __nv_bfloat16* hi) {
    int idx = blockIdx.x * blockDim.x + threadIdx.x;
    if (idx >= 81920) return;
    const float* W; int K, base;
    if (idx < 32768)       { W = Wp;  K = 256; base = 0; }
    else if (idx < 49152)  { W = W1;  K = 128; base = 32768; }
    else if (idx < 65536)  { W = W2;  K = 128; base = 49152; }
    else                   { W = Wl1; K = 128; base = 65536; }
    int loc = idx - base;
    int n = loc / K, k = loc % K;
    hi[idx] = __float2bfloat16(W[(size_t)k * 128 + n]);
}

// ================= HMMA GEMM cores =================
#define KP 72
#define A_BUF (64 * KP * 2)
#define B_BUF (128 * KP * 2)
#define OFF_AH 0
#define OFF_AL (2 * A_BUF)
#define OFF_BH (4 * A_BUF)
#define GEMM_SMEM_F32 (4 * A_BUF + 2 * B_BUF)   // 73728
#define OFF_A2 0
#define OFF_B2 (2 * A_BUF)
#define GEMM_SMEM_B16 (2 * A_BUF + 2 * B_BUF)   // 55296

// ---- mainloop, fp32 A with hi/lo split (2 MMAs) ----
template <int K>
__device__ __forceinline__ void gemm_mainloop_f32(
    char* sm, const float* __restrict__ A, const __nv_bfloat16* __restrict__ Whi,
    int M, int row0, int tid, int wm, int wn, int lane, float acc[2][4][4])
{
    constexpr int CHUNKS = K / 64;
    const int ar = tid >> 2;
    const int ac = (tid & 3) * 16;
    const int gr = row0 + ar;
    const bool aok = gr < M;
    const float4* arow = (const float4*)(A + (size_t)gr * K + ac);
    const int br = tid >> 1;
    const int bc = (tid & 1) * 32;
    const __nv_bfloat16* bh_row = Whi + (size_t)br * K + bc;

    float4 areg[4];
    const float4 z4 = make_float4(0.f, 0.f, 0.f, 0.f);

    {
        __nv_bfloat16* dbh = (__nv_bfloat16*)(sm + OFF_BH) + br * KP + bc;
#pragma unroll
        for (int j = 0; j < 4; j++) cp16(dbh + j * 8, bh_row + j * 8);
        CP_COMMIT();
#pragma unroll
        for (int j = 0; j < 4; j++) areg[j] = aok ? arow[j] : z4;
        __nv_bfloat16* dah = (__nv_bfloat16*)(sm + OFF_AH) + ar * KP + ac;
        __nv_bfloat16* dal = (__nv_bfloat16*)(sm + OFF_AL) + ar * KP + ac;
#pragma unroll
        for (int j = 0; j < 2; j++) {
            uint4 uh, ul;
            split8(areg[2*j], areg[2*j+1], uh, ul);
            *(uint4*)(dah + j * 8) = uh;
            *(uint4*)(dal + j * 8) = ul;
        }
        CP_WAIT0();
    }
    __syncthreads();

#pragma unroll
    for (int c = 0; c < CHUNKS; c++) {
        const int buf = c & 1;
        const int nbuf = buf ^ 1;
        const bool more = (c + 1) < CHUNKS;

        if (more) {
            int kn = (c + 1) * 64;
            __nv_bfloat16* dbh = (__nv_bfloat16*)(sm + OFF_BH + nbuf * B_BUF) + br * KP + bc;
#pragma unroll
            for (int j = 0; j < 4; j++) cp16(dbh + j * 8, bh_row + kn + j * 8);
            CP_COMMIT();
#pragma unroll
            for (int j = 0; j < 4; j++) areg[j] = aok ? arow[kn / 4 + j] : z4;
        }

        const __nv_bfloat16* Ah = (const __nv_bfloat16*)(sm + OFF_AH + buf * A_BUF);
        const __nv_bfloat16* Al = (const __nv_bfloat16*)(sm + OFF_AL + buf * A_BUF);
        const __nv_bfloat16* Bh = (const __nv_bfloat16*)(sm + OFF_BH + buf * B_BUF);
#pragma unroll
        for (int ks = 0; ks < 64; ks += 16) {
            uint32_t ah[2][4], al[2][4], bhf[4][2];
#pragma unroll
            for (int mt = 0; mt < 2; mt++) {
                int r = wm * 32 + mt * 16 + (lane & 15);
                int cc = ks + ((lane >> 4) << 3);
                ldsm4(ah[mt], Ah + r * KP + cc);
                ldsm4(al[mt], Al + r * KP + cc);
            }
#pragma unroll
            for (int nt = 0; nt < 4; nt++) {
                int n = wn * 32 + nt * 8 + (lane & 7);
                int cc = ks + ((lane >> 3) & 1) * 8;
                ldsm2(bhf[nt], Bh + n * KP + cc);
            }
#pragma unroll
            for (int mt = 0; mt < 2; mt++)
#pragma unroll
                for (int nt = 0; nt < 4; nt++) {
                    mma16816(acc[mt][nt], ah[mt], bhf[nt]);
                    mma16816(acc[mt][nt], al[mt], bhf[nt]);
                }
        }

        if (more) {
            __nv_bfloat16* dah = (__nv_bfloat16*)(sm + OFF_AH + nbuf * A_BUF) + ar * KP + ac;
            __nv_bfloat16* dal = (__nv_bfloat16*)(sm + OFF_AL + nbuf * A_BUF) + ar * KP + ac;
#pragma unroll
            for (int j = 0; j < 2; j++) {
                uint4 uh, ul;
                split8(areg[2*j], areg[2*j+1], uh, ul);
                *(uint4*)(dah + j * 8) = uh;
                *(uint4*)(dal + j * 8) = ul;
            }
            CP_WAIT0();
            __syncthreads();
        }
    }
}

// ---- mainloop, bf16 A (1 MMA), both operands via cp.async ----
template <int K>
__device__ __forceinline__ void gemm_mainloop_b16(
    char* sm, const __nv_bfloat16* __restrict__ A, const __nv_bfloat16* __restrict__ Whi,
    int M, int row0, int tid, int wm, int wn, int lane, float acc[2][4][4])
{
    constexpr int CHUNKS = K / 64;
    const int ar = tid >> 2;
    const int ac = (tid & 3) * 16;
    const int gr = row0 + ar;
    const bool aok = gr < M;
    const __nv_bfloat16* arow = A + (size_t)(aok ? gr : 0) * K + ac;
    const int br = tid >> 1;
    const int bc = (tid & 1) * 32;
    const __nv_bfloat16* bh_row = Whi + (size_t)br * K + bc;

#pragma unroll
    for (int c = 0; c < CHUNKS; c++) {
        const int buf = c & 1;
        {
            int kn = c * 64;
            __nv_bfloat16* da = (__nv_bfloat16*)(sm + OFF_A2 + buf * A_BUF) + ar * KP + ac;
            __nv_bfloat16* db = (__nv_bfloat16*)(sm + OFF_B2 + buf * B_BUF) + br * KP + bc;
            cp16z(da,     arow + kn,     aok);
            cp16z(da + 8, arow + kn + 8, aok);
#pragma unroll
            for (int j = 0; j < 4; j++) cp16(db + j * 8, bh_row + kn + j * 8);
            CP_COMMIT();
        }
        CP_WAIT0(); __syncthreads();

        const __nv_bfloat16* Ah = (const __nv_bfloat16*)(sm + OFF_A2 + buf * A_BUF);
        const __nv_bfloat16* Bh = (const __nv_bfloat16*)(sm + OFF_B2 + buf * B_BUF);
#pragma unroll
        for (int ks = 0; ks < 64; ks += 16) {
            uint32_t ah[2][4], bhf[4][2];
#pragma unroll
            for (int mt = 0; mt < 2; mt++) {
                int r = wm * 32 + mt * 16 + (lane & 15);
                int cc = ks + ((lane >> 4) << 3);
                ldsm4(ah[mt], Ah + r * KP + cc);
            }
#pragma unroll
            for (int nt = 0; nt < 4; nt++) {
                int n = wn * 32 + nt * 8 + (lane & 7);
                int cc = ks + ((lane >> 3) & 1) * 8;
                ldsm2(bhf[nt], Bh + n * KP + cc);
            }
#pragma unroll
            for (int mt = 0; mt < 2; mt++)
#pragma unroll
                for (int nt = 0; nt < 4; nt++)
                    mma16816(acc[mt][nt], ah[mt], bhf[nt]);
        }
        if (c + 1 < CHUNKS) __syncthreads();
    }
}

// GEMM1: fp32 A, bf16 out = relu(acc + bias)
__global__ __launch_bounds__(256) void k_gemm1(
    const float* __restrict__ A, const __nv_bfloat16* __restrict__ Whi,
    const float* __restrict__ bias, __nv_bfloat16* __restrict__ out, int M)
{
    extern __shared__ char sm[];
    const int tid  = threadIdx.x;
    const int wid  = tid >> 5;
    const int lane = tid & 31;
    const int wm   = wid & 1;
    const int wn   = wid >> 1;
    const int row0 = blockIdx.x * 64;

    float acc[2][4][4];
#pragma unroll
    for (int mt = 0; mt < 2; mt++)
#pragma unroll
        for (int nt = 0; nt < 4; nt++)
#pragma unroll
            for (int j = 0; j < 4; j++) acc[mt][nt][j] = 0.0f;

    gemm_mainloop_f32<256>(sm, A, Whi, M, row0, tid, wm, wn, lane, acc);

#pragma unroll
    for (int mt = 0; mt < 2; mt++) {
        int r1 = row0 + wm * 32 + mt * 16 + (lane >> 2);
        int r2 = r1 + 8;
#pragma unroll
        for (int nt = 0; nt < 4; nt++) {
            int c = wn * 32 + nt * 8 + (lane & 3) * 2;
            float b0 = __ldg(bias + c), b1 = __ldg(bias + c + 1);
            uint32_t p1 = pack_bf16(__float2bfloat16(fmaxf(acc[mt][nt][0] + b0, 0.f)),
                                    __float2bfloat16(fmaxf(acc[mt][nt][1] + b1, 0.f)));
            uint32_t p2 = pack_bf16(__float2bfloat16(fmaxf(acc[mt][nt][2] + b0, 0.f)),
                                    __float2bfloat16(fmaxf(acc[mt][nt][3] + b1, 0.f)));
            if (r1 < M) *(uint32_t*)&out[(size_t)r1 * 128 + c] = p1;
            if (r2 < M) *(uint32_t*)&out[(size_t)r2 * 128 + c] = p2;
        }
    }
}

// Conv GEMM: bf16 A, bf16 out = acc (raw)
__global__ __launch_bounds__(256) void k_gemm_b16(
    const __nv_bfloat16* __restrict__ A, const __nv_bfloat16* __restrict__ Whi,
    __nv_bfloat16* __restrict__ out, int M)
{
    extern __shared__ char sm[];
    const int tid  = threadIdx.x;
    const int wid  = tid >> 5;
    const int lane = tid & 31;
    const int wm   = wid & 1;
    const int wn   = wid >> 1;
    const int row0 = blockIdx.x * 64;

    float acc[2][4][4];
#pragma unroll
    for (int mt = 0; mt < 2; mt++)
#pragma unroll
        for (int nt = 0; nt < 4; nt++)
#pragma unroll
            for (int j = 0; j < 4; j++) acc[mt][nt][j] = 0.0f;

    gemm_mainloop_b16<128>(sm, A, Whi, M, row0, tid, wm, wn, lane, acc);

#pragma unroll
    for (int mt = 0; mt < 2; mt++) {
        int r1 = row0 + wm * 32 + mt * 16 + (lane >> 2);
        int r2 = r1 + 8;
#pragma unroll
        for (int nt = 0; nt < 4; nt++) {
            int c = wn * 32 + nt * 8 + (lane & 3) * 2;
            uint32_t p1 = pack_bf16(__float2bfloat16(acc[mt][nt][0]),
                                    __float2bfloat16(acc[mt][nt][1]));
            uint32_t p2 = pack_bf16(__float2bfloat16(acc[mt][nt][2]),
                                    __float2bfloat16(acc[mt][nt][3]));
            if (r1 < M) *(uint32_t*)&out[(size_t)r1 * 128 + c] = p1;
            if (r2 < M) *(uint32_t*)&out[(size_t)r2 * 128 + c] = p2;
        }
    }
}

// Fused final: bf16 A; hmid = relu(acc+bl1) in smem; logits = hmid@Wl2+bl2; softmax.
__global__ __launch_bounds__(256) void k_gemm_last(
    const __nv_bfloat16* __restrict__ A, const __nv_bfloat16* __restrict__ Whi,
    const float* __restrict__ bl1, const float* __restrict__ Wl2,
    const float* __restrict__ bl2, float* __restrict__ out, int M)
{
    extern __shared__ char sm[];
    const int tid  = threadIdx.x;
    const int wid  = tid >> 5;
    const int lane = tid & 31;
    const int wm   = wid & 1;
    const int wn   = wid >> 1;
    const int row0 = blockIdx.x * 64;

    float acc[2][4][4];
#pragma unroll
    for (int mt = 0; mt < 2; mt++)
#pragma unroll
        for (int nt = 0; nt < 4; nt++)
#pragma unroll
            for (int j = 0; j < 4; j++) acc[mt][nt][j] = 0.0f;

    gemm_mainloop_b16<128>(sm, A, Whi, M, row0, tid, wm, wn, lane, acc);

    __syncthreads();
    float* hs  = (float*)sm;             // 64 x 128 fp32 = 32768 B
    float* w2s = (float*)(sm + 32768);   // 128 x 32 fp32 = 16384 B

#pragma unroll
    for (int mt = 0; mt < 2; mt++) {
        int lr1 = wm * 32 + mt * 16 + (lane >> 2);
        int lr2 = lr1 + 8;
#pragma unroll
        for (int nt = 0; nt < 4; nt++) {
            int c = wn * 32 + nt * 8 + (lane & 3) * 2;
            float b0 = __ldg(bl1 + c), b1 = __ldg(bl1 + c + 1);
            float2 v1 = make_float2(fmaxf(acc[mt][nt][0] + b0, 0.f),
                                    fmaxf(acc[mt][nt][1] + b1, 0.f));
            float2 v2 = make_float2(fmaxf(acc[mt][nt][2] + b0, 0.f),
                                    fmaxf(acc[mt][nt][3] + b1, 0.f));
            *(float2*)&hs[lr1 * 128 + c] = v1;
            *(float2*)&hs[lr2 * 128 + c] = v2;
        }
    }
    for (int i = tid; i < 4096; i += 256) w2s[i] = __ldg(Wl2 + i);
    __syncthreads();

    float bb = __ldg(bl2 + lane);
#pragma unroll 1
    for (int i = 0; i < 8; i++) {
        int r = row0 + wid * 8 + i;
        if (r >= M) break;
        const float* hr = hs + (wid * 8 + i) * 128;
        float a = bb;
#pragma unroll
        for (int k = 0; k < 128; k += 4) {
            float4 h4 = *(const float4*)(hr + k);
            a += h4.x * w2s[(k + 0) * 32 + lane];
            a += h4.y * w2s[(k + 1) * 32 + lane];
            a += h4.z * w2s[(k + 2) * 32 + lane];
            a += h4.w * w2s[(k + 3) * 32 + lane];
        }
        float m = a;
#pragma unroll
        for (int o = 16; o >= 1; o >>= 1) m = fmaxf(m, __shfl_xor_sync(0xFFFFFFFFu, m, o));
        float e = __expf(a - m);
        float s = e;
#pragma unroll
        for (int o = 16; o >= 1; o >>= 1) s += __shfl_xor_sync(0xFFFFFFFFu, s, o);
        out[(size_t)r * 32 + lane] = e / s;
    }
}

// ================= gather aggregation (bf16 t -> bf16 h): one warp per node =================
__global__ __launch_bounds__(256) void k_agg(
    const int* __restrict__ off, const int2* __restrict__ epack,
    const __nv_bfloat16* __restrict__ t, const float* __restrict__ dinv,
    const float* __restrict__ bias, __nv_bfloat16* __restrict__ out, int n)
{
    int w = (blockIdx.x * blockDim.x + threadIdx.x) >> 5;
    if (w >= n) return;
    int lane = threadIdx.x & 31;

    const uint2* tp = (const uint2*)t;
    int beg = __ldg(off + w);
    int end = __ldg(off + w + 1);

    float di = __ldg(dinv + w);
    float s = di * di;

    float4 acc;
    {
        uint2 raw = tp[(size_t)w * 32 + lane];
        float2 f01 = __bfloat1622float2(*reinterpret_cast<const __nv_bfloat162*>(&raw.x));
        float2 f23 = __bfloat1622float2(*reinterpret_cast<const __nv_bfloat162*>(&raw.y));
        acc = make_float4(s * f01.x, s * f01.y, s * f23.x, s * f23.y);
    }

    int e = beg;
    for (; e + 3 < end; e += 4) {
        int2 p0 = __ldg(epack + e);
        int2 p1 = __ldg(epack + e + 1);
        int2 p2 = __ldg(epack + e + 2);
        int2 p3 = __ldg(epack + e + 3);
        uint2 r0 = tp[(size_t)p0.x * 32 + lane];
        uint2 r1 = tp[(size_t)p1.x * 32 + lane];
        uint2 r2 = tp[(size_t)p2.x * 32 + lane];
        uint2 r3 = tp[(size_t)p3.x * 32 + lane];
        float c0 = __int_as_float(p0.y), c1 = __int_as_float(p1.y);
        float c2 = __int_as_float(p2.y), c3 = __int_as_float(p3.y);
        float2 a0 = __bfloat1622float2(*reinterpret_cast<const __nv_bfloat162*>(&r0.x));
        float2 b0 = __bfloat1622float2(*reinterpret_cast<const __nv_bfloat162*>(&r0.y));
        float2 a1 = __bfloat1622float2(*reinterpret_cast<const __nv_bfloat162*>(&r1.x));
        float2 b1 = __bfloat1622float2(*reinterpret_cast<const __nv_bfloat162*>(&r1.y));
        float2 a2 = __bfloat1622float2(*reinterpret_cast<const __nv_bfloat162*>(&r2.x));
        float2 b2 = __bfloat1622float2(*reinterpret_cast<const __nv_bfloat162*>(&r2.y));
        float2 a3 = __bfloat1622float2(*reinterpret_cast<const __nv_bfloat162*>(&r3.x));
        float2 b3 = __bfloat1622float2(*reinterpret_cast<const __nv_bfloat162*>(&r3.y));
        acc.x += c0 * a0.x + c1 * a1.x + c2 * a2.x + c3 * a3.x;
        acc.y += c0 * a0.y + c1 * a1.y + c2 * a2.y + c3 * a3.y;
        acc.z += c0 * b0.x + c1 * b1.x + c2 * b2.x + c3 * b3.x;
        acc.w += c0 * b0.y + c1 * b1.y + c2 * b2.y + c3 * b3.y;
    }
    for (; e < end; e++) {
        int2 p0 = __ldg(epack + e);
        float c0 = __int_as_float(p0.y);
        uint2 r0 = tp[(size_t)p0.x * 32 + lane];
        float2 a0 = __bfloat1622float2(*reinterpret_cast<const __nv_bfloat162*>(&r0.x));
        float2 b0 = __bfloat1622float2(*reinterpret_cast<const __nv_bfloat162*>(&r0.y));
        acc.x += c0 * a0.x;
        acc.y += c0 * a0.y;
        acc.z += c0 * b0.x;
        acc.w += c0 * b0.y;
    }

    float4 bv = *(const float4*)&bias[lane * 4];
    uint2 o;
    o.x = pack_bf16(__float2bfloat16(fmaxf(acc.x + bv.x, 0.f)),
                    __float2bfloat16(fmaxf(acc.y + bv.y, 0.f)));
    o.y = pack_bf16(__float2bfloat16(fmaxf(acc.z + bv.z, 0.f)),
                    __float2bfloat16(fmaxf(acc.w + bv.w, 0.f)));
    ((uint2*)out)[(size_t)w * 32 + lane] = o;
}

// ================= launch =================
extern "C" void kernel_launch(void* const* d_in, const int* in_sizes, int n_in,
                              void* d_out, int out_size)
{
    const float* x   = (const float*)d_in[0];
    const int*   ei  = (const int*)d_in[1];
    const float* ew  = (const float*)d_in[2];
    const float* Wp  = (const float*)d_in[3];
    const float* bp  = (const float*)d_in[4];
    const float* W1  = (const float*)d_in[5];
    const float* b1  = (const float*)d_in[6];
    const float* W2  = (const float*)d_in[7];
    const float* b2  = (const float*)d_in[8];
    const float* Wl1 = (const float*)d_in[9];
    const float* bl1 = (const float*)d_in[10];
    const float* Wl2 = (const float*)d_in[11];
    const float* bl2 = (const float*)d_in[12];
    float* out = (float*)d_out;

    const int M = in_sizes[0] / 256;   // 100000
    const int E = in_sizes[1] / 2;     // 1600000
    const int* src = ei;
    const int* dst = ei + E;

    float *p_dinv;
    __nv_bfloat16 *p_h, *p_t, *p_whi;
    unsigned long long* p_degcnt;
    int *p_cnt, *p_off, *p_cur, *p_part;
    int2 *p_epack;
    cudaGetSymbolAddress((void**)&p_h, g_h);
    cudaGetSymbolAddress((void**)&p_t, g_t);
    cudaGetSymbolAddress((void**)&p_degcnt, g_degcnt);
    cudaGetSymbolAddress((void**)&p_dinv, g_dinv);
    cudaGetSymbolAddress((void**)&p_cnt, g_cnt);
    cudaGetSymbolAddress((void**)&p_off, g_off);
    cudaGetSymbolAddress((void**)&p_cur, g_cur);
    cudaGetSymbolAddress((void**)&p_epack, g_epack);
    cudaGetSymbolAddress((void**)&p_part, g_part);
    cudaGetSymbolAddress((void**)&p_whi, g_whi);

    cudaFuncSetAttribute(k_gemm1,     cudaFuncAttributeMaxDynamicSharedMemorySize, GEMM_SMEM_F32);
    cudaFuncSetAttribute(k_gemm_b16,  cudaFuncAttributeMaxDynamicSharedMemorySize, GEMM_SMEM_B16);
    cudaFuncSetAttribute(k_gemm_last, cudaFuncAttributeMaxDynamicSharedMemorySize, GEMM_SMEM_B16);

    // second stream + fork/join events, created once on the first (uncaptured) call
    static cudaStream_t s2 = nullptr;
    static cudaEvent_t evF = nullptr, evJ = nullptr;
    if (s2 == nullptr) {
        cudaStreamCreateWithFlags(&s2, cudaStreamNonBlocking);
        cudaEventCreateWithFlags(&evF, cudaEventDisableTiming);
        cudaEventCreateWithFlags(&evJ, cudaEventDisableTiming);
    }

    const int gemm_blocks = (M + 63) / 64;
    const int agg_blocks  = (M + 7) / 8;
    const int scan_blocks = (M + SCAN_CHUNK - 1) / SCAN_CHUNK;

    // ---- fork: CSR branch on s2 ----
    cudaEventRecord(evF, 0);
    cudaStreamWaitEvent(s2, evF, 0);

    cudaMemsetAsync(p_degcnt, 0, (size_t)NN * sizeof(unsigned long long), s2);
    k_edge_deg<<<(E + 255) / 256, 256, 0, s2>>>(dst, ew, p_degcnt, E);
    k_dinv<<<(M + 255) / 256, 256, 0, s2>>>(p_degcnt, p_dinv, p_cnt, M);
    k_scan1<<<scan_blocks, SCAN_CHUNK, 0, s2>>>(p_cnt, p_part, M);
    k_scan2<<<1, 512, 0, s2>>>(p_part, scan_blocks);
    k_scan3<<<scan_blocks, SCAN_CHUNK, 0, s2>>>(p_cnt, p_part, p_off, p_cur, M, E);
    k_scatter<<<(E + 255) / 256, 256, 0, s2>>>(src, dst, ew, p_dinv, p_cur, p_epack, E);
    cudaEventRecord(evJ, s2);

    // ---- main branch on default stream: prep + gemm1 + conv1 GEMM ----
    k_prep_all<<<(81920 + 255) / 256, 256>>>(Wp, W1, W2, Wl1, p_whi);
    k_gemm1<<<gemm_blocks, 256, GEMM_SMEM_F32>>>(x, p_whi, bp, p_h, M);
    k_gemm_b16<<<gemm_blocks, 256, GEMM_SMEM_B16>>>(p_h, p_whi + 32768, p_t, M);

    // ---- join: agg needs CSR ----
    cudaStreamWaitEvent(0, evJ, 0);

    k_agg<<<agg_blocks, 256>>>(p_off, p_epack, p_t, p_dinv, b1, p_h, M);

    // conv2
    k_gemm_b16<<<gemm_blocks, 256, GEMM_SMEM_B16>>>(p_h, p_whi + 49152, p_t, M);
    k_agg<<<agg_blocks, 256>>>(p_off, p_epack, p_t, p_dinv, b2, p_h, M);

    // fused: softmax(relu(h @ Wl1 + bl1) @ Wl2 + bl2)
    k_gemm_last<<<gemm_blocks, 256, GEMM_SMEM_B16>>>(p_h, p_whi + 65536, bl1, Wl2, bl2, out, M);
}

// round 15
// speedup vs baseline: 1.7109x; 1.0594x over previous
#include <cuda_runtime.h>
#include <cuda_bf16.h>
#include <math.h>
#include <stdint.h>

#define NN 100000
#define EE 1600000
#define SCAN_CHUNK 256

// Scratch (no device allocation allowed)
__device__ __nv_bfloat16 g_h[(size_t)NN * 128];   // activations, bf16
__device__ __nv_bfloat16 g_t[(size_t)NN * 128];   // conv GEMM output, bf16
__device__ unsigned long long g_degcnt[NN];
__device__ float g_dinv[NN];
__device__ int   g_cnt[NN];
__device__ int   g_off[NN + 1];
__device__ int   g_cur[NN];
__device__ int2  g_epack[EE];     // {src, coef-as-int}
__device__ int   g_part[512];
// transposed bf16 weights: Wp^T @0 (128x256), W1^T @32768, W2^T @49152, Wl1^T @65536
__device__ __nv_bfloat16 g_whi[81920];

// ================= mma.sync / cp.async helpers (baseline PTX, sm_80+) =================
__device__ __forceinline__ void ldsm4(uint32_t d[4], const void* p) {
    uint32_t a = (uint32_t)__cvta_generic_to_shared(p);
    asm volatile("ldmatrix.sync.aligned.m8n8.x4.shared.b16 {%0,%1,%2,%3}, [%4];"
        : "=r"(d[0]), "=r"(d[1]), "=r"(d[2]), "=r"(d[3]) : "r"(a));
}
__device__ __forceinline__ void ldsm2(uint32_t d[2], const void* p) {
    uint32_t a = (uint32_t)__cvta_generic_to_shared(p);
    asm volatile("ldmatrix.sync.aligned.m8n8.x2.shared.b16 {%0,%1}, [%2];"
        : "=r"(d[0]), "=r"(d[1]) : "r"(a));
}
__device__ __forceinline__ void mma16816(float c[4], const uint32_t a[4], const uint32_t b[2]) {
    asm volatile("mma.sync.aligned.m16n8k16.row.col.f32.bf16.bf16.f32 "
        "{%0,%1,%2,%3}, {%4,%5,%6,%7}, {%8,%9}, {%0,%1,%2,%3};"
        : "+f"(c[0]), "+f"(c[1]), "+f"(c[2]), "+f"(c[3])
        : "r"(a[0]), "r"(a[1]), "r"(a[2]), "r"(a[3]), "r"(b[0]), "r"(b[1]));
}
__device__ __forceinline__ uint32_t pack_bf16(__nv_bfloat16 a, __nv_bfloat16 b) {
    return (uint32_t)__bfloat16_as_ushort(a) | ((uint32_t)__bfloat16_as_ushort(b) << 16);
}
__device__ __forceinline__ void split8(const float4& v0, const float4& v1,
                                       uint4& uh, uint4& ul) {
    float f[8] = {v0.x, v0.y, v0.z, v0.w, v1.x, v1.y, v1.z, v1.w};
    uint32_t h[4], l[4];
#pragma unroll
    for (int j = 0; j < 4; j++) {
        __nv_bfloat16 h0 = __float2bfloat16(f[2*j]);
        __nv_bfloat16 h1 = __float2bfloat16(f[2*j+1]);
        __nv_bfloat16 l0 = __float2bfloat16(f[2*j]   - __bfloat162float(h0));
        __nv_bfloat16 l1 = __float2bfloat16(f[2*j+1] - __bfloat162float(h1));
        h[j] = pack_bf16(h0, h1);
        l[j] = pack_bf16(l0, l1);
    }
    uh = make_uint4(h[0], h[1], h[2], h[3]);
    ul = make_uint4(l[0], l[1], l[2], l[3]);
}
__device__ __forceinline__ void cp16(void* dst_smem, const void* src) {
    uint32_t d = (uint32_t)__cvta_generic_to_shared(dst_smem);
    asm volatile("cp.async.cg.shared.global [%0], [%1], 16;" :: "r"(d), "l"(src) : "memory");
}
__device__ __forceinline__ void cp16z(void* dst_smem, const void* src, bool pred) {
    uint32_t d = (uint32_t)__cvta_generic_to_shared(dst_smem);
    int sz = pred ? 16 : 0;
    asm volatile("cp.async.cg.shared.global [%0], [%1], 16, %2;"
                 :: "r"(d), "l"(src), "r"(sz) : "memory");
}
#define CP_COMMIT() asm volatile("cp.async.commit_group;" ::: "memory")
#define CP_WAIT0()  asm volatile("cp.async.wait_group 0;" ::: "memory")

// ================= CSR build =================
__global__ void k_edge_deg(const int* __restrict__ dst, const float* __restrict__ ew,
                           unsigned long long* degcnt, int E) {
    int e = blockIdx.x * blockDim.x + threadIdx.x;
    if (e < E) {
        unsigned long long v = (1ull << 40)
            + (unsigned long long)((double)ew[e] * 16777216.0);
        atomicAdd(&degcnt[dst[e]], v);
    }
}
// dinv + cnt + per-block partial sums (merged k_dinv + k_scan1)
__global__ __launch_bounds__(SCAN_CHUNK) void k_dinv_scan1(
    const unsigned long long* __restrict__ degcnt,
    float* dinv, int* cnt, int* part, int n) {
    __shared__ int ws[8];
    int i = blockIdx.x * SCAN_CHUNK + threadIdx.x;
    int c = 0;
    if (i < n) {
        unsigned long long v = degcnt[i];
        c = (int)(v >> 40);
        cnt[i] = c;
        float deg = 1.0f + (float)((double)(v & ((1ull << 40) - 1)) * (1.0 / 16777216.0));
        dinv[i] = rsqrtf(deg);
    }
    int s = c;
#pragma unroll
    for (int o = 16; o >= 1; o >>= 1) s += __shfl_xor_sync(0xFFFFFFFFu, s, o);
    if ((threadIdx.x & 31) == 0) ws[threadIdx.x >> 5] = s;
    __syncthreads();
    if (threadIdx.x == 0) {
        int t = 0;
#pragma unroll
        for (int w = 0; w < 8; w++) t += ws[w];
        part[blockIdx.x] = t;
    }
}
__global__ __launch_bounds__(512) void k_scan2(int* part, int nb) {
    __shared__ int s[512];
    int tid = threadIdx.x;
    int v = (tid < nb) ? part[tid] : 0;
    s[tid] = v;
    __syncthreads();
#pragma unroll
    for (int d = 1; d < 512; d <<= 1) {
        int add = (tid >= d) ? s[tid - d] : 0;
        __syncthreads();
        s[tid] += add;
        __syncthreads();
    }
    if (tid < nb) part[tid] = s[tid] - v;
}
__global__ __launch_bounds__(SCAN_CHUNK) void k_scan3(const int* __restrict__ cnt,
                                                      const int* __restrict__ part,
                                                      int* off, int* cur, int n, int E) {
    __shared__ int ws[8];
    int tid = threadIdx.x;
    int i = blockIdx.x * SCAN_CHUNK + tid;
    int lane = tid & 31;
    int warp = tid >> 5;
    int v = (i < n) ? cnt[i] : 0;
    int x = v;
#pragma unroll
    for (int o = 1; o < 32; o <<= 1) {
        int y = __shfl_up_sync(0xFFFFFFFFu, x, o);
        if (lane >= o) x += y;
    }
    if (lane == 31) ws[warp] = x;
    __syncthreads();
    if (warp == 0 && lane < 8) {
        int y = ws[lane];
        int z = y;
#pragma unroll
        for (int o = 1; o < 8; o <<= 1) {
            int u = __shfl_up_sync(0xFFu, z, o);
            if (lane >= o) z += u;
        }
        ws[lane] = z - y;
    }
    __syncthreads();
    if (i < n) {
        int excl = part[blockIdx.x] + ws[warp] + x - v;
        off[i] = excl;
        cur[i] = excl;
    }
    if (i == n - 1) off[n] = E;
}
__global__ void k_scatter(const int* __restrict__ src, const int* __restrict__ dst,
                          const float* __restrict__ ew, const float* __restrict__ dinv,
                          int* cur, int2* epack, int E) {
    int e = blockIdx.x * blockDim.x + threadIdx.x;
    if (e >= E) return;
    int s = src[e];
    int d = dst[e];
    float c = __ldg(dinv + s) * ew[e] * __ldg(dinv + d);
    int pos = atomicAdd(&cur[d], 1);
    epack[pos] = make_int2(s, __float_as_int(c));
}

// ================= all-weights transpose to bf16 (one launch) =================
__global__ void k_prep_all(const float* __restrict__ Wp, const float* __restrict__ W1,
                           const float* __restrict__ W2, const float* __restrict__ Wl1,
                           __nv_bfloat16* hi) {
    int idx = blockIdx.x * blockDim.x + threadIdx.x;
    if (idx >= 81920) return;
    const float* W; int K, base;
    if (idx < 32768)       { W = Wp;  K = 256; base = 0; }
    else if (idx < 49152)  { W = W1;  K = 128; base = 32768; }
    else if (idx < 65536)  { W = W2;  K = 128; base = 49152; }
    else                   { W = Wl1; K = 128; base = 65536; }
    int loc = idx - base;
    int n = loc / K, k = loc % K;
    hi[idx] = __float2bfloat16(W[(size_t)k * 128 + n]);
}

// ================= HMMA GEMM cores =================
#define KP 72
#define A_BUF (64 * KP * 2)
#define B_BUF (128 * KP * 2)
#define OFF_AH 0
#define OFF_AL (2 * A_BUF)
#define OFF_BH (4 * A_BUF)
#define GEMM_SMEM_F32 (4 * A_BUF + 2 * B_BUF)   // 73728
#define OFF_A2 0
#define OFF_B2 (2 * A_BUF)
#define GEMM_SMEM_B16 (2 * A_BUF + 2 * B_BUF)   // 55296

template <int K>
__device__ __forceinline__ void gemm_mainloop_f32(
    char* sm, const float* __restrict__ A, const __nv_bfloat16* __restrict__ Whi,
    int M, int row0, int tid, int wm, int wn, int lane, float acc[2][4][4])
{
    constexpr int CHUNKS = K / 64;
    const int ar = tid >> 2;
    const int ac = (tid & 3) * 16;
    const int gr = row0 + ar;
    const bool aok = gr < M;
    const float4* arow = (const float4*)(A + (size_t)gr * K + ac);
    const int br = tid >> 1;
    const int bc = (tid & 1) * 32;
    const __nv_bfloat16* bh_row = Whi + (size_t)br * K + bc;

    float4 areg[4];
    const float4 z4 = make_float4(0.f, 0.f, 0.f, 0.f);

    {
        __nv_bfloat16* dbh = (__nv_bfloat16*)(sm + OFF_BH) + br * KP + bc;
#pragma unroll
        for (int j = 0; j < 4; j++) cp16(dbh + j * 8, bh_row + j * 8);
        CP_COMMIT();
#pragma unroll
        for (int j = 0; j < 4; j++) areg[j] = aok ? arow[j] : z4;
        __nv_bfloat16* dah = (__nv_bfloat16*)(sm + OFF_AH) + ar * KP + ac;
        __nv_bfloat16* dal = (__nv_bfloat16*)(sm + OFF_AL) + ar * KP + ac;
#pragma unroll
        for (int j = 0; j < 2; j++) {
            uint4 uh, ul;
            split8(areg[2*j], areg[2*j+1], uh, ul);
            *(uint4*)(dah + j * 8) = uh;
            *(uint4*)(dal + j * 8) = ul;
        }
        CP_WAIT0();
    }
    __syncthreads();

#pragma unroll
    for (int c = 0; c < CHUNKS; c++) {
        const int buf = c & 1;
        const int nbuf = buf ^ 1;
        const bool more = (c + 1) < CHUNKS;

        if (more) {
            int kn = (c + 1) * 64;
            __nv_bfloat16* dbh = (__nv_bfloat16*)(sm + OFF_BH + nbuf * B_BUF) + br * KP + bc;
#pragma unroll
            for (int j = 0; j < 4; j++) cp16(dbh + j * 8, bh_row + kn + j * 8);
            CP_COMMIT();
#pragma unroll
            for (int j = 0; j < 4; j++) areg[j] = aok ? arow[kn / 4 + j] : z4;
        }

        const __nv_bfloat16* Ah = (const __nv_bfloat16*)(sm + OFF_AH + buf * A_BUF);
        const __nv_bfloat16* Al = (const __nv_bfloat16*)(sm + OFF_AL + buf * A_BUF);
        const __nv_bfloat16* Bh = (const __nv_bfloat16*)(sm + OFF_BH + buf * B_BUF);
#pragma unroll
        for (int ks = 0; ks < 64; ks += 16) {
            uint32_t ah[2][4], al[2][4], bhf[4][2];
#pragma unroll
            for (int mt = 0; mt < 2; mt++) {
                int r = wm * 32 + mt * 16 + (lane & 15);
                int cc = ks + ((lane >> 4) << 3);
                ldsm4(ah[mt], Ah + r * KP + cc);
                ldsm4(al[mt], Al + r * KP + cc);
            }
#pragma unroll
            for (int nt = 0; nt < 4; nt++) {
                int n = wn * 32 + nt * 8 + (lane & 7);
                int cc = ks + ((lane >> 3) & 1) * 8;
                ldsm2(bhf[nt], Bh + n * KP + cc);
            }
#pragma unroll
            for (int mt = 0; mt < 2; mt++)
#pragma unroll
                for (int nt = 0; nt < 4; nt++) {
                    mma16816(acc[mt][nt], ah[mt], bhf[nt]);
                    mma16816(acc[mt][nt], al[mt], bhf[nt]);
                }
        }

        if (more) {
            __nv_bfloat16* dah = (__nv_bfloat16*)(sm + OFF_AH + nbuf * A_BUF) + ar * KP + ac;
            __nv_bfloat16* dal = (__nv_bfloat16*)(sm + OFF_AL + nbuf * A_BUF) + ar * KP + ac;
#pragma unroll
            for (int j = 0; j < 2; j++) {
                uint4 uh, ul;
                split8(areg[2*j], areg[2*j+1], uh, ul);
                *(uint4*)(dah + j * 8) = uh;
                *(uint4*)(dal + j * 8) = ul;
            }
            CP_WAIT0();
            __syncthreads();
        }
    }
}

template <int K>
__device__ __forceinline__ void gemm_mainloop_b16(
    char* sm, const __nv_bfloat16* __restrict__ A, const __nv_bfloat16* __restrict__ Whi,
    int M, int row0, int tid, int wm, int wn, int lane, float acc[2][4][4])
{
    constexpr int CHUNKS = K / 64;
    const int ar = tid >> 2;
    const int ac = (tid & 3) * 16;
    const int gr = row0 + ar;
    const bool aok = gr < M;
    const __nv_bfloat16* arow = A + (size_t)(aok ? gr : 0) * K + ac;
    const int br = tid >> 1;
    const int bc = (tid & 1) * 32;
    const __nv_bfloat16* bh_row = Whi + (size_t)br * K + bc;

#pragma unroll
    for (int c = 0; c < CHUNKS; c++) {
        const int buf = c & 1;
        {
            int kn = c * 64;
            __nv_bfloat16* da = (__nv_bfloat16*)(sm + OFF_A2 + buf * A_BUF) + ar * KP + ac;
            __nv_bfloat16* db = (__nv_bfloat16*)(sm + OFF_B2 + buf * B_BUF) + br * KP + bc;
            cp16z(da,     arow + kn,     aok);
            cp16z(da + 8, arow + kn + 8, aok);
#pragma unroll
            for (int j = 0; j < 4; j++) cp16(db + j * 8, bh_row + kn + j * 8);
            CP_COMMIT();
        }
        CP_WAIT0(); __syncthreads();

        const __nv_bfloat16* Ah = (const __nv_bfloat16*)(sm + OFF_A2 + buf * A_BUF);
        const __nv_bfloat16* Bh = (const __nv_bfloat16*)(sm + OFF_B2 + buf * B_BUF);
#pragma unroll
        for (int ks = 0; ks < 64; ks += 16) {
            uint32_t ah[2][4], bhf[4][2];
#pragma unroll
            for (int mt = 0; mt < 2; mt++) {
                int r = wm * 32 + mt * 16 + (lane & 15);
                int cc = ks + ((lane >> 4) << 3);
                ldsm4(ah[mt], Ah + r * KP + cc);
            }
#pragma unroll
            for (int nt = 0; nt < 4; nt++) {
                int n = wn * 32 + nt * 8 + (lane & 7);
                int cc = ks + ((lane >> 3) & 1) * 8;
                ldsm2(bhf[nt], Bh + n * KP + cc);
            }
#pragma unroll
            for (int mt = 0; mt < 2; mt++)
#pragma unroll
                for (int nt = 0; nt < 4; nt++)
                    mma16816(acc[mt][nt], ah[mt], bhf[nt]);
        }
        if (c + 1 < CHUNKS) __syncthreads();
    }
}

// GEMM1: fp32 A, bf16 out = relu(acc + bias)
__global__ __launch_bounds__(256) void k_gemm1(
    const float* __restrict__ A, const __nv_bfloat16* __restrict__ Whi,
    const float* __restrict__ bias, __nv_bfloat16* __restrict__ out, int M)
{
    extern __shared__ char sm[];
    const int tid  = threadIdx.x;
    const int wid  = tid >> 5;
    const int lane = tid & 31;
    const int wm   = wid & 1;
    const int wn   = wid >> 1;
    const int row0 = blockIdx.x * 64;

    float acc[2][4][4];
#pragma unroll
    for (int mt = 0; mt < 2; mt++)
#pragma unroll
        for (int nt = 0; nt < 4; nt++)
#pragma unroll
            for (int j = 0; j < 4; j++) acc[mt][nt][j] = 0.0f;

    gemm_mainloop_f32<256>(sm, A, Whi, M, row0, tid, wm, wn, lane, acc);

#pragma unroll
    for (int mt = 0; mt < 2; mt++) {
        int r1 = row0 + wm * 32 + mt * 16 + (lane >> 2);
        int r2 = r1 + 8;
#pragma unroll
        for (int nt = 0; nt < 4; nt++) {
            int c = wn * 32 + nt * 8 + (lane & 3) * 2;
            float b0 = __ldg(bias + c), b1 = __ldg(bias + c + 1);
            uint32_t p1 = pack_bf16(__float2bfloat16(fmaxf(acc[mt][nt][0] + b0, 0.f)),
                                    __float2bfloat16(fmaxf(acc[mt][nt][1] + b1, 0.f)));
            uint32_t p2 = pack_bf16(__float2bfloat16(fmaxf(acc[mt][nt][2] + b0, 0.f)),
                                    __float2bfloat16(fmaxf(acc[mt][nt][3] + b1, 0.f)));
            if (r1 < M) *(uint32_t*)&out[(size_t)r1 * 128 + c] = p1;
            if (r2 < M) *(uint32_t*)&out[(size_t)r2 * 128 + c] = p2;
        }
    }
}

// Conv GEMM: bf16 A, bf16 out = acc (raw)
__global__ __launch_bounds__(256) void k_gemm_b16(
    const __nv_bfloat16* __restrict__ A, const __nv_bfloat16* __restrict__ Whi,
    __nv_bfloat16* __restrict__ out, int M)
{
    extern __shared__ char sm[];
    const int tid  = threadIdx.x;
    const int wid  = tid >> 5;
    const int lane = tid & 31;
    const int wm   = wid & 1;
    const int wn   = wid >> 1;
    const int row0 = blockIdx.x * 64;

    float acc[2][4][4];
#pragma unroll
    for (int mt = 0; mt < 2; mt++)
#pragma unroll
        for (int nt = 0; nt < 4; nt++)
#pragma unroll
            for (int j = 0; j < 4; j++) acc[mt][nt][j] = 0.0f;

    gemm_mainloop_b16<128>(sm, A, Whi, M, row0, tid, wm, wn, lane, acc);

#pragma unroll
    for (int mt = 0; mt < 2; mt++) {
        int r1 = row0 + wm * 32 + mt * 16 + (lane >> 2);
        int r2 = r1 + 8;
#pragma unroll
        for (int nt = 0; nt < 4; nt++) {
            int c = wn * 32 + nt * 8 + (lane & 3) * 2;
            uint32_t p1 = pack_bf16(__float2bfloat16(acc[mt][nt][0]),
                                    __float2bfloat16(acc[mt][nt][1]));
            uint32_t p2 = pack_bf16(__float2bfloat16(acc[mt][nt][2]),
                                    __float2bfloat16(acc[mt][nt][3]));
            if (r1 < M) *(uint32_t*)&out[(size_t)r1 * 128 + c] = p1;
            if (r2 < M) *(uint32_t*)&out[(size_t)r2 * 128 + c] = p2;
        }
    }
}

// Fused final: bf16 A; hmid = relu(acc+bl1) in smem; logits = hmid@Wl2+bl2; softmax.
__global__ __launch_bounds__(256) void k_gemm_last(
    const __nv_bfloat16* __restrict__ A, const __nv_bfloat16* __restrict__ Whi,
    const float* __restrict__ bl1, const float* __restrict__ Wl2,
    const float* __restrict__ bl2, float* __restrict__ out, int M)
{
    extern __shared__ char sm[];
    const int tid  = threadIdx.x;
    const int wid  = tid >> 5;
    const int lane = tid & 31;
    const int wm   = wid & 1;
    const int wn   = wid >> 1;
    const int row0 = blockIdx.x * 64;

    float acc[2][4][4];
#pragma unroll
    for (int mt = 0; mt < 2; mt++)
#pragma unroll
        for (int nt = 0; nt < 4; nt++)
#pragma unroll
            for (int j = 0; j < 4; j++) acc[mt][nt][j] = 0.0f;

    gemm_mainloop_b16<128>(sm, A, Whi, M, row0, tid, wm, wn, lane, acc);

    __syncthreads();
    float* hs  = (float*)sm;             // 64 x 128 fp32 = 32768 B
    float* w2s = (float*)(sm + 32768);   // 128 x 32 fp32 = 16384 B

#pragma unroll
    for (int mt = 0; mt < 2; mt++) {
        int lr1 = wm * 32 + mt * 16 + (lane >> 2);
        int lr2 = lr1 + 8;
#pragma unroll
        for (int nt = 0; nt < 4; nt++) {
            int c = wn * 32 + nt * 8 + (lane & 3) * 2;
            float b0 = __ldg(bl1 + c), b1 = __ldg(bl1 + c + 1);
            float2 v1 = make_float2(fmaxf(acc[mt][nt][0] + b0, 0.f),
                                    fmaxf(acc[mt][nt][1] + b1, 0.f));
            float2 v2 = make_float2(fmaxf(acc[mt][nt][2] + b0, 0.f),
                                    fmaxf(acc[mt][nt][3] + b1, 0.f));
            *(float2*)&hs[lr1 * 128 + c] = v1;
            *(float2*)&hs[lr2 * 128 + c] = v2;
        }
    }
    for (int i = tid; i < 4096; i += 256) w2s[i] = __ldg(Wl2 + i);
    __syncthreads();

    float bb = __ldg(bl2 + lane);
#pragma unroll 1
    for (int i = 0; i < 8; i++) {
        int r = row0 + wid * 8 + i;
        if (r >= M) break;
        const float* hr = hs + (wid * 8 + i) * 128;
        float a = bb;
#pragma unroll
        for (int k = 0; k < 128; k += 4) {
            float4 h4 = *(const float4*)(hr + k);
            a += h4.x * w2s[(k + 0) * 32 + lane];
            a += h4.y * w2s[(k + 1) * 32 + lane];
            a += h4.z * w2s[(k + 2) * 32 + lane];
            a += h4.w * w2s[(k + 3) * 32 + lane];
        }
        float m = a;
#pragma unroll
        for (int o = 16; o >= 1; o >>= 1) m = fmaxf(m, __shfl_xor_sync(0xFFFFFFFFu, m, o));
        float e = __expf(a - m);
        float s = e;
#pragma unroll
        for (int o = 16; o >= 1; o >>= 1) s += __shfl_xor_sync(0xFFFFFFFFu, s, o);
        out[(size_t)r * 32 + lane] = e / s;
    }
}

// ================= gather aggregation: half-warp per node, uint4 per lane =================
__global__ __launch_bounds__(256) void k_agg(
    const int* __restrict__ off, const int2* __restrict__ epack,
    const __nv_bfloat16* __restrict__ t, const float* __restrict__ dinv,
    const float* __restrict__ bias, __nv_bfloat16* __restrict__ out, int n)
{
    int warp = (blockIdx.x * blockDim.x + threadIdx.x) >> 5;
    int lane = threadIdx.x & 31;
    int half = lane >> 4;              // 0 or 1
    int hl   = lane & 15;              // lane within half
    int node = warp * 2 + half;
    if (node >= n) return;

    const uint4* tp = (const uint4*)t;   // 8 bf16 per lane; 16 uint4 per row
    int beg = __ldg(off + node);
    int end = __ldg(off + node + 1);

    float di = __ldg(dinv + node);
    float s = di * di;

    float acc[8];
    {
        uint4 raw = tp[(size_t)node * 16 + hl];
        float2 f0 = __bfloat1622float2(*reinterpret_cast<const __nv_bfloat162*>(&raw.x));
        float2 f1 = __bfloat1622float2(*reinterpret_cast<const __nv_bfloat162*>(&raw.y));
        float2 f2 = __bfloat1622float2(*reinterpret_cast<const __nv_bfloat162*>(&raw.z));
        float2 f3 = __bfloat1622float2(*reinterpret_cast<const __nv_bfloat162*>(&raw.w));
        acc[0] = s * f0.x; acc[1] = s * f0.y;
        acc[2] = s * f1.x; acc[3] = s * f1.y;
        acc[4] = s * f2.x; acc[5] = s * f2.y;
        acc[6] = s * f3.x; acc[7] = s * f3.y;
    }

    int e = beg;
    for (; e + 3 < end; e += 4) {
        int2 p0 = __ldg(epack + e);
        int2 p1 = __ldg(epack + e + 1);
        int2 p2 = __ldg(epack + e + 2);
        int2 p3 = __ldg(epack + e + 3);
        uint4 r0 = tp[(size_t)p0.x * 16 + hl];
        uint4 r1 = tp[(size_t)p1.x * 16 + hl];
        uint4 r2 = tp[(size_t)p2.x * 16 + hl];
        uint4 r3 = tp[(size_t)p3.x * 16 + hl];
        float c0 = __int_as_float(p0.y), c1 = __int_as_float(p1.y);
        float c2 = __int_as_float(p2.y), c3 = __int_as_float(p3.y);
        const uint32_t* rr[4] = {&r0.x, &r1.x, &r2.x, &r3.x};
        float cc[4] = {c0, c1, c2, c3};
#pragma unroll
        for (int q = 0; q < 4; q++) {
#pragma unroll
            for (int j = 0; j < 4; j++) {
                float2 f = __bfloat1622float2(*reinterpret_cast<const __nv_bfloat162*>(&rr[q][j]));
                acc[2*j]   += cc[q] * f.x;
                acc[2*j+1] += cc[q] * f.y;
            }
        }
    }
    for (; e < end; e++) {
        int2 p0 = __ldg(epack + e);
        float c0 = __int_as_float(p0.y);
        uint4 r0 = tp[(size_t)p0.x * 16 + hl];
        const uint32_t* rr = &r0.x;
#pragma unroll
        for (int j = 0; j < 4; j++) {
            float2 f = __bfloat1622float2(*reinterpret_cast<const __nv_bfloat162*>(&rr[j]));
            acc[2*j]   += c0 * f.x;
            acc[2*j+1] += c0 * f.y;
        }
    }

    int ch = hl * 8;
    float4 bv0 = *(const float4*)&bias[ch];
    float4 bv1 = *(const float4*)&bias[ch + 4];
    uint4 o;
    o.x = pack_bf16(__float2bfloat16(fmaxf(acc[0] + bv0.x, 0.f)),
                    __float2bfloat16(fmaxf(acc[1] + bv0.y, 0.f)));
    o.y = pack_bf16(__float2bfloat16(fmaxf(acc[2] + bv0.z, 0.f)),
                    __float2bfloat16(fmaxf(acc[3] + bv0.w, 0.f)));
    o.z = pack_bf16(__float2bfloat16(fmaxf(acc[4] + bv1.x, 0.f)),
                    __float2bfloat16(fmaxf(acc[5] + bv1.y, 0.f)));
    o.w = pack_bf16(__float2bfloat16(fmaxf(acc[6] + bv1.z, 0.f)),
                    __float2bfloat16(fmaxf(acc[7] + bv1.w, 0.f)));
    ((uint4*)out)[(size_t)node * 16 + hl] = o;
}

// ================= launch =================
extern "C" void kernel_launch(void* const* d_in, const int* in_sizes, int n_in,
                              void* d_out, int out_size)
{
    const float* x   = (const float*)d_in[0];
    const int*   ei  = (const int*)d_in[1];
    const float* ew  = (const float*)d_in[2];
    const float* Wp  = (const float*)d_in[3];
    const float* bp  = (const float*)d_in[4];
    const float* W1  = (const float*)d_in[5];
    const float* b1  = (const float*)d_in[6];
    const float* W2  = (const float*)d_in[7];
    const float* b2  = (const float*)d_in[8];
    const float* Wl1 = (const float*)d_in[9];
    const float* bl1 = (const float*)d_in[10];
    const float* Wl2 = (const float*)d_in[11];
    const float* bl2 = (const float*)d_in[12];
    float* out = (float*)d_out;

    const int M = in_sizes[0] / 256;   // 100000
    const int E = in_sizes[1] / 2;     // 1600000
    const int* src = ei;
    const int* dst = ei + E;

    float *p_dinv;
    __nv_bfloat16 *p_h, *p_t, *p_whi;
    unsigned long long* p_degcnt;
    int *p_cnt, *p_off, *p_cur, *p_part;
    int2 *p_epack;
    cudaGetSymbolAddress((void**)&p_h, g_h);
    cudaGetSymbolAddress((void**)&p_t, g_t);
    cudaGetSymbolAddress((void**)&p_degcnt, g_degcnt);
    cudaGetSymbolAddress((void**)&p_dinv, g_dinv);
    cudaGetSymbolAddress((void**)&p_cnt, g_cnt);
    cudaGetSymbolAddress((void**)&p_off, g_off);
    cudaGetSymbolAddress((void**)&p_cur, g_cur);
    cudaGetSymbolAddress((void**)&p_epack, g_epack);
    cudaGetSymbolAddress((void**)&p_part, g_part);
    cudaGetSymbolAddress((void**)&p_whi, g_whi);

    cudaFuncSetAttribute(k_gemm1,     cudaFuncAttributeMaxDynamicSharedMemorySize, GEMM_SMEM_F32);
    cudaFuncSetAttribute(k_gemm_b16,  cudaFuncAttributeMaxDynamicSharedMemorySize, GEMM_SMEM_B16);
    cudaFuncSetAttribute(k_gemm_last, cudaFuncAttributeMaxDynamicSharedMemorySize, GEMM_SMEM_B16);

    static cudaStream_t s2 = nullptr;
    static cudaEvent_t evF = nullptr, evJ = nullptr;
    if (s2 == nullptr) {
        cudaStreamCreateWithFlags(&s2, cudaStreamNonBlocking);
        cudaEventCreateWithFlags(&evF, cudaEventDisableTiming);
        cudaEventCreateWithFlags(&evJ, cudaEventDisableTiming);
    }

    const int gemm_blocks = (M + 63) / 64;
    const int agg_blocks  = (M + 15) / 16;   // 2 nodes per warp, 8 warps per block
    const int scan_blocks = (M + SCAN_CHUNK - 1) / SCAN_CHUNK;

    // ---- fork: CSR branch on s2 ----
    cudaEventRecord(evF, 0);
    cudaStreamWaitEvent(s2, evF, 0);

    cudaMemsetAsync(p_degcnt, 0, (size_t)NN * sizeof(unsigned long long), s2);
    k_edge_deg<<<(E + 255) / 256, 256, 0, s2>>>(dst, ew, p_degcnt, E);
    k_dinv_scan1<<<scan_blocks, SCAN_CHUNK, 0, s2>>>(p_degcnt, p_dinv, p_cnt, p_part, M);
    k_scan2<<<1, 512, 0, s2>>>(p_part, scan_blocks);
    k_scan3<<<scan_blocks, SCAN_CHUNK, 0, s2>>>(p_cnt, p_part, p_off, p_cur, M, E);
    k_scatter<<<(E + 255) / 256, 256, 0, s2>>>(src, dst, ew, p_dinv, p_cur, p_epack, E);
    cudaEventRecord(evJ, s2);

    // ---- main branch: prep + gemm1 + conv1 GEMM ----
    k_prep_all<<<(81920 + 255) / 256, 256>>>(Wp, W1, W2, Wl1, p_whi);
    k_gemm1<<<gemm_blocks, 256, GEMM_SMEM_F32>>>(x, p_whi, bp, p_h, M);
    k_gemm_b16<<<gemm_blocks, 256, GEMM_SMEM_B16>>>(p_h, p_whi + 32768, p_t, M);

    // ---- join ----
    cudaStreamWaitEvent(0, evJ, 0);

    k_agg<<<agg_blocks, 256>>>(p_off, p_epack, p_t, p_dinv, b1, p_h, M);

    // conv2
    k_gemm_b16<<<gemm_blocks, 256, GEMM_SMEM_B16>>>(p_h, p_whi + 49152, p_t, M);
    k_agg<<<agg_blocks, 256>>>(p_off, p_epack, p_t, p_dinv, b2, p_h, M);

    // fused: softmax(relu(h @ Wl1 + bl1) @ Wl2 + bl2)
    k_gemm_last<<<gemm_blocks, 256, GEMM_SMEM_B16>>>(p_h, p_whi + 65536, bl1, Wl2, bl2, out, M);
}